// round 10
// baseline (speedup 1.0000x reference)
#include <cuda_runtime.h>
#include <cuda_fp16.h>
#include <math.h>
#include <stdint.h>

#define NB 64
#define LL 512
#define NT (NB*LL)
#define DD 128
#define HH 8
#define FFD 512
#define NLAYERS 6
#define OUTC 10

#define SZ_WP   (128*128)
#define SZ_QKV  (NLAYERS*128*384)
#define SZ_OUT  (NLAYERS*128*128)
#define SZ_F1   (NLAYERS*128*512)
#define SZ_F2   (NLAYERS*512*128)
#define OFF_WP  0
#define OFF_QKV (SZ_WP)
#define OFF_OUT (OFF_QKV+SZ_QKV)
#define OFF_F1  (OFF_OUT+SZ_OUT)
#define OFF_F2  (OFF_F1+SZ_F1)
#define W16_TOT (OFF_F2+SZ_F2)

typedef unsigned long long ull;

__device__ float  g_h   [NT*DD];
__device__ __align__(16) __half g_h16   [NT*DD];
__device__ __align__(16) __half g_x16   [NT*DD];
__device__ __align__(16) __half g_qkv16 [NT*3*DD];
__device__ __align__(16) __half g_attn16[NT*DD];
__device__ __align__(16) __half g_ff16  [NT*FFD];
__device__ __align__(16) __half g_whi   [W16_TOT];
__device__ float g_pool4[4][NB*DD];

__device__ __forceinline__ uint32_t su32(const void* p){
    return (uint32_t)__cvta_generic_to_shared(p);
}
__device__ __forceinline__ void ldmx4(uint32_t a, uint32_t& r0, uint32_t& r1,
                                      uint32_t& r2, uint32_t& r3){
    asm volatile("ldmatrix.sync.aligned.m8n8.x4.shared.b16 {%0,%1,%2,%3},[%4];"
        :"=r"(r0),"=r"(r1),"=r"(r2),"=r"(r3):"r"(a));
}
__device__ __forceinline__ void ldmx4t(uint32_t a, uint32_t& r0, uint32_t& r1,
                                       uint32_t& r2, uint32_t& r3){
    asm volatile("ldmatrix.sync.aligned.m8n8.x4.trans.shared.b16 {%0,%1,%2,%3},[%4];"
        :"=r"(r0),"=r"(r1),"=r"(r2),"=r"(r3):"r"(a));
}
__device__ __forceinline__ void mma16816(float* c, const uint32_t* a,
                                         uint32_t b0, uint32_t b1){
    asm volatile("mma.sync.aligned.m16n8k16.row.col.f32.f16.f16.f32 "
        "{%0,%1,%2,%3},{%4,%5,%6,%7},{%8,%9},{%0,%1,%2,%3};"
        :"+f"(c[0]),"+f"(c[1]),"+f"(c[2]),"+f"(c[3])
        :"r"(a[0]),"r"(a[1]),"r"(a[2]),"r"(a[3]),"r"(b0),"r"(b1));
}
// f16-accumulator mma, D = A*B (zero C)
__device__ __forceinline__ void mma16816h(uint32_t& d0, uint32_t& d1,
                                          const uint32_t* a,
                                          uint32_t b0, uint32_t b1){
    asm volatile("mma.sync.aligned.m16n8k16.row.col.f16.f16.f16.f16 "
        "{%0,%1},{%2,%3,%4,%5},{%6,%7},{%8,%9};"
        :"=r"(d0),"=r"(d1)
        :"r"(a[0]),"r"(a[1]),"r"(a[2]),"r"(a[3]),"r"(b0),"r"(b1),
         "r"(0u),"r"(0u));
}
__device__ __forceinline__ void cpa16(uint32_t dst, const void* src){
    asm volatile("cp.async.cg.shared.global [%0],[%1],16;"::"r"(dst),"l"(src));
}

// ---------------- single fused conversion kernel ----------------
__global__ void cvtall(const float* __restrict__ Wp, const float* __restrict__ qkvw,
                       const float* __restrict__ outw, const float* __restrict__ f1,
                       const float* __restrict__ f2, const float* __restrict__ x,
                       __half* __restrict__ hi, __half* __restrict__ x16)
{
    const int TOT = W16_TOT + NT*DD;
    for (int i = blockIdx.x*blockDim.x + threadIdx.x; i < TOT;
         i += gridDim.x*blockDim.x){
        if (i >= W16_TOT){
            int j = i - W16_TOT;
            x16[j] = __float2half_rn(x[j]);
            continue;
        }
        float w;
        if (i < OFF_QKV){
            w = Wp[i];
        } else if (i < OFF_OUT){
            int j = i - OFF_QKV;
            int L = j / (128*384); int r = j - L*(128*384);
            int k = r / 384, n = r - k*384;
            w = qkvw[(size_t)L*384*128 + (size_t)n*128 + k];
        } else if (i < OFF_F1){
            int j = i - OFF_OUT;
            int L = j / (128*128); int r = j - L*(128*128);
            int k = r >> 7, n = r & 127;
            w = outw[(size_t)L*128*128 + (size_t)n*128 + k];
        } else if (i < OFF_F2){
            w = f1[i - OFF_F1];
        } else {
            w = f2[i - OFF_F2];
        }
        hi[i] = __float2half_rn(w);
    }
}

// ---------------- fp16 tensor-core GEMM (compile-time N,K; full unroll) ----------------
template<int NN, int KK, bool WF32, bool WF16, bool RELU, bool LN>
__global__ __launch_bounds__(256)
void hgemm(const __half* __restrict__ A, const __half* __restrict__ W,
           const float* __restrict__ bias,
           float* __restrict__ C32, __half* __restrict__ C16,
           const float* __restrict__ resid, const float* __restrict__ lng,
           const float* __restrict__ lnb)
{
    __shared__ __align__(16) __half As[2][128*32];
    __shared__ __align__(16) __half Ws[2][32*128];
    const int tid = threadIdx.x;
    const int lane = tid & 31, wid = tid >> 5;
    const int wm = wid & 3, wn = wid >> 2;
    const int bm = blockIdx.y * 128, bn = blockIdx.x * 128;

    float acc[2][8][4];
#pragma unroll
    for (int i=0;i<2;i++)
#pragma unroll
        for (int j=0;j<8;j++)
#pragma unroll
            for (int k=0;k<4;k++) acc[i][j][k]=0.f;

    constexpr int KT = KK/32;

    // staging (verified R8 mapping): 512 vecs each for A and W, 2 iters
    auto issue = [&](int kt){
        int buf = kt & 1;
        int k0  = kt * 32;
        uint32_t sA = su32(&As[buf][0]);
        uint32_t sW = su32(&Ws[buf][0]);
#pragma unroll
        for (int i=0;i<2;i++){
            int id = tid + i*256;
            int r = id >> 2, c = id & 3;
            cpa16(sA + r*64 + ((c ^ ((r>>1)&3)) << 4),
                  A + (size_t)(bm + r)*KK + k0 + c*8);
            int k = id >> 4, cc = id & 15;
            cpa16(sW + k*256 + ((cc ^ (k&7)) << 4),
                  W + (size_t)(k0 + k)*NN + bn + cc*8);
        }
        asm volatile("cp.async.commit_group;":::"memory");
    };

    issue(0);
#pragma unroll
    for (int kt = 0; kt < KT; kt++){
        int buf = kt & 1;
        if (kt + 1 < KT){
            issue(kt + 1);
            asm volatile("cp.async.wait_group 1;":::"memory");
        } else {
            asm volatile("cp.async.wait_group 0;":::"memory");
        }
        __syncthreads();
        uint32_t sA = su32(&As[buf][0]);
        uint32_t sW = su32(&Ws[buf][0]);
#pragma unroll
        for (int ks = 0; ks < 32; ks += 16){
            uint32_t afr[2][4];
#pragma unroll
            for (int mt=0; mt<2; mt++){
                int r = wm*32 + mt*16 + (lane & 15);
                int cg = (ks >> 3) + (lane >> 4);
                ldmx4(sA + r*64 + ((cg ^ ((r>>1)&3)) << 4),
                      afr[mt][0], afr[mt][1], afr[mt][2], afr[mt][3]);
            }
            uint32_t bfr[4][4];
#pragma unroll
            for (int ntp=0; ntp<4; ntp++){
                int k  = ks + (lane & 15);
                int cc = wn*8 + ntp*2 + (lane >> 4);
                ldmx4t(sW + k*256 + ((cc ^ (k&7)) << 4),
                       bfr[ntp][0], bfr[ntp][1], bfr[ntp][2], bfr[ntp][3]);
            }
#pragma unroll
            for (int mt=0; mt<2; mt++)
#pragma unroll
                for (int nt=0; nt<8; nt++)
                    mma16816(acc[mt][nt], afr[mt],
                             bfr[nt>>1][(nt&1)*2], bfr[nt>>1][(nt&1)*2+1]);
        }
        __syncthreads();
    }

    const int g = lane >> 2, q = lane & 3;

    if (LN) {
        __shared__ float sS[2][128], sQ[2][128];
        float vsum[2][2], vsq[2][2];
#pragma unroll
        for (int mt=0; mt<2; mt++){ vsum[mt][0]=vsum[mt][1]=0.f; vsq[mt][0]=vsq[mt][1]=0.f; }
#pragma unroll
        for (int mt=0; mt<2; mt++){
            int row0 = bm + wm*32 + mt*16 + g;
#pragma unroll
            for (int nt=0; nt<8; nt++){
                int col = bn + wn*64 + nt*8 + q*2;
                float2 bv  = *(const float2*)&bias[col];
                float2 rr0 = *(const float2*)&resid[(size_t)row0*128 + col];
                float2 rr1 = *(const float2*)&resid[(size_t)(row0+8)*128 + col];
                float v0 = acc[mt][nt][0] + bv.x + rr0.x;
                float v1 = acc[mt][nt][1] + bv.y + rr0.y;
                float v2 = acc[mt][nt][2] + bv.x + rr1.x;
                float v3 = acc[mt][nt][3] + bv.y + rr1.y;
                acc[mt][nt][0]=v0; acc[mt][nt][1]=v1;
                acc[mt][nt][2]=v2; acc[mt][nt][3]=v3;
                vsum[mt][0] += v0+v1; vsq[mt][0] = fmaf(v0,v0,fmaf(v1,v1,vsq[mt][0]));
                vsum[mt][1] += v2+v3; vsq[mt][1] = fmaf(v2,v2,fmaf(v3,v3,vsq[mt][1]));
            }
        }
#pragma unroll
        for (int mt=0; mt<2; mt++)
#pragma unroll
            for (int r2=0; r2<2; r2++){
                vsum[mt][r2] += __shfl_xor_sync(0xffffffffu, vsum[mt][r2], 1);
                vsum[mt][r2] += __shfl_xor_sync(0xffffffffu, vsum[mt][r2], 2);
                vsq[mt][r2]  += __shfl_xor_sync(0xffffffffu, vsq[mt][r2], 1);
                vsq[mt][r2]  += __shfl_xor_sync(0xffffffffu, vsq[mt][r2], 2);
            }
        if (q == 0){
#pragma unroll
            for (int mt=0; mt<2; mt++)
#pragma unroll
                for (int r2=0; r2<2; r2++){
                    int r = wm*32 + mt*16 + g + r2*8;
                    sS[wn][r] = vsum[mt][r2];
                    sQ[wn][r] = vsq[mt][r2];
                }
        }
        __syncthreads();
#pragma unroll
        for (int mt=0; mt<2; mt++){
            int r0 = wm*32 + mt*16 + g, r1 = r0 + 8;
            float mean0 = (sS[0][r0]+sS[1][r0]) * (1.f/128.f);
            float mean1 = (sS[0][r1]+sS[1][r1]) * (1.f/128.f);
            float var0  = (sQ[0][r0]+sQ[1][r0]) * (1.f/128.f) - mean0*mean0;
            float var1  = (sQ[0][r1]+sQ[1][r1]) * (1.f/128.f) - mean1*mean1;
            float rs0 = rsqrtf(var0 + 1e-5f);
            float rs1 = rsqrtf(var1 + 1e-5f);
            int row0 = bm + r0;
#pragma unroll
            for (int nt=0; nt<8; nt++){
                int col = bn + wn*64 + nt*8 + q*2;
                float2 gg = *(const float2*)&lng[col];
                float2 bb = *(const float2*)&lnb[col];
                float y0 = (acc[mt][nt][0]-mean0)*rs0*gg.x + bb.x;
                float y1 = (acc[mt][nt][1]-mean0)*rs0*gg.y + bb.y;
                float y2 = (acc[mt][nt][2]-mean1)*rs1*gg.x + bb.x;
                float y3 = (acc[mt][nt][3]-mean1)*rs1*gg.y + bb.y;
                *(float2*)&C32[(size_t)row0*128 + col]     = make_float2(y0,y1);
                *(float2*)&C32[(size_t)(row0+8)*128 + col] = make_float2(y2,y3);
                *(__half2*)&C16[(size_t)row0*128 + col]     = __floats2half2_rn(y0,y1);
                *(__half2*)&C16[(size_t)(row0+8)*128 + col] = __floats2half2_rn(y2,y3);
            }
        }
        return;
    }

#pragma unroll
    for (int mt=0; mt<2; mt++){
        int row = bm + wm*32 + mt*16 + g;
#pragma unroll
        for (int nt=0; nt<8; nt++){
            int col = bn + wn*64 + nt*8 + q*2;
            float2 bv = *(const float2*)&bias[col];
            float v0 = acc[mt][nt][0] + bv.x;
            float v1 = acc[mt][nt][1] + bv.y;
            float v2 = acc[mt][nt][2] + bv.x;
            float v3 = acc[mt][nt][3] + bv.y;
            if (RELU){
                v0=fmaxf(v0,0.f); v1=fmaxf(v1,0.f);
                v2=fmaxf(v2,0.f); v3=fmaxf(v3,0.f);
            }
            if (WF32){
                *(float2*)&C32[(size_t)row*NN + col]     = make_float2(v0,v1);
                *(float2*)&C32[(size_t)(row+8)*NN + col] = make_float2(v2,v3);
            }
            if (WF16){
                *(__half2*)&C16[(size_t)row*NN + col]     = __floats2half2_rn(v0,v1);
                *(__half2*)&C16[(size_t)(row+8)*NN + col] = __floats2half2_rn(v2,v3);
            }
        }
    }
}

// ---------------- fused flash MHA v6 ----------------
// f16-acc S-mma, HFMA2 exp, l via HADD2 on P fragments (no ones-mma).
__global__ __launch_bounds__(256)
void attn_k(const __half* __restrict__ qkv, __half* __restrict__ out)
{
    __shared__ __align__(16) __half Ks[3][128*24];
    __shared__ __align__(16) __half Vs[3][128*24];

    const int qb = blockIdx.x, h = blockIdx.y, b = blockIdx.z;
    const int tid = threadIdx.x, lane = tid & 31, w = tid >> 5;
    const int g = lane >> 2, q = lane & 3;
    const size_t base = (size_t)b * LL * 384;

    const __half2 C3 = __float2half2_rn(0.05550411f);
    const __half2 C2 = __float2half2_rn(0.24022651f);
    const __half2 C1 = __float2half2_rn(0.69314718f);
    const __half2 C0 = __float2half2_rn(1.0f);

    const int skey  = tid >> 2;
    const int spart = tid & 3;
    const __half* ssrc = qkv + base + 128 + (spart>>1)*128 + h*16 + (spart&1)*8;
    const int sd0 = skey*24 + (spart&1)*8;
    const int sd1 = (skey+64)*24 + (spart&1)*8;

    auto stage = [&](int c, int buf){
        __half* bb = (spart < 2) ? &Ks[buf][0] : &Vs[buf][0];
        cpa16(su32(bb + sd0), ssrc + (size_t)(c*128 + skey)*384);
        cpa16(su32(bb + sd1), ssrc + (size_t)(c*128 + skey + 64)*384);
        asm volatile("cp.async.commit_group;":::"memory");
    };

    const int koff = ((lane&7) + ((lane>>4)<<3))*48 + (((lane>>3)&1) << 4);
    const int voff = (lane&15)*48 + ((lane>>4) << 4);

    uint32_t qfr[4];
    {
        const int r0 = qb*128 + w*16 + g, r1 = r0 + 8;
        const __half* p0 = qkv + base + (size_t)r0*384 + h*16;
        const __half* p1 = qkv + base + (size_t)r1*384 + h*16;
        const __half2 cs = __float2half2_rn(0.25f * 1.44269504f);
        __half2 a0 = __hmul2(*(const __half2*)(p0 + 2*q), cs);
        __half2 a1 = __hmul2(*(const __half2*)(p1 + 2*q), cs);
        __half2 a2 = __hmul2(*(const __half2*)(p0 + 8 + 2*q), cs);
        __half2 a3 = __hmul2(*(const __half2*)(p1 + 8 + 2*q), cs);
        qfr[0] = *(uint32_t*)&a0; qfr[1] = *(uint32_t*)&a1;
        qfr[2] = *(uint32_t*)&a2; qfr[3] = *(uint32_t*)&a3;
    }

    auto exp2h2 = [&](uint32_t s)->uint32_t{
        __half2 y = *(__half2*)&s;
        __half2 p = __hfma2(C3, y, C2);
        p = __hfma2(p, y, C1);
        p = __hfma2(p, y, C0);
        return *(uint32_t*)&p;
    };

    float of0[4]={0,0,0,0}, of1[4]={0,0,0,0};
    __half2 ls0 = __float2half2_rn(0.f), ls1 = __float2half2_rn(0.f);

    stage(0, 0);
    stage(1, 1);
#pragma unroll
    for (int c = 0; c < 4; c++){
        if (c < 3) asm volatile("cp.async.wait_group 1;":::"memory");
        else       asm volatile("cp.async.wait_group 0;":::"memory");
        __syncthreads();
        if (c < 2) stage(c + 2, (c + 2) % 3);

        const int buf = c % 3;
        const uint32_t kb = su32(&Ks[buf][0]) + koff;
        const uint32_t vb = su32(&Vs[buf][0]) + voff;

        uint32_t pa[8][4];
#pragma unroll
        for (int jp=0; jp<8; jp++){
            uint32_t k0,k1,k2,k3, s0,s1,s2,s3;
            ldmx4(kb + jp*768, k0,k1,k2,k3);
            mma16816h(s0, s1, qfr, k0, k1);
            mma16816h(s2, s3, qfr, k2, k3);
            uint32_t p0 = exp2h2(s0), p1 = exp2h2(s1);
            uint32_t p2 = exp2h2(s2), p3 = exp2h2(s3);
            pa[jp][0]=p0; pa[jp][1]=p1; pa[jp][2]=p2; pa[jp][3]=p3;
            ls0 = __hadd2(ls0, __hadd2(*(__half2*)&p0, *(__half2*)&p2));
            ls1 = __hadd2(ls1, __hadd2(*(__half2*)&p1, *(__half2*)&p3));
        }
#pragma unroll
        for (int t=0; t<8; t++){
            uint32_t v0,v1,v2,v3;
            ldmx4t(vb + t*768, v0,v1,v2,v3);
            mma16816(of0, pa[t], v0, v1);
            mma16816(of1, pa[t], v2, v3);
        }
    }

    float l0 = __half2float(__low2half(ls0)) + __half2float(__high2half(ls0));
    float l1 = __half2float(__low2half(ls1)) + __half2float(__high2half(ls1));
    l0 += __shfl_xor_sync(0xffffffffu, l0, 1);
    l0 += __shfl_xor_sync(0xffffffffu, l0, 2);
    l1 += __shfl_xor_sync(0xffffffffu, l1, 1);
    l1 += __shfl_xor_sync(0xffffffffu, l1, 2);
    const float i0 = 1.f / l0, i1 = 1.f / l1;
    const int row = b*LL + qb*128 + w*16 + g;
    {
        int col = h*16 + 2*q;
        *(__half2*)&out[(size_t)row*DD + col]         = __floats2half2_rn(of0[0]*i0, of0[1]*i0);
        *(__half2*)&out[(size_t)(row+8)*DD + col]     = __floats2half2_rn(of0[2]*i1, of0[3]*i1);
        *(__half2*)&out[(size_t)row*DD + col + 8]     = __floats2half2_rn(of1[0]*i0, of1[1]*i0);
        *(__half2*)&out[(size_t)(row+8)*DD + col + 8] = __floats2half2_rn(of1[2]*i1, of1[3]*i1);
    }
}

// ---------------- pooling + classifier ----------------
__global__ __launch_bounds__(256)
void pool_k(const float* __restrict__ h, float* __restrict__ pooled4)
{
    const int b = blockIdx.x, c = blockIdx.y, t = threadIdx.x;
    const int col = t & 127, hs = t >> 7;
    __shared__ float red[256];
    const float* p = h + (size_t)b*LL*DD + (size_t)(c*128 + hs*64)*DD + col;
    float s = 0.f;
    for (int l=0; l<64; l++) s += p[(size_t)l*DD];
    red[t] = s;
    __syncthreads();
    if (t < 128) pooled4[(size_t)c*NB*DD + b*DD + t] = red[t] + red[t+128];
}

__global__ __launch_bounds__(64)
void cls_k(const float* __restrict__ pooled4,
           const float* __restrict__ W1, const float* __restrict__ b1,
           const float* __restrict__ W2, const float* __restrict__ b2,
           float* __restrict__ out)
{
    const int b = blockIdx.x, t = threadIdx.x;
    __shared__ float ps[128], hid[64];
#pragma unroll
    for (int i=0;i<2;i++){
        int col = t + i*64;
        float s = 0.f;
#pragma unroll
        for (int c=0;c<4;c++) s += pooled4[(size_t)c*NB*DD + b*DD + col];
        ps[col] = s * (1.f/(float)LL);
    }
    __syncthreads();
    float a = b1[t];
    for (int k=0;k<128;k++) a = fmaf(ps[k], W1[k*64 + t], a);
    hid[t] = fmaxf(a, 0.f);
    __syncthreads();
    if (t < OUTC){
        float o = b2[t];
#pragma unroll
        for (int k=0;k<64;k++) o = fmaf(hid[k], W2[k*OUTC + t], o);
        out[b*OUTC + t] = o;
    }
}

extern "C" void kernel_launch(void* const* d_in, const int* in_sizes, int n_in,
                              void* d_out, int out_size)
{
    const float* x      = (const float*)d_in[0];
    const float* Wp     = (const float*)d_in[n_in-18];
    const float* bp     = (const float*)d_in[n_in-17];
    const float* qkv_w  = (const float*)d_in[n_in-16];
    const float* qkv_b  = (const float*)d_in[n_in-15];
    const float* out_w  = (const float*)d_in[n_in-14];
    const float* out_b  = (const float*)d_in[n_in-13];
    const float* ln1_g  = (const float*)d_in[n_in-12];
    const float* ln1_b  = (const float*)d_in[n_in-11];
    const float* ffn_w1 = (const float*)d_in[n_in-10];
    const float* ffn_b1 = (const float*)d_in[n_in-9];
    const float* ffn_w2 = (const float*)d_in[n_in-8];
    const float* ffn_b2 = (const float*)d_in[n_in-7];
    const float* ln2_g  = (const float*)d_in[n_in-6];
    const float* ln2_b  = (const float*)d_in[n_in-5];
    const float* cls_w1 = (const float*)d_in[n_in-4];
    const float* cls_b1 = (const float*)d_in[n_in-3];
    const float* cls_w2 = (const float*)d_in[n_in-2];
    const float* cls_b2 = (const float*)d_in[n_in-1];
    float* out = (float*)d_out;

    float *h, *pooled4;
    __half *h16, *x16, *qkv16, *attn16, *ff16, *whi;
    cudaGetSymbolAddress((void**)&h,       g_h);
    cudaGetSymbolAddress((void**)&pooled4, g_pool4);
    cudaGetSymbolAddress((void**)&h16,     g_h16);
    cudaGetSymbolAddress((void**)&x16,     g_x16);
    cudaGetSymbolAddress((void**)&qkv16,   g_qkv16);
    cudaGetSymbolAddress((void**)&attn16,  g_attn16);
    cudaGetSymbolAddress((void**)&ff16,    g_ff16);
    cudaGetSymbolAddress((void**)&whi,     g_whi);

    cvtall<<<2048,256>>>(Wp, qkv_w, out_w, ffn_w1, ffn_w2, x, whi, x16);

    const int MB = NT/128;

    hgemm<128,128,true,true,false,false><<<dim3(1,MB),256>>>(
        x16, whi+OFF_WP, bp, h, h16,
        (const float*)0, (const float*)0, (const float*)0);

    for (int i=0; i<NLAYERS; i++){
        hgemm<384,128,false,true,false,false><<<dim3(3,MB),256>>>(
            h16, whi+OFF_QKV+(size_t)i*128*384,
            qkv_b+(size_t)i*384, (float*)0, qkv16,
            (const float*)0, (const float*)0, (const float*)0);

        attn_k<<<dim3(4,HH,NB),256>>>(qkv16, attn16);

        hgemm<128,128,true,true,false,true><<<dim3(1,MB),256>>>(
            attn16, whi+OFF_OUT+(size_t)i*128*128,
            out_b+(size_t)i*128, h, h16,
            h, ln1_g+(size_t)i*DD, ln1_b+(size_t)i*DD);

        hgemm<512,128,false,true,true,false><<<dim3(4,MB),256>>>(
            h16, whi+OFF_F1+(size_t)i*128*512,
            ffn_b1+(size_t)i*512, (float*)0, ff16,
            (const float*)0, (const float*)0, (const float*)0);

        hgemm<128,512,true,true,false,true><<<dim3(1,MB),256>>>(
            ff16, whi+OFF_F2+(size_t)i*512*128,
            ffn_b2+(size_t)i*128, h, h16,
            h, ln2_g+(size_t)i*DD, ln2_b+(size_t)i*DD);
    }

    pool_k<<<dim3(NB,4),256>>>(h, pooled4);
    cls_k<<<NB,64>>>(pooled4, cls_w1, cls_b1, cls_w2, cls_b2, out);

    (void)in_sizes; (void)out_size;
}

// round 11
// speedup vs baseline: 1.4187x; 1.4187x over previous
#include <cuda_runtime.h>
#include <cuda_fp16.h>
#include <math.h>
#include <stdint.h>

#define NB 64
#define LL 512
#define NT (NB*LL)
#define DD 128
#define HH 8
#define FFD 512
#define NLAYERS 6
#define OUTC 10

#define SZ_WP   (128*128)
#define SZ_QKV  (NLAYERS*128*384)
#define SZ_OUT  (NLAYERS*128*128)
#define SZ_F1   (NLAYERS*128*512)
#define SZ_F2   (NLAYERS*512*128)
#define OFF_WP  0
#define OFF_QKV (SZ_WP)
#define OFF_OUT (OFF_QKV+SZ_QKV)
#define OFF_F1  (OFF_OUT+SZ_OUT)
#define OFF_F2  (OFF_F1+SZ_F1)
#define W16_TOT (OFF_F2+SZ_F2)

typedef unsigned long long ull;

__device__ float  g_h   [NT*DD];
__device__ __align__(16) __half g_h16   [NT*DD];
__device__ __align__(16) __half g_x16   [NT*DD];
__device__ __align__(16) __half g_qkv16 [NT*3*DD];
__device__ __align__(16) __half g_attn16[NT*DD];
__device__ __align__(16) __half g_ff16  [NT*FFD];
__device__ __align__(16) __half g_whi   [W16_TOT];
__device__ float g_pool4[4][NB*DD];

__device__ __forceinline__ uint32_t su32(const void* p){
    return (uint32_t)__cvta_generic_to_shared(p);
}
__device__ __forceinline__ void ldmx4(uint32_t a, uint32_t& r0, uint32_t& r1,
                                      uint32_t& r2, uint32_t& r3){
    asm volatile("ldmatrix.sync.aligned.m8n8.x4.shared.b16 {%0,%1,%2,%3},[%4];"
        :"=r"(r0),"=r"(r1),"=r"(r2),"=r"(r3):"r"(a));
}
__device__ __forceinline__ void ldmx4t(uint32_t a, uint32_t& r0, uint32_t& r1,
                                       uint32_t& r2, uint32_t& r3){
    asm volatile("ldmatrix.sync.aligned.m8n8.x4.trans.shared.b16 {%0,%1,%2,%3},[%4];"
        :"=r"(r0),"=r"(r1),"=r"(r2),"=r"(r3):"r"(a));
}
__device__ __forceinline__ void mma16816(float* c, const uint32_t* a,
                                         uint32_t b0, uint32_t b1){
    asm volatile("mma.sync.aligned.m16n8k16.row.col.f32.f16.f16.f32 "
        "{%0,%1,%2,%3},{%4,%5,%6,%7},{%8,%9},{%0,%1,%2,%3};"
        :"+f"(c[0]),"+f"(c[1]),"+f"(c[2]),"+f"(c[3])
        :"r"(a[0]),"r"(a[1]),"r"(a[2]),"r"(a[3]),"r"(b0),"r"(b1));
}
// f16-accumulator mma, D = A*B (zero C)
__device__ __forceinline__ void mma16816h(uint32_t& d0, uint32_t& d1,
                                          const uint32_t* a,
                                          uint32_t b0, uint32_t b1){
    asm volatile("mma.sync.aligned.m16n8k16.row.col.f16.f16.f16.f16 "
        "{%0,%1},{%2,%3,%4,%5},{%6,%7},{%8,%9};"
        :"=r"(d0),"=r"(d1)
        :"r"(a[0]),"r"(a[1]),"r"(a[2]),"r"(a[3]),"r"(b0),"r"(b1),
         "r"(0u),"r"(0u));
}
// f16-accumulator mma, D += A*B
__device__ __forceinline__ void mma16816hacc(uint32_t& d0, uint32_t& d1,
                                             const uint32_t* a,
                                             uint32_t b0, uint32_t b1){
    asm volatile("mma.sync.aligned.m16n8k16.row.col.f16.f16.f16.f16 "
        "{%0,%1},{%2,%3,%4,%5},{%6,%7},{%0,%1};"
        :"+r"(d0),"+r"(d1)
        :"r"(a[0]),"r"(a[1]),"r"(a[2]),"r"(a[3]),"r"(b0),"r"(b1));
}
__device__ __forceinline__ void cpa16(uint32_t dst, const void* src){
    asm volatile("cp.async.cg.shared.global [%0],[%1],16;"::"r"(dst),"l"(src));
}

// ---------------- single fused conversion kernel ----------------
__global__ void cvtall(const float* __restrict__ Wp, const float* __restrict__ qkvw,
                       const float* __restrict__ outw, const float* __restrict__ f1,
                       const float* __restrict__ f2, const float* __restrict__ x,
                       __half* __restrict__ hi, __half* __restrict__ x16)
{
    const int TOT = W16_TOT + NT*DD;
    for (int i = blockIdx.x*blockDim.x + threadIdx.x; i < TOT;
         i += gridDim.x*blockDim.x){
        if (i >= W16_TOT){
            int j = i - W16_TOT;
            x16[j] = __float2half_rn(x[j]);
            continue;
        }
        float w;
        if (i < OFF_QKV){
            w = Wp[i];
        } else if (i < OFF_OUT){
            int j = i - OFF_QKV;
            int L = j / (128*384); int r = j - L*(128*384);
            int k = r / 384, n = r - k*384;
            w = qkvw[(size_t)L*384*128 + (size_t)n*128 + k];
        } else if (i < OFF_F1){
            int j = i - OFF_OUT;
            int L = j / (128*128); int r = j - L*(128*128);
            int k = r >> 7, n = r & 127;
            w = outw[(size_t)L*128*128 + (size_t)n*128 + k];
        } else if (i < OFF_F2){
            w = f1[i - OFF_F1];
        } else {
            w = f2[i - OFF_F2];
        }
        hi[i] = __float2half_rn(w);
    }
}

// ---------------- fp16 tensor-core GEMM (f32 accum; runtime N,K — R8 proven) ----------------
template<bool WF32, bool WF16, bool RELU, bool LN>
__global__ __launch_bounds__(256)
void hgemm(const __half* __restrict__ A, const __half* __restrict__ W,
           const float* __restrict__ bias,
           float* __restrict__ C32, __half* __restrict__ C16, int N, int K,
           const float* __restrict__ resid, const float* __restrict__ lng,
           const float* __restrict__ lnb)
{
    __shared__ __align__(16) __half As[2][128*32];
    __shared__ __align__(16) __half Ws[2][32*128];
    const int tid = threadIdx.x;
    const int lane = tid & 31, wid = tid >> 5;
    const int wm = wid & 3, wn = wid >> 2;
    const int bm = blockIdx.y * 128, bn = blockIdx.x * 128;

    float acc[2][8][4];
#pragma unroll
    for (int i=0;i<2;i++)
#pragma unroll
        for (int j=0;j<8;j++)
#pragma unroll
            for (int k=0;k<4;k++) acc[i][j][k]=0.f;

    const int KT = K/32;

    auto issue = [&](int kt){
        int buf = kt & 1;
        int k0  = kt * 32;
        uint32_t sA = su32(&As[buf][0]);
        uint32_t sW = su32(&Ws[buf][0]);
#pragma unroll
        for (int i=0;i<2;i++){
            int id = tid + i*256;
            int r = id >> 2, c = id & 3;
            cpa16(sA + r*64 + ((c ^ ((r>>1)&3)) << 4),
                  A + (size_t)(bm + r)*K + k0 + c*8);
            int k = id >> 4, cc = id & 15;
            cpa16(sW + k*256 + ((cc ^ (k&7)) << 4),
                  W + (size_t)(k0 + k)*N + bn + cc*8);
        }
        asm volatile("cp.async.commit_group;":::"memory");
    };

    issue(0);
    for (int kt = 0; kt < KT; kt++){
        int buf = kt & 1;
        if (kt + 1 < KT){
            issue(kt + 1);
            asm volatile("cp.async.wait_group 1;":::"memory");
        } else {
            asm volatile("cp.async.wait_group 0;":::"memory");
        }
        __syncthreads();
        uint32_t sA = su32(&As[buf][0]);
        uint32_t sW = su32(&Ws[buf][0]);
#pragma unroll
        for (int ks = 0; ks < 32; ks += 16){
            uint32_t afr[2][4];
#pragma unroll
            for (int mt=0; mt<2; mt++){
                int r = wm*32 + mt*16 + (lane & 15);
                int cg = (ks >> 3) + (lane >> 4);
                ldmx4(sA + r*64 + ((cg ^ ((r>>1)&3)) << 4),
                      afr[mt][0], afr[mt][1], afr[mt][2], afr[mt][3]);
            }
            uint32_t bfr[4][4];
#pragma unroll
            for (int ntp=0; ntp<4; ntp++){
                int k  = ks + (lane & 15);
                int cc = wn*8 + ntp*2 + (lane >> 4);
                ldmx4t(sW + k*256 + ((cc ^ (k&7)) << 4),
                       bfr[ntp][0], bfr[ntp][1], bfr[ntp][2], bfr[ntp][3]);
            }
#pragma unroll
            for (int mt=0; mt<2; mt++)
#pragma unroll
                for (int nt=0; nt<8; nt++)
                    mma16816(acc[mt][nt], afr[mt],
                             bfr[nt>>1][(nt&1)*2], bfr[nt>>1][(nt&1)*2+1]);
        }
        __syncthreads();
    }

    const int g = lane >> 2, q = lane & 3;

    if (LN) {
        __shared__ float sS[2][128], sQ[2][128];
        float vsum[2][2], vsq[2][2];
#pragma unroll
        for (int mt=0; mt<2; mt++){ vsum[mt][0]=vsum[mt][1]=0.f; vsq[mt][0]=vsq[mt][1]=0.f; }
#pragma unroll
        for (int mt=0; mt<2; mt++){
            int row0 = bm + wm*32 + mt*16 + g;
#pragma unroll
            for (int nt=0; nt<8; nt++){
                int col = bn + wn*64 + nt*8 + q*2;
                float2 bv  = *(const float2*)&bias[col];
                float2 rr0 = *(const float2*)&resid[(size_t)row0*128 + col];
                float2 rr1 = *(const float2*)&resid[(size_t)(row0+8)*128 + col];
                float v0 = acc[mt][nt][0] + bv.x + rr0.x;
                float v1 = acc[mt][nt][1] + bv.y + rr0.y;
                float v2 = acc[mt][nt][2] + bv.x + rr1.x;
                float v3 = acc[mt][nt][3] + bv.y + rr1.y;
                acc[mt][nt][0]=v0; acc[mt][nt][1]=v1;
                acc[mt][nt][2]=v2; acc[mt][nt][3]=v3;
                vsum[mt][0] += v0+v1; vsq[mt][0] = fmaf(v0,v0,fmaf(v1,v1,vsq[mt][0]));
                vsum[mt][1] += v2+v3; vsq[mt][1] = fmaf(v2,v2,fmaf(v3,v3,vsq[mt][1]));
            }
        }
#pragma unroll
        for (int mt=0; mt<2; mt++)
#pragma unroll
            for (int r2=0; r2<2; r2++){
                vsum[mt][r2] += __shfl_xor_sync(0xffffffffu, vsum[mt][r2], 1);
                vsum[mt][r2] += __shfl_xor_sync(0xffffffffu, vsum[mt][r2], 2);
                vsq[mt][r2]  += __shfl_xor_sync(0xffffffffu, vsq[mt][r2], 1);
                vsq[mt][r2]  += __shfl_xor_sync(0xffffffffu, vsq[mt][r2], 2);
            }
        if (q == 0){
#pragma unroll
            for (int mt=0; mt<2; mt++)
#pragma unroll
                for (int r2=0; r2<2; r2++){
                    int r = wm*32 + mt*16 + g + r2*8;
                    sS[wn][r] = vsum[mt][r2];
                    sQ[wn][r] = vsq[mt][r2];
                }
        }
        __syncthreads();
#pragma unroll
        for (int mt=0; mt<2; mt++){
            int r0 = wm*32 + mt*16 + g, r1 = r0 + 8;
            float mean0 = (sS[0][r0]+sS[1][r0]) * (1.f/128.f);
            float mean1 = (sS[0][r1]+sS[1][r1]) * (1.f/128.f);
            float var0  = (sQ[0][r0]+sQ[1][r0]) * (1.f/128.f) - mean0*mean0;
            float var1  = (sQ[0][r1]+sQ[1][r1]) * (1.f/128.f) - mean1*mean1;
            float rs0 = rsqrtf(var0 + 1e-5f);
            float rs1 = rsqrtf(var1 + 1e-5f);
            int row0 = bm + r0;
#pragma unroll
            for (int nt=0; nt<8; nt++){
                int col = bn + wn*64 + nt*8 + q*2;
                float2 gg = *(const float2*)&lng[col];
                float2 bb = *(const float2*)&lnb[col];
                float y0 = (acc[mt][nt][0]-mean0)*rs0*gg.x + bb.x;
                float y1 = (acc[mt][nt][1]-mean0)*rs0*gg.y + bb.y;
                float y2 = (acc[mt][nt][2]-mean1)*rs1*gg.x + bb.x;
                float y3 = (acc[mt][nt][3]-mean1)*rs1*gg.y + bb.y;
                *(float2*)&C32[(size_t)row0*128 + col]     = make_float2(y0,y1);
                *(float2*)&C32[(size_t)(row0+8)*128 + col] = make_float2(y2,y3);
                *(__half2*)&C16[(size_t)row0*128 + col]     = __floats2half2_rn(y0,y1);
                *(__half2*)&C16[(size_t)(row0+8)*128 + col] = __floats2half2_rn(y2,y3);
            }
        }
        return;
    }

#pragma unroll
    for (int mt=0; mt<2; mt++){
        int row = bm + wm*32 + mt*16 + g;
#pragma unroll
        for (int nt=0; nt<8; nt++){
            int col = bn + wn*64 + nt*8 + q*2;
            float2 bv = *(const float2*)&bias[col];
            float v0 = acc[mt][nt][0] + bv.x;
            float v1 = acc[mt][nt][1] + bv.y;
            float v2 = acc[mt][nt][2] + bv.x;
            float v3 = acc[mt][nt][3] + bv.y;
            if (RELU){
                v0=fmaxf(v0,0.f); v1=fmaxf(v1,0.f);
                v2=fmaxf(v2,0.f); v3=fmaxf(v3,0.f);
            }
            if (WF32){
                *(float2*)&C32[(size_t)row*N + col]     = make_float2(v0,v1);
                *(float2*)&C32[(size_t)(row+8)*N + col] = make_float2(v2,v3);
            }
            if (WF16){
                *(__half2*)&C16[(size_t)row*N + col]     = __floats2half2_rn(v0,v1);
                *(__half2*)&C16[(size_t)(row+8)*N + col] = __floats2half2_rn(v2,v3);
            }
        }
    }
}

// ---------------- f16-accumulator GEMM (qkv only: output fp16, no relu/LN) ----------------
__global__ __launch_bounds__(256)
void hgemm16(const __half* __restrict__ A, const __half* __restrict__ W,
             const float* __restrict__ bias, __half* __restrict__ C16,
             int N, int K)
{
    __shared__ __align__(16) __half As[2][128*32];
    __shared__ __align__(16) __half Ws[2][32*128];
    const int tid = threadIdx.x;
    const int lane = tid & 31, wid = tid >> 5;
    const int wm = wid & 3, wn = wid >> 2;
    const int bm = blockIdx.y * 128, bn = blockIdx.x * 128;

    uint32_t hacc[2][8][2];
#pragma unroll
    for (int i=0;i<2;i++)
#pragma unroll
        for (int j=0;j<8;j++){ hacc[i][j][0]=0u; hacc[i][j][1]=0u; }

    const int KT = K/32;

    auto issue = [&](int kt){
        int buf = kt & 1;
        int k0  = kt * 32;
        uint32_t sA = su32(&As[buf][0]);
        uint32_t sW = su32(&Ws[buf][0]);
#pragma unroll
        for (int i=0;i<2;i++){
            int id = tid + i*256;
            int r = id >> 2, c = id & 3;
            cpa16(sA + r*64 + ((c ^ ((r>>1)&3)) << 4),
                  A + (size_t)(bm + r)*K + k0 + c*8);
            int k = id >> 4, cc = id & 15;
            cpa16(sW + k*256 + ((cc ^ (k&7)) << 4),
                  W + (size_t)(k0 + k)*N + bn + cc*8);
        }
        asm volatile("cp.async.commit_group;":::"memory");
    };

    issue(0);
    for (int kt = 0; kt < KT; kt++){
        int buf = kt & 1;
        if (kt + 1 < KT){
            issue(kt + 1);
            asm volatile("cp.async.wait_group 1;":::"memory");
        } else {
            asm volatile("cp.async.wait_group 0;":::"memory");
        }
        __syncthreads();
        uint32_t sA = su32(&As[buf][0]);
        uint32_t sW = su32(&Ws[buf][0]);
#pragma unroll
        for (int ks = 0; ks < 32; ks += 16){
            uint32_t afr[2][4];
#pragma unroll
            for (int mt=0; mt<2; mt++){
                int r = wm*32 + mt*16 + (lane & 15);
                int cg = (ks >> 3) + (lane >> 4);
                ldmx4(sA + r*64 + ((cg ^ ((r>>1)&3)) << 4),
                      afr[mt][0], afr[mt][1], afr[mt][2], afr[mt][3]);
            }
            uint32_t bfr[4][4];
#pragma unroll
            for (int ntp=0; ntp<4; ntp++){
                int k  = ks + (lane & 15);
                int cc = wn*8 + ntp*2 + (lane >> 4);
                ldmx4t(sW + k*256 + ((cc ^ (k&7)) << 4),
                       bfr[ntp][0], bfr[ntp][1], bfr[ntp][2], bfr[ntp][3]);
            }
#pragma unroll
            for (int mt=0; mt<2; mt++)
#pragma unroll
                for (int nt=0; nt<8; nt++)
                    mma16816hacc(hacc[mt][nt][0], hacc[mt][nt][1], afr[mt],
                                 bfr[nt>>1][(nt&1)*2], bfr[nt>>1][(nt&1)*2+1]);
        }
        __syncthreads();
    }

    const int g = lane >> 2, q = lane & 3;
#pragma unroll
    for (int mt=0; mt<2; mt++){
        int row = bm + wm*32 + mt*16 + g;
#pragma unroll
        for (int nt=0; nt<8; nt++){
            int col = bn + wn*64 + nt*8 + q*2;
            float2 bv = *(const float2*)&bias[col];
            __half2 hb = __floats2half2_rn(bv.x, bv.y);
            __half2 v0 = __hadd2(*(__half2*)&hacc[mt][nt][0], hb);
            __half2 v1 = __hadd2(*(__half2*)&hacc[mt][nt][1], hb);
            *(__half2*)&C16[(size_t)row*N + col]     = v0;
            *(__half2*)&C16[(size_t)(row+8)*N + col] = v1;
        }
    }
}

// ---------------- fused flash MHA v5 (R8 proven: ones-mma l, 3-buffer) ----------------
__global__ __launch_bounds__(256)
void attn_k(const __half* __restrict__ qkv, __half* __restrict__ out)
{
    __shared__ __align__(16) __half Ks[3][128*24];
    __shared__ __align__(16) __half Vs[3][128*24];

    const int qb = blockIdx.x, h = blockIdx.y, b = blockIdx.z;
    const int tid = threadIdx.x, lane = tid & 31, w = tid >> 5;
    const int g = lane >> 2, q = lane & 3;
    const size_t base = (size_t)b * LL * 384;

    const __half2 C3 = __float2half2_rn(0.05550411f);
    const __half2 C2 = __float2half2_rn(0.24022651f);
    const __half2 C1 = __float2half2_rn(0.69314718f);
    const __half2 C0 = __float2half2_rn(1.0f);
    const uint32_t ONE2 = 0x3C003C00u;

    const int skey  = tid >> 2;
    const int spart = tid & 3;
    const __half* ssrc = qkv + base + 128 + (spart>>1)*128 + h*16 + (spart&1)*8;
    const int sd0 = skey*24 + (spart&1)*8;
    const int sd1 = (skey+64)*24 + (spart&1)*8;

    auto stage = [&](int c, int buf){
        __half* bb = (spart < 2) ? &Ks[buf][0] : &Vs[buf][0];
        cpa16(su32(bb + sd0), ssrc + (size_t)(c*128 + skey)*384);
        cpa16(su32(bb + sd1), ssrc + (size_t)(c*128 + skey + 64)*384);
        asm volatile("cp.async.commit_group;":::"memory");
    };

    const int koff = ((lane&7) + ((lane>>4)<<3))*48 + (((lane>>3)&1) << 4);
    const int voff = (lane&15)*48 + ((lane>>4) << 4);

    uint32_t qfr[4];
    {
        const int r0 = qb*128 + w*16 + g, r1 = r0 + 8;
        const __half* p0 = qkv + base + (size_t)r0*384 + h*16;
        const __half* p1 = qkv + base + (size_t)r1*384 + h*16;
        const __half2 cs = __float2half2_rn(0.25f * 1.44269504f);
        __half2 a0 = __hmul2(*(const __half2*)(p0 + 2*q), cs);
        __half2 a1 = __hmul2(*(const __half2*)(p1 + 2*q), cs);
        __half2 a2 = __hmul2(*(const __half2*)(p0 + 8 + 2*q), cs);
        __half2 a3 = __hmul2(*(const __half2*)(p1 + 8 + 2*q), cs);
        qfr[0] = *(uint32_t*)&a0; qfr[1] = *(uint32_t*)&a1;
        qfr[2] = *(uint32_t*)&a2; qfr[3] = *(uint32_t*)&a3;
    }

    auto exp2h2 = [&](uint32_t s)->uint32_t{
        __half2 y = *(__half2*)&s;
        __half2 p = __hfma2(C3, y, C2);
        p = __hfma2(p, y, C1);
        p = __hfma2(p, y, C0);
        return *(uint32_t*)&p;
    };

    float of0[4]={0,0,0,0}, of1[4]={0,0,0,0}, of2[4]={0,0,0,0};

    stage(0, 0);
    stage(1, 1);
#pragma unroll
    for (int c = 0; c < 4; c++){
        if (c < 3) asm volatile("cp.async.wait_group 1;":::"memory");
        else       asm volatile("cp.async.wait_group 0;":::"memory");
        __syncthreads();
        if (c < 2) stage(c + 2, (c + 2) % 3);

        const int buf = c % 3;
        const uint32_t kb = su32(&Ks[buf][0]) + koff;
        const uint32_t vb = su32(&Vs[buf][0]) + voff;

        uint32_t pa[8][4];
#pragma unroll
        for (int jp=0; jp<8; jp++){
            uint32_t k0,k1,k2,k3, s0,s1,s2,s3;
            ldmx4(kb + jp*768, k0,k1,k2,k3);
            mma16816h(s0, s1, qfr, k0, k1);
            mma16816h(s2, s3, qfr, k2, k3);
            pa[jp][0] = exp2h2(s0); pa[jp][1] = exp2h2(s1);
            pa[jp][2] = exp2h2(s2); pa[jp][3] = exp2h2(s3);
        }
#pragma unroll
        for (int t=0; t<8; t++){
            uint32_t v0,v1,v2,v3;
            ldmx4t(vb + t*768, v0,v1,v2,v3);
            mma16816(of0, pa[t], v0, v1);
            mma16816(of1, pa[t], v2, v3);
            mma16816(of2, pa[t], ONE2, ONE2);
        }
    }

    const float i0 = 1.f / of2[0], i1 = 1.f / of2[2];
    const int row = b*LL + qb*128 + w*16 + g;
    {
        int col = h*16 + 2*q;
        *(__half2*)&out[(size_t)row*DD + col]         = __floats2half2_rn(of0[0]*i0, of0[1]*i0);
        *(__half2*)&out[(size_t)(row+8)*DD + col]     = __floats2half2_rn(of0[2]*i1, of0[3]*i1);
        *(__half2*)&out[(size_t)row*DD + col + 8]     = __floats2half2_rn(of1[0]*i0, of1[1]*i0);
        *(__half2*)&out[(size_t)(row+8)*DD + col + 8] = __floats2half2_rn(of1[2]*i1, of1[3]*i1);
    }
}

// ---------------- pooling + classifier ----------------
__global__ __launch_bounds__(256)
void pool_k(const float* __restrict__ h, float* __restrict__ pooled4)
{
    const int b = blockIdx.x, c = blockIdx.y, t = threadIdx.x;
    const int col = t & 127, hs = t >> 7;
    __shared__ float red[256];
    const float* p = h + (size_t)b*LL*DD + (size_t)(c*128 + hs*64)*DD + col;
    float s = 0.f;
    for (int l=0; l<64; l++) s += p[(size_t)l*DD];
    red[t] = s;
    __syncthreads();
    if (t < 128) pooled4[(size_t)c*NB*DD + b*DD + t] = red[t] + red[t+128];
}

__global__ __launch_bounds__(64)
void cls_k(const float* __restrict__ pooled4,
           const float* __restrict__ W1, const float* __restrict__ b1,
           const float* __restrict__ W2, const float* __restrict__ b2,
           float* __restrict__ out)
{
    const int b = blockIdx.x, t = threadIdx.x;
    __shared__ float ps[128], hid[64];
#pragma unroll
    for (int i=0;i<2;i++){
        int col = t + i*64;
        float s = 0.f;
#pragma unroll
        for (int c=0;c<4;c++) s += pooled4[(size_t)c*NB*DD + b*DD + col];
        ps[col] = s * (1.f/(float)LL);
    }
    __syncthreads();
    float a = b1[t];
    for (int k=0;k<128;k++) a = fmaf(ps[k], W1[k*64 + t], a);
    hid[t] = fmaxf(a, 0.f);
    __syncthreads();
    if (t < OUTC){
        float o = b2[t];
#pragma unroll
        for (int k=0;k<64;k++) o = fmaf(hid[k], W2[k*OUTC + t], o);
        out[b*OUTC + t] = o;
    }
}

extern "C" void kernel_launch(void* const* d_in, const int* in_sizes, int n_in,
                              void* d_out, int out_size)
{
    const float* x      = (const float*)d_in[0];
    const float* Wp     = (const float*)d_in[n_in-18];
    const float* bp     = (const float*)d_in[n_in-17];
    const float* qkv_w  = (const float*)d_in[n_in-16];
    const float* qkv_b  = (const float*)d_in[n_in-15];
    const float* out_w  = (const float*)d_in[n_in-14];
    const float* out_b  = (const float*)d_in[n_in-13];
    const float* ln1_g  = (const float*)d_in[n_in-12];
    const float* ln1_b  = (const float*)d_in[n_in-11];
    const float* ffn_w1 = (const float*)d_in[n_in-10];
    const float* ffn_b1 = (const float*)d_in[n_in-9];
    const float* ffn_w2 = (const float*)d_in[n_in-8];
    const float* ffn_b2 = (const float*)d_in[n_in-7];
    const float* ln2_g  = (const float*)d_in[n_in-6];
    const float* ln2_b  = (const float*)d_in[n_in-5];
    const float* cls_w1 = (const float*)d_in[n_in-4];
    const float* cls_b1 = (const float*)d_in[n_in-3];
    const float* cls_w2 = (const float*)d_in[n_in-2];
    const float* cls_b2 = (const float*)d_in[n_in-1];
    float* out = (float*)d_out;

    float *h, *pooled4;
    __half *h16, *x16, *qkv16, *attn16, *ff16, *whi;
    cudaGetSymbolAddress((void**)&h,       g_h);
    cudaGetSymbolAddress((void**)&pooled4, g_pool4);
    cudaGetSymbolAddress((void**)&h16,     g_h16);
    cudaGetSymbolAddress((void**)&x16,     g_x16);
    cudaGetSymbolAddress((void**)&qkv16,   g_qkv16);
    cudaGetSymbolAddress((void**)&attn16,  g_attn16);
    cudaGetSymbolAddress((void**)&ff16,    g_ff16);
    cudaGetSymbolAddress((void**)&whi,     g_whi);

    cvtall<<<2048,256>>>(Wp, qkv_w, out_w, ffn_w1, ffn_w2, x, whi, x16);

    const int MB = NT/128;

    hgemm<true,true,false,false><<<dim3(1,MB),256>>>(
        x16, whi+OFF_WP, bp, h, h16, DD, DD,
        (const float*)0, (const float*)0, (const float*)0);

    for (int i=0; i<NLAYERS; i++){
        // qkv: f16-accumulator GEMM (2x tensor rate; output is fp16 anyway)
        hgemm16<<<dim3(3,MB),256>>>(
            h16, whi+OFF_QKV+(size_t)i*128*384,
            qkv_b+(size_t)i*384, qkv16, 384, 128);

        attn_k<<<dim3(4,HH,NB),256>>>(qkv16, attn16);

        hgemm<true,true,false,true><<<dim3(1,MB),256>>>(
            attn16, whi+OFF_OUT+(size_t)i*128*128,
            out_b+(size_t)i*128, h, h16, DD, DD,
            h, ln1_g+(size_t)i*DD, ln1_b+(size_t)i*DD);

        hgemm<false,true,true,false><<<dim3(4,MB),256>>>(
            h16, whi+OFF_F1+(size_t)i*128*512,
            ffn_b1+(size_t)i*512, (float*)0, ff16, FFD, DD,
            (const float*)0, (const float*)0, (const float*)0);

        hgemm<true,true,false,true><<<dim3(1,MB),256>>>(
            ff16, whi+OFF_F2+(size_t)i*512*128,
            ffn_b2+(size_t)i*128, h, h16, DD, FFD,
            h, ln2_g+(size_t)i*DD, ln2_b+(size_t)i*DD);
    }

    pool_k<<<dim3(NB,4),256>>>(h, pooled4);
    cls_k<<<NB,64>>>(pooled4, cls_w1, cls_b1, cls_w2, cls_b2, out);

    (void)in_sizes; (void)out_size;
}

// round 12
// speedup vs baseline: 1.5258x; 1.0755x over previous
#include <cuda_runtime.h>
#include <cuda_fp16.h>
#include <math.h>
#include <stdint.h>

#define NB 64
#define LL 512
#define NT (NB*LL)
#define DD 128
#define HH 8
#define FFD 512
#define NLAYERS 6
#define OUTC 10

#define SZ_WP   (128*128)
#define SZ_QKV  (NLAYERS*128*384)
#define SZ_OUT  (NLAYERS*128*128)
#define SZ_F1   (NLAYERS*128*512)
#define SZ_F2   (NLAYERS*512*128)
#define OFF_WP  0
#define OFF_QKV (SZ_WP)
#define OFF_OUT (OFF_QKV+SZ_QKV)
#define OFF_F1  (OFF_OUT+SZ_OUT)
#define OFF_F2  (OFF_F1+SZ_F1)
#define W16_TOT (OFF_F2+SZ_F2)

// fused FFN dynamic smem: AF 32KB + FF 128KB + Ws 16KB + LN 2KB
#define FFN_SMEM (32768 + 131072 + 16384 + 2048)

typedef unsigned long long ull;

__device__ float  g_h   [NT*DD];
__device__ __align__(16) __half g_h16   [NT*DD];
__device__ __align__(16) __half g_x16   [NT*DD];   // also reused as attn16
__device__ __align__(16) __half g_qkv16 [NT*3*DD];
__device__ __align__(16) __half g_whi   [W16_TOT];
__device__ float g_pool4[4][NB*DD];

__device__ __forceinline__ uint32_t su32(const void* p){
    return (uint32_t)__cvta_generic_to_shared(p);
}
__device__ __forceinline__ void ldmx4(uint32_t a, uint32_t& r0, uint32_t& r1,
                                      uint32_t& r2, uint32_t& r3){
    asm volatile("ldmatrix.sync.aligned.m8n8.x4.shared.b16 {%0,%1,%2,%3},[%4];"
        :"=r"(r0),"=r"(r1),"=r"(r2),"=r"(r3):"r"(a));
}
__device__ __forceinline__ void ldmx4t(uint32_t a, uint32_t& r0, uint32_t& r1,
                                       uint32_t& r2, uint32_t& r3){
    asm volatile("ldmatrix.sync.aligned.m8n8.x4.trans.shared.b16 {%0,%1,%2,%3},[%4];"
        :"=r"(r0),"=r"(r1),"=r"(r2),"=r"(r3):"r"(a));
}
__device__ __forceinline__ void mma16816(float* c, const uint32_t* a,
                                         uint32_t b0, uint32_t b1){
    asm volatile("mma.sync.aligned.m16n8k16.row.col.f32.f16.f16.f32 "
        "{%0,%1,%2,%3},{%4,%5,%6,%7},{%8,%9},{%0,%1,%2,%3};"
        :"+f"(c[0]),"+f"(c[1]),"+f"(c[2]),"+f"(c[3])
        :"r"(a[0]),"r"(a[1]),"r"(a[2]),"r"(a[3]),"r"(b0),"r"(b1));
}
__device__ __forceinline__ void mma16816h(uint32_t& d0, uint32_t& d1,
                                          const uint32_t* a,
                                          uint32_t b0, uint32_t b1){
    asm volatile("mma.sync.aligned.m16n8k16.row.col.f16.f16.f16.f16 "
        "{%0,%1},{%2,%3,%4,%5},{%6,%7},{%8,%9};"
        :"=r"(d0),"=r"(d1)
        :"r"(a[0]),"r"(a[1]),"r"(a[2]),"r"(a[3]),"r"(b0),"r"(b1),
         "r"(0u),"r"(0u));
}
__device__ __forceinline__ void mma16816hacc(uint32_t& d0, uint32_t& d1,
                                             const uint32_t* a,
                                             uint32_t b0, uint32_t b1){
    asm volatile("mma.sync.aligned.m16n8k16.row.col.f16.f16.f16.f16 "
        "{%0,%1},{%2,%3,%4,%5},{%6,%7},{%0,%1};"
        :"+r"(d0),"+r"(d1)
        :"r"(a[0]),"r"(a[1]),"r"(a[2]),"r"(a[3]),"r"(b0),"r"(b1));
}
__device__ __forceinline__ void cpa16(uint32_t dst, const void* src){
    asm volatile("cp.async.cg.shared.global [%0],[%1],16;"::"r"(dst),"l"(src));
}

// ---------------- single fused conversion kernel ----------------
__global__ void cvtall(const float* __restrict__ Wp, const float* __restrict__ qkvw,
                       const float* __restrict__ outw, const float* __restrict__ f1,
                       const float* __restrict__ f2, const float* __restrict__ x,
                       __half* __restrict__ hi, __half* __restrict__ x16)
{
    const int TOT = W16_TOT + NT*DD;
    for (int i = blockIdx.x*blockDim.x + threadIdx.x; i < TOT;
         i += gridDim.x*blockDim.x){
        if (i >= W16_TOT){
            int j = i - W16_TOT;
            x16[j] = __float2half_rn(x[j]);
            continue;
        }
        float w;
        if (i < OFF_QKV){
            w = Wp[i];
        } else if (i < OFF_OUT){
            int j = i - OFF_QKV;
            int L = j / (128*384); int r = j - L*(128*384);
            int k = r / 384, n = r - k*384;
            w = qkvw[(size_t)L*384*128 + (size_t)n*128 + k];
        } else if (i < OFF_F1){
            int j = i - OFF_OUT;
            int L = j / (128*128); int r = j - L*(128*128);
            int k = r >> 7, n = r & 127;
            w = outw[(size_t)L*128*128 + (size_t)n*128 + k];
        } else if (i < OFF_F2){
            w = f1[i - OFF_F1];
        } else {
            w = f2[i - OFF_F2];
        }
        hi[i] = __float2half_rn(w);
    }
}

// ---------------- fp16 tensor-core GEMM (f32 accum; R8 proven) ----------------
template<bool WF32, bool WF16, bool RELU, bool LN>
__global__ __launch_bounds__(256)
void hgemm(const __half* __restrict__ A, const __half* __restrict__ W,
           const float* __restrict__ bias,
           float* __restrict__ C32, __half* __restrict__ C16, int N, int K,
           const float* __restrict__ resid, const float* __restrict__ lng,
           const float* __restrict__ lnb)
{
    __shared__ __align__(16) __half As[2][128*32];
    __shared__ __align__(16) __half Ws[2][32*128];
    const int tid = threadIdx.x;
    const int lane = tid & 31, wid = tid >> 5;
    const int wm = wid & 3, wn = wid >> 2;
    const int bm = blockIdx.y * 128, bn = blockIdx.x * 128;

    float acc[2][8][4];
#pragma unroll
    for (int i=0;i<2;i++)
#pragma unroll
        for (int j=0;j<8;j++)
#pragma unroll
            for (int k=0;k<4;k++) acc[i][j][k]=0.f;

    const int KT = K/32;

    auto issue = [&](int kt){
        int buf = kt & 1;
        int k0  = kt * 32;
        uint32_t sA = su32(&As[buf][0]);
        uint32_t sW = su32(&Ws[buf][0]);
#pragma unroll
        for (int i=0;i<2;i++){
            int id = tid + i*256;
            int r = id >> 2, c = id & 3;
            cpa16(sA + r*64 + ((c ^ ((r>>1)&3)) << 4),
                  A + (size_t)(bm + r)*K + k0 + c*8);
            int k = id >> 4, cc = id & 15;
            cpa16(sW + k*256 + ((cc ^ (k&7)) << 4),
                  W + (size_t)(k0 + k)*N + bn + cc*8);
        }
        asm volatile("cp.async.commit_group;":::"memory");
    };

    issue(0);
    for (int kt = 0; kt < KT; kt++){
        int buf = kt & 1;
        if (kt + 1 < KT){
            issue(kt + 1);
            asm volatile("cp.async.wait_group 1;":::"memory");
        } else {
            asm volatile("cp.async.wait_group 0;":::"memory");
        }
        __syncthreads();
        uint32_t sA = su32(&As[buf][0]);
        uint32_t sW = su32(&Ws[buf][0]);
#pragma unroll
        for (int ks = 0; ks < 32; ks += 16){
            uint32_t afr[2][4];
#pragma unroll
            for (int mt=0; mt<2; mt++){
                int r = wm*32 + mt*16 + (lane & 15);
                int cg = (ks >> 3) + (lane >> 4);
                ldmx4(sA + r*64 + ((cg ^ ((r>>1)&3)) << 4),
                      afr[mt][0], afr[mt][1], afr[mt][2], afr[mt][3]);
            }
            uint32_t bfr[4][4];
#pragma unroll
            for (int ntp=0; ntp<4; ntp++){
                int k  = ks + (lane & 15);
                int cc = wn*8 + ntp*2 + (lane >> 4);
                ldmx4t(sW + k*256 + ((cc ^ (k&7)) << 4),
                       bfr[ntp][0], bfr[ntp][1], bfr[ntp][2], bfr[ntp][3]);
            }
#pragma unroll
            for (int mt=0; mt<2; mt++)
#pragma unroll
                for (int nt=0; nt<8; nt++)
                    mma16816(acc[mt][nt], afr[mt],
                             bfr[nt>>1][(nt&1)*2], bfr[nt>>1][(nt&1)*2+1]);
        }
        __syncthreads();
    }

    const int g = lane >> 2, q = lane & 3;

    if (LN) {
        __shared__ float sS[2][128], sQ[2][128];
        float vsum[2][2], vsq[2][2];
#pragma unroll
        for (int mt=0; mt<2; mt++){ vsum[mt][0]=vsum[mt][1]=0.f; vsq[mt][0]=vsq[mt][1]=0.f; }
#pragma unroll
        for (int mt=0; mt<2; mt++){
            int row0 = bm + wm*32 + mt*16 + g;
#pragma unroll
            for (int nt=0; nt<8; nt++){
                int col = bn + wn*64 + nt*8 + q*2;
                float2 bv  = *(const float2*)&bias[col];
                float2 rr0 = *(const float2*)&resid[(size_t)row0*128 + col];
                float2 rr1 = *(const float2*)&resid[(size_t)(row0+8)*128 + col];
                float v0 = acc[mt][nt][0] + bv.x + rr0.x;
                float v1 = acc[mt][nt][1] + bv.y + rr0.y;
                float v2 = acc[mt][nt][2] + bv.x + rr1.x;
                float v3 = acc[mt][nt][3] + bv.y + rr1.y;
                acc[mt][nt][0]=v0; acc[mt][nt][1]=v1;
                acc[mt][nt][2]=v2; acc[mt][nt][3]=v3;
                vsum[mt][0] += v0+v1; vsq[mt][0] = fmaf(v0,v0,fmaf(v1,v1,vsq[mt][0]));
                vsum[mt][1] += v2+v3; vsq[mt][1] = fmaf(v2,v2,fmaf(v3,v3,vsq[mt][1]));
            }
        }
#pragma unroll
        for (int mt=0; mt<2; mt++)
#pragma unroll
            for (int r2=0; r2<2; r2++){
                vsum[mt][r2] += __shfl_xor_sync(0xffffffffu, vsum[mt][r2], 1);
                vsum[mt][r2] += __shfl_xor_sync(0xffffffffu, vsum[mt][r2], 2);
                vsq[mt][r2]  += __shfl_xor_sync(0xffffffffu, vsq[mt][r2], 1);
                vsq[mt][r2]  += __shfl_xor_sync(0xffffffffu, vsq[mt][r2], 2);
            }
        if (q == 0){
#pragma unroll
            for (int mt=0; mt<2; mt++)
#pragma unroll
                for (int r2=0; r2<2; r2++){
                    int r = wm*32 + mt*16 + g + r2*8;
                    sS[wn][r] = vsum[mt][r2];
                    sQ[wn][r] = vsq[mt][r2];
                }
        }
        __syncthreads();
#pragma unroll
        for (int mt=0; mt<2; mt++){
            int r0 = wm*32 + mt*16 + g, r1 = r0 + 8;
            float mean0 = (sS[0][r0]+sS[1][r0]) * (1.f/128.f);
            float mean1 = (sS[0][r1]+sS[1][r1]) * (1.f/128.f);
            float var0  = (sQ[0][r0]+sQ[1][r0]) * (1.f/128.f) - mean0*mean0;
            float var1  = (sQ[0][r1]+sQ[1][r1]) * (1.f/128.f) - mean1*mean1;
            float rs0 = rsqrtf(var0 + 1e-5f);
            float rs1 = rsqrtf(var1 + 1e-5f);
            int row0 = bm + r0;
#pragma unroll
            for (int nt=0; nt<8; nt++){
                int col = bn + wn*64 + nt*8 + q*2;
                float2 gg = *(const float2*)&lng[col];
                float2 bb = *(const float2*)&lnb[col];
                float y0 = (acc[mt][nt][0]-mean0)*rs0*gg.x + bb.x;
                float y1 = (acc[mt][nt][1]-mean0)*rs0*gg.y + bb.y;
                float y2 = (acc[mt][nt][2]-mean1)*rs1*gg.x + bb.x;
                float y3 = (acc[mt][nt][3]-mean1)*rs1*gg.y + bb.y;
                *(float2*)&C32[(size_t)row0*128 + col]     = make_float2(y0,y1);
                *(float2*)&C32[(size_t)(row0+8)*128 + col] = make_float2(y2,y3);
                *(__half2*)&C16[(size_t)row0*128 + col]     = __floats2half2_rn(y0,y1);
                *(__half2*)&C16[(size_t)(row0+8)*128 + col] = __floats2half2_rn(y2,y3);
            }
        }
        return;
    }

#pragma unroll
    for (int mt=0; mt<2; mt++){
        int row = bm + wm*32 + mt*16 + g;
#pragma unroll
        for (int nt=0; nt<8; nt++){
            int col = bn + wn*64 + nt*8 + q*2;
            float2 bv = *(const float2*)&bias[col];
            float v0 = acc[mt][nt][0] + bv.x;
            float v1 = acc[mt][nt][1] + bv.y;
            float v2 = acc[mt][nt][2] + bv.x;
            float v3 = acc[mt][nt][3] + bv.y;
            if (RELU){
                v0=fmaxf(v0,0.f); v1=fmaxf(v1,0.f);
                v2=fmaxf(v2,0.f); v3=fmaxf(v3,0.f);
            }
            if (WF32){
                *(float2*)&C32[(size_t)row*N + col]     = make_float2(v0,v1);
                *(float2*)&C32[(size_t)(row+8)*N + col] = make_float2(v2,v3);
            }
            if (WF16){
                *(__half2*)&C16[(size_t)row*N + col]     = __floats2half2_rn(v0,v1);
                *(__half2*)&C16[(size_t)(row+8)*N + col] = __floats2half2_rn(v2,v3);
            }
        }
    }
}

// ---------------- f16-accumulator GEMM (qkv only) ----------------
__global__ __launch_bounds__(256)
void hgemm16(const __half* __restrict__ A, const __half* __restrict__ W,
             const float* __restrict__ bias, __half* __restrict__ C16,
             int N, int K)
{
    __shared__ __align__(16) __half As[2][128*32];
    __shared__ __align__(16) __half Ws[2][32*128];
    const int tid = threadIdx.x;
    const int lane = tid & 31, wid = tid >> 5;
    const int wm = wid & 3, wn = wid >> 2;
    const int bm = blockIdx.y * 128, bn = blockIdx.x * 128;

    uint32_t hacc[2][8][2];
#pragma unroll
    for (int i=0;i<2;i++)
#pragma unroll
        for (int j=0;j<8;j++){ hacc[i][j][0]=0u; hacc[i][j][1]=0u; }

    const int KT = K/32;

    auto issue = [&](int kt){
        int buf = kt & 1;
        int k0  = kt * 32;
        uint32_t sA = su32(&As[buf][0]);
        uint32_t sW = su32(&Ws[buf][0]);
#pragma unroll
        for (int i=0;i<2;i++){
            int id = tid + i*256;
            int r = id >> 2, c = id & 3;
            cpa16(sA + r*64 + ((c ^ ((r>>1)&3)) << 4),
                  A + (size_t)(bm + r)*K + k0 + c*8);
            int k = id >> 4, cc = id & 15;
            cpa16(sW + k*256 + ((cc ^ (k&7)) << 4),
                  W + (size_t)(k0 + k)*N + bn + cc*8);
        }
        asm volatile("cp.async.commit_group;":::"memory");
    };

    issue(0);
    for (int kt = 0; kt < KT; kt++){
        int buf = kt & 1;
        if (kt + 1 < KT){
            issue(kt + 1);
            asm volatile("cp.async.wait_group 1;":::"memory");
        } else {
            asm volatile("cp.async.wait_group 0;":::"memory");
        }
        __syncthreads();
        uint32_t sA = su32(&As[buf][0]);
        uint32_t sW = su32(&Ws[buf][0]);
#pragma unroll
        for (int ks = 0; ks < 32; ks += 16){
            uint32_t afr[2][4];
#pragma unroll
            for (int mt=0; mt<2; mt++){
                int r = wm*32 + mt*16 + (lane & 15);
                int cg = (ks >> 3) + (lane >> 4);
                ldmx4(sA + r*64 + ((cg ^ ((r>>1)&3)) << 4),
                      afr[mt][0], afr[mt][1], afr[mt][2], afr[mt][3]);
            }
            uint32_t bfr[4][4];
#pragma unroll
            for (int ntp=0; ntp<4; ntp++){
                int k  = ks + (lane & 15);
                int cc = wn*8 + ntp*2 + (lane >> 4);
                ldmx4t(sW + k*256 + ((cc ^ (k&7)) << 4),
                       bfr[ntp][0], bfr[ntp][1], bfr[ntp][2], bfr[ntp][3]);
            }
#pragma unroll
            for (int mt=0; mt<2; mt++)
#pragma unroll
                for (int nt=0; nt<8; nt++)
                    mma16816hacc(hacc[mt][nt][0], hacc[mt][nt][1], afr[mt],
                                 bfr[nt>>1][(nt&1)*2], bfr[nt>>1][(nt&1)*2+1]);
        }
        __syncthreads();
    }

    const int g = lane >> 2, q = lane & 3;
#pragma unroll
    for (int mt=0; mt<2; mt++){
        int row = bm + wm*32 + mt*16 + g;
#pragma unroll
        for (int nt=0; nt<8; nt++){
            int col = bn + wn*64 + nt*8 + q*2;
            float2 bv = *(const float2*)&bias[col];
            __half2 hb = __floats2half2_rn(bv.x, bv.y);
            __half2 v0 = __hadd2(*(__half2*)&hacc[mt][nt][0], hb);
            __half2 v1 = __hadd2(*(__half2*)&hacc[mt][nt][1], hb);
            *(__half2*)&C16[(size_t)row*N + col]     = v0;
            *(__half2*)&C16[(size_t)(row+8)*N + col] = v1;
        }
    }
}

// ---------------- fused FFN: h = LN(h + relu(h16@W1+b1)@W2 + b2) ----------------
// FF intermediate (128x512 fp16) lives entirely in shared memory.
__global__ __launch_bounds__(256)
void ffn_k(const __half* __restrict__ A16, const __half* __restrict__ W1,
           const float* __restrict__ b1, const __half* __restrict__ W2,
           const float* __restrict__ b2,
           float* __restrict__ h, __half* __restrict__ h16,
           const float* __restrict__ lng, const float* __restrict__ lnb)
{
    extern __shared__ __align__(16) char dsm[];
    __half* AF = (__half*)dsm;                       // 4 ktiles (32KB)
    __half* FF = (__half*)(dsm + 32768);             // 16 ktiles (128KB)
    __half* WS = (__half*)(dsm + 32768 + 131072);    // 2 bufs (16KB)
    float*  sS = (float*)(dsm + 32768 + 131072 + 16384);  // 2*128
    float*  sQ = sS + 256;

    const int tid = threadIdx.x, lane = tid & 31, wid = tid >> 5;
    const int wm = wid & 3, wn = wid >> 2;
    const int g = lane >> 2, q = lane & 3;
    const int bm = blockIdx.x * 128;

    const uint32_t sAF = su32(AF);
    const uint32_t sFF = su32(FF);
    const uint32_t sW  = su32(WS);

    // stage A block (128x128 h16) into 4 swizzled ktiles (one group)
    {
#pragma unroll
        for (int i=0;i<8;i++){
            int id = tid + i*256;            // 0..2047 vec8s
            int r = id >> 4, c = id & 15;
            int kt = c >> 2, cc = c & 3;
            cpa16(sAF + kt*8192 + r*64 + ((cc ^ ((r>>1)&3)) << 4),
                  A16 + (size_t)(bm + r)*128 + c*8);
        }
        asm volatile("cp.async.commit_group;":::"memory");
    }

    auto issueW1 = [&](int j, int kt){
        int buf = kt & 1;
        int k0  = kt * 32;
#pragma unroll
        for (int i=0;i<2;i++){
            int id = tid + i*256;
            int k = id >> 4, cc = id & 15;
            cpa16(sW + buf*8192 + k*256 + ((cc ^ (k&7)) << 4),
                  W1 + (size_t)(k0 + k)*512 + j*128 + cc*8);
        }
        asm volatile("cp.async.commit_group;":::"memory");
    };
    auto issueW2 = [&](int kt){
        int buf = kt & 1;
        int k0  = kt * 32;
#pragma unroll
        for (int i=0;i<2;i++){
            int id = tid + i*256;
            int k = id >> 4, cc = id & 15;
            cpa16(sW + buf*8192 + k*256 + ((cc ^ (k&7)) << 4),
                  W2 + (size_t)(k0 + k)*128 + cc*8);
        }
        asm volatile("cp.async.commit_group;":::"memory");
    };

    // ---- phase 1: FF = relu(A @ W1 + b1) in smem ----
    for (int j=0;j<4;j++){
        float acc[2][8][4];
#pragma unroll
        for (int i=0;i<2;i++)
#pragma unroll
            for (int jj=0;jj<8;jj++)
#pragma unroll
                for (int k=0;k<4;k++) acc[i][jj][k]=0.f;

        issueW1(j, 0);
        for (int kt = 0; kt < 4; kt++){
            if (kt + 1 < 4){
                issueW1(j, kt + 1);
                asm volatile("cp.async.wait_group 1;":::"memory");
            } else {
                asm volatile("cp.async.wait_group 0;":::"memory");
            }
            __syncthreads();
            uint32_t sWb = sW + (kt&1)*8192;
#pragma unroll
            for (int ks = 0; ks < 32; ks += 16){
                uint32_t afr[2][4];
#pragma unroll
                for (int mt=0; mt<2; mt++){
                    int r = wm*32 + mt*16 + (lane & 15);
                    int cg = (ks >> 3) + (lane >> 4);
                    ldmx4(sAF + kt*8192 + r*64 + ((cg ^ ((r>>1)&3)) << 4),
                          afr[mt][0], afr[mt][1], afr[mt][2], afr[mt][3]);
                }
                uint32_t bfr[4][4];
#pragma unroll
                for (int ntp=0; ntp<4; ntp++){
                    int k  = ks + (lane & 15);
                    int cc = wn*8 + ntp*2 + (lane >> 4);
                    ldmx4t(sWb + k*256 + ((cc ^ (k&7)) << 4),
                           bfr[ntp][0], bfr[ntp][1], bfr[ntp][2], bfr[ntp][3]);
                }
#pragma unroll
                for (int mt=0; mt<2; mt++)
#pragma unroll
                    for (int nt=0; nt<8; nt++)
                        mma16816(acc[mt][nt], afr[mt],
                                 bfr[nt>>1][(nt&1)*2], bfr[nt>>1][(nt&1)*2+1]);
            }
            __syncthreads();
        }
        // epilogue: relu -> fp16 -> FF smem ktiles
#pragma unroll
        for (int mt=0; mt<2; mt++){
            int row0 = wm*32 + mt*16 + g;
            int row1 = row0 + 8;
#pragma unroll
            for (int nt=0; nt<8; nt++){
                int col = j*128 + wn*64 + nt*8 + q*2;
                float2 bv = *(const float2*)&b1[col];
                float v0 = fmaxf(acc[mt][nt][0] + bv.x, 0.f);
                float v1 = fmaxf(acc[mt][nt][1] + bv.y, 0.f);
                float v2 = fmaxf(acc[mt][nt][2] + bv.x, 0.f);
                float v3 = fmaxf(acc[mt][nt][3] + bv.y, 0.f);
                int ktile = col >> 5, c = col & 31, c8 = c >> 3;
                int base = ktile*8192 + (c&7)*2;
                int o0 = base + row0*64 + ((c8 ^ ((row0>>1)&3)) << 4);
                int o1 = base + row1*64 + ((c8 ^ ((row1>>1)&3)) << 4);
                *(__half2*)((char*)FF + o0) = __floats2half2_rn(v0, v1);
                *(__half2*)((char*)FF + o1) = __floats2half2_rn(v2, v3);
            }
        }
    }
    __syncthreads();   // FF complete and visible to all warps

    // ---- phase 2: out = LN(resid + FF @ W2 + b2) ----
    float acc[2][8][4];
#pragma unroll
    for (int i=0;i<2;i++)
#pragma unroll
        for (int jj=0;jj<8;jj++)
#pragma unroll
            for (int k=0;k<4;k++) acc[i][jj][k]=0.f;

    issueW2(0);
    for (int kt = 0; kt < 16; kt++){
        if (kt + 1 < 16){
            issueW2(kt + 1);
            asm volatile("cp.async.wait_group 1;":::"memory");
        } else {
            asm volatile("cp.async.wait_group 0;":::"memory");
        }
        __syncthreads();
        uint32_t sWb = sW + (kt&1)*8192;
#pragma unroll
        for (int ks = 0; ks < 32; ks += 16){
            uint32_t afr[2][4];
#pragma unroll
            for (int mt=0; mt<2; mt++){
                int r = wm*32 + mt*16 + (lane & 15);
                int cg = (ks >> 3) + (lane >> 4);
                ldmx4(sFF + kt*8192 + r*64 + ((cg ^ ((r>>1)&3)) << 4),
                      afr[mt][0], afr[mt][1], afr[mt][2], afr[mt][3]);
            }
            uint32_t bfr[4][4];
#pragma unroll
            for (int ntp=0; ntp<4; ntp++){
                int k  = ks + (lane & 15);
                int cc = wn*8 + ntp*2 + (lane >> 4);
                ldmx4t(sWb + k*256 + ((cc ^ (k&7)) << 4),
                       bfr[ntp][0], bfr[ntp][1], bfr[ntp][2], bfr[ntp][3]);
            }
#pragma unroll
            for (int mt=0; mt<2; mt++)
#pragma unroll
                for (int nt=0; nt<8; nt++)
                    mma16816(acc[mt][nt], afr[mt],
                             bfr[nt>>1][(nt&1)*2], bfr[nt>>1][(nt&1)*2+1]);
        }
        __syncthreads();
    }

    // fused residual + LN epilogue (N=128, bn=0)
    {
        float vsum[2][2], vsq[2][2];
#pragma unroll
        for (int mt=0; mt<2; mt++){ vsum[mt][0]=vsum[mt][1]=0.f; vsq[mt][0]=vsq[mt][1]=0.f; }
#pragma unroll
        for (int mt=0; mt<2; mt++){
            int row0 = bm + wm*32 + mt*16 + g;
#pragma unroll
            for (int nt=0; nt<8; nt++){
                int col = wn*64 + nt*8 + q*2;
                float2 bv  = *(const float2*)&b2[col];
                float2 rr0 = *(const float2*)&h[(size_t)row0*128 + col];
                float2 rr1 = *(const float2*)&h[(size_t)(row0+8)*128 + col];
                float v0 = acc[mt][nt][0] + bv.x + rr0.x;
                float v1 = acc[mt][nt][1] + bv.y + rr0.y;
                float v2 = acc[mt][nt][2] + bv.x + rr1.x;
                float v3 = acc[mt][nt][3] + bv.y + rr1.y;
                acc[mt][nt][0]=v0; acc[mt][nt][1]=v1;
                acc[mt][nt][2]=v2; acc[mt][nt][3]=v3;
                vsum[mt][0] += v0+v1; vsq[mt][0] = fmaf(v0,v0,fmaf(v1,v1,vsq[mt][0]));
                vsum[mt][1] += v2+v3; vsq[mt][1] = fmaf(v2,v2,fmaf(v3,v3,vsq[mt][1]));
            }
        }
#pragma unroll
        for (int mt=0; mt<2; mt++)
#pragma unroll
            for (int r2=0; r2<2; r2++){
                vsum[mt][r2] += __shfl_xor_sync(0xffffffffu, vsum[mt][r2], 1);
                vsum[mt][r2] += __shfl_xor_sync(0xffffffffu, vsum[mt][r2], 2);
                vsq[mt][r2]  += __shfl_xor_sync(0xffffffffu, vsq[mt][r2], 1);
                vsq[mt][r2]  += __shfl_xor_sync(0xffffffffu, vsq[mt][r2], 2);
            }
        if (q == 0){
#pragma unroll
            for (int mt=0; mt<2; mt++)
#pragma unroll
                for (int r2=0; r2<2; r2++){
                    int r = wm*32 + mt*16 + g + r2*8;
                    sS[wn*128 + r] = vsum[mt][r2];
                    sQ[wn*128 + r] = vsq[mt][r2];
                }
        }
        __syncthreads();
#pragma unroll
        for (int mt=0; mt<2; mt++){
            int r0 = wm*32 + mt*16 + g, r1 = r0 + 8;
            float mean0 = (sS[r0]+sS[128+r0]) * (1.f/128.f);
            float mean1 = (sS[r1]+sS[128+r1]) * (1.f/128.f);
            float var0  = (sQ[r0]+sQ[128+r0]) * (1.f/128.f) - mean0*mean0;
            float var1  = (sQ[r1]+sQ[128+r1]) * (1.f/128.f) - mean1*mean1;
            float rs0 = rsqrtf(var0 + 1e-5f);
            float rs1 = rsqrtf(var1 + 1e-5f);
            int row0 = bm + r0;
#pragma unroll
            for (int nt=0; nt<8; nt++){
                int col = wn*64 + nt*8 + q*2;
                float2 gg = *(const float2*)&lng[col];
                float2 bb = *(const float2*)&lnb[col];
                float y0 = (acc[mt][nt][0]-mean0)*rs0*gg.x + bb.x;
                float y1 = (acc[mt][nt][1]-mean0)*rs0*gg.y + bb.y;
                float y2 = (acc[mt][nt][2]-mean1)*rs1*gg.x + bb.x;
                float y3 = (acc[mt][nt][3]-mean1)*rs1*gg.y + bb.y;
                *(float2*)&h[(size_t)row0*128 + col]     = make_float2(y0,y1);
                *(float2*)&h[(size_t)(row0+8)*128 + col] = make_float2(y2,y3);
                *(__half2*)&h16[(size_t)row0*128 + col]     = __floats2half2_rn(y0,y1);
                *(__half2*)&h16[(size_t)(row0+8)*128 + col] = __floats2half2_rn(y2,y3);
            }
        }
    }
}

// ---------------- fused flash MHA (R8 proven) ----------------
__global__ __launch_bounds__(256)
void attn_k(const __half* __restrict__ qkv, __half* __restrict__ out)
{
    __shared__ __align__(16) __half Ks[3][128*24];
    __shared__ __align__(16) __half Vs[3][128*24];

    const int qb = blockIdx.x, h = blockIdx.y, b = blockIdx.z;
    const int tid = threadIdx.x, lane = tid & 31, w = tid >> 5;
    const int g = lane >> 2, q = lane & 3;
    const size_t base = (size_t)b * LL * 384;

    const __half2 C3 = __float2half2_rn(0.05550411f);
    const __half2 C2 = __float2half2_rn(0.24022651f);
    const __half2 C1 = __float2half2_rn(0.69314718f);
    const __half2 C0 = __float2half2_rn(1.0f);
    const uint32_t ONE2 = 0x3C003C00u;

    const int skey  = tid >> 2;
    const int spart = tid & 3;
    const __half* ssrc = qkv + base + 128 + (spart>>1)*128 + h*16 + (spart&1)*8;
    const int sd0 = skey*24 + (spart&1)*8;
    const int sd1 = (skey+64)*24 + (spart&1)*8;

    auto stage = [&](int c, int buf){
        __half* bb = (spart < 2) ? &Ks[buf][0] : &Vs[buf][0];
        cpa16(su32(bb + sd0), ssrc + (size_t)(c*128 + skey)*384);
        cpa16(su32(bb + sd1), ssrc + (size_t)(c*128 + skey + 64)*384);
        asm volatile("cp.async.commit_group;":::"memory");
    };

    const int koff = ((lane&7) + ((lane>>4)<<3))*48 + (((lane>>3)&1) << 4);
    const int voff = (lane&15)*48 + ((lane>>4) << 4);

    uint32_t qfr[4];
    {
        const int r0 = qb*128 + w*16 + g, r1 = r0 + 8;
        const __half* p0 = qkv + base + (size_t)r0*384 + h*16;
        const __half* p1 = qkv + base + (size_t)r1*384 + h*16;
        const __half2 cs = __float2half2_rn(0.25f * 1.44269504f);
        __half2 a0 = __hmul2(*(const __half2*)(p0 + 2*q), cs);
        __half2 a1 = __hmul2(*(const __half2*)(p1 + 2*q), cs);
        __half2 a2 = __hmul2(*(const __half2*)(p0 + 8 + 2*q), cs);
        __half2 a3 = __hmul2(*(const __half2*)(p1 + 8 + 2*q), cs);
        qfr[0] = *(uint32_t*)&a0; qfr[1] = *(uint32_t*)&a1;
        qfr[2] = *(uint32_t*)&a2; qfr[3] = *(uint32_t*)&a3;
    }

    auto exp2h2 = [&](uint32_t s)->uint32_t{
        __half2 y = *(__half2*)&s;
        __half2 p = __hfma2(C3, y, C2);
        p = __hfma2(p, y, C1);
        p = __hfma2(p, y, C0);
        return *(uint32_t*)&p;
    };

    float of0[4]={0,0,0,0}, of1[4]={0,0,0,0}, of2[4]={0,0,0,0};

    stage(0, 0);
    stage(1, 1);
#pragma unroll
    for (int c = 0; c < 4; c++){
        if (c < 3) asm volatile("cp.async.wait_group 1;":::"memory");
        else       asm volatile("cp.async.wait_group 0;":::"memory");
        __syncthreads();
        if (c < 2) stage(c + 2, (c + 2) % 3);

        const int buf = c % 3;
        const uint32_t kb = su32(&Ks[buf][0]) + koff;
        const uint32_t vb = su32(&Vs[buf][0]) + voff;

        uint32_t pa[8][4];
#pragma unroll
        for (int jp=0; jp<8; jp++){
            uint32_t k0,k1,k2,k3, s0,s1,s2,s3;
            ldmx4(kb + jp*768, k0,k1,k2,k3);
            mma16816h(s0, s1, qfr, k0, k1);
            mma16816h(s2, s3, qfr, k2, k3);
            pa[jp][0] = exp2h2(s0); pa[jp][1] = exp2h2(s1);
            pa[jp][2] = exp2h2(s2); pa[jp][3] = exp2h2(s3);
        }
#pragma unroll
        for (int t=0; t<8; t++){
            uint32_t v0,v1,v2,v3;
            ldmx4t(vb + t*768, v0,v1,v2,v3);
            mma16816(of0, pa[t], v0, v1);
            mma16816(of1, pa[t], v2, v3);
            mma16816(of2, pa[t], ONE2, ONE2);
        }
    }

    const float i0 = 1.f / of2[0], i1 = 1.f / of2[2];
    const int row = b*LL + qb*128 + w*16 + g;
    {
        int col = h*16 + 2*q;
        *(__half2*)&out[(size_t)row*DD + col]         = __floats2half2_rn(of0[0]*i0, of0[1]*i0);
        *(__half2*)&out[(size_t)(row+8)*DD + col]     = __floats2half2_rn(of0[2]*i1, of0[3]*i1);
        *(__half2*)&out[(size_t)row*DD + col + 8]     = __floats2half2_rn(of1[0]*i0, of1[1]*i0);
        *(__half2*)&out[(size_t)(row+8)*DD + col + 8] = __floats2half2_rn(of1[2]*i1, of1[3]*i1);
    }
}

// ---------------- pooling + classifier ----------------
__global__ __launch_bounds__(256)
void pool_k(const float* __restrict__ h, float* __restrict__ pooled4)
{
    const int b = blockIdx.x, c = blockIdx.y, t = threadIdx.x;
    const int col = t & 127, hs = t >> 7;
    __shared__ float red[256];
    const float* p = h + (size_t)b*LL*DD + (size_t)(c*128 + hs*64)*DD + col;
    float s = 0.f;
    for (int l=0; l<64; l++) s += p[(size_t)l*DD];
    red[t] = s;
    __syncthreads();
    if (t < 128) pooled4[(size_t)c*NB*DD + b*DD + t] = red[t] + red[t+128];
}

__global__ __launch_bounds__(64)
void cls_k(const float* __restrict__ pooled4,
           const float* __restrict__ W1, const float* __restrict__ b1,
           const float* __restrict__ W2, const float* __restrict__ b2,
           float* __restrict__ out)
{
    const int b = blockIdx.x, t = threadIdx.x;
    __shared__ float ps[128], hid[64];
#pragma unroll
    for (int i=0;i<2;i++){
        int col = t + i*64;
        float s = 0.f;
#pragma unroll
        for (int c=0;c<4;c++) s += pooled4[(size_t)c*NB*DD + b*DD + col];
        ps[col] = s * (1.f/(float)LL);
    }
    __syncthreads();
    float a = b1[t];
    for (int k=0;k<128;k++) a = fmaf(ps[k], W1[k*64 + t], a);
    hid[t] = fmaxf(a, 0.f);
    __syncthreads();
    if (t < OUTC){
        float o = b2[t];
#pragma unroll
        for (int k=0;k<64;k++) o = fmaf(hid[k], W2[k*OUTC + t], o);
        out[b*OUTC + t] = o;
    }
}

extern "C" void kernel_launch(void* const* d_in, const int* in_sizes, int n_in,
                              void* d_out, int out_size)
{
    const float* x      = (const float*)d_in[0];
    const float* Wp     = (const float*)d_in[n_in-18];
    const float* bp     = (const float*)d_in[n_in-17];
    const float* qkv_w  = (const float*)d_in[n_in-16];
    const float* qkv_b  = (const float*)d_in[n_in-15];
    const float* out_w  = (const float*)d_in[n_in-14];
    const float* out_b  = (const float*)d_in[n_in-13];
    const float* ln1_g  = (const float*)d_in[n_in-12];
    const float* ln1_b  = (const float*)d_in[n_in-11];
    const float* ffn_w1 = (const float*)d_in[n_in-10];
    const float* ffn_b1 = (const float*)d_in[n_in-9];
    const float* ffn_w2 = (const float*)d_in[n_in-8];
    const float* ffn_b2 = (const float*)d_in[n_in-7];
    const float* ln2_g  = (const float*)d_in[n_in-6];
    const float* ln2_b  = (const float*)d_in[n_in-5];
    const float* cls_w1 = (const float*)d_in[n_in-4];
    const float* cls_b1 = (const float*)d_in[n_in-3];
    const float* cls_w2 = (const float*)d_in[n_in-2];
    const float* cls_b2 = (const float*)d_in[n_in-1];
    float* out = (float*)d_out;

    float *h, *pooled4;
    __half *h16, *x16, *qkv16, *whi;
    cudaGetSymbolAddress((void**)&h,       g_h);
    cudaGetSymbolAddress((void**)&pooled4, g_pool4);
    cudaGetSymbolAddress((void**)&h16,     g_h16);
    cudaGetSymbolAddress((void**)&x16,     g_x16);
    cudaGetSymbolAddress((void**)&qkv16,   g_qkv16);
    cudaGetSymbolAddress((void**)&whi,     g_whi);
    __half* attn16 = x16;   // x16 dead after input projection; reuse (L2-friendly)

    cudaFuncSetAttribute(ffn_k, cudaFuncAttributeMaxDynamicSharedMemorySize, FFN_SMEM);

    cvtall<<<2048,256>>>(Wp, qkv_w, out_w, ffn_w1, ffn_w2, x, whi, x16);

    const int MB = NT/128;

    hgemm<true,true,false,false><<<dim3(1,MB),256>>>(
        x16, whi+OFF_WP, bp, h, h16, DD, DD,
        (const float*)0, (const float*)0, (const float*)0);

    for (int i=0; i<NLAYERS; i++){
        hgemm16<<<dim3(3,MB),256>>>(
            h16, whi+OFF_QKV+(size_t)i*128*384,
            qkv_b+(size_t)i*384, qkv16, 384, 128);

        attn_k<<<dim3(4,HH,NB),256>>>(qkv16, attn16);

        hgemm<true,true,false,true><<<dim3(1,MB),256>>>(
            attn16, whi+OFF_OUT+(size_t)i*128*128,
            out_b+(size_t)i*128, h, h16, DD, DD,
            h, ln1_g+(size_t)i*DD, ln1_b+(size_t)i*DD);

        ffn_k<<<MB,256,FFN_SMEM>>>(
            h16, whi+OFF_F1+(size_t)i*128*512, ffn_b1+(size_t)i*512,
            whi+OFF_F2+(size_t)i*512*128, ffn_b2+(size_t)i*128,
            h, h16, ln2_g+(size_t)i*DD, ln2_b+(size_t)i*DD);
    }

    pool_k<<<dim3(NB,4),256>>>(h, pooled4);
    cls_k<<<NB,64>>>(pooled4, cls_w1, cls_b1, cls_w2, cls_b2, out);

    (void)in_sizes; (void)out_size;
}

// round 13
// speedup vs baseline: 1.5381x; 1.0080x over previous
#include <cuda_runtime.h>
#include <cuda_fp16.h>
#include <math.h>
#include <stdint.h>

#define NB 64
#define LL 512
#define NT (NB*LL)
#define DD 128
#define HH 8
#define FFD 512
#define NLAYERS 6
#define OUTC 10

#define SZ_WP   (128*128)
#define SZ_QKV  (NLAYERS*128*384)
#define SZ_OUT  (NLAYERS*128*128)
#define SZ_F1   (NLAYERS*128*512)
#define SZ_F2   (NLAYERS*512*128)
#define OFF_WP  0
#define OFF_QKV (SZ_WP)
#define OFF_OUT (OFF_QKV+SZ_QKV)
#define OFF_F1  (OFF_OUT+SZ_OUT)
#define OFF_F2  (OFF_F1+SZ_F1)
#define W16_TOT (OFF_F2+SZ_F2)

// fused FFN dynamic smem: AF 32KB + FF 128KB + Ws 16KB + LN 2KB
#define FFN_SMEM (32768 + 131072 + 16384 + 2048)

typedef unsigned long long ull;

__device__ float  g_h   [NT*DD];
__device__ __align__(16) __half g_h16   [NT*DD];
__device__ __align__(16) __half g_x16   [NT*DD];   // also reused as attn16
__device__ __align__(16) __half g_qkv16 [NT*3*DD];
__device__ __align__(16) __half g_whi   [W16_TOT];
__device__ float g_pool4[4][NB*DD];

__device__ __forceinline__ uint32_t su32(const void* p){
    return (uint32_t)__cvta_generic_to_shared(p);
}
__device__ __forceinline__ void ldmx4(uint32_t a, uint32_t& r0, uint32_t& r1,
                                      uint32_t& r2, uint32_t& r3){
    asm volatile("ldmatrix.sync.aligned.m8n8.x4.shared.b16 {%0,%1,%2,%3},[%4];"
        :"=r"(r0),"=r"(r1),"=r"(r2),"=r"(r3):"r"(a));
}
__device__ __forceinline__ void ldmx4t(uint32_t a, uint32_t& r0, uint32_t& r1,
                                       uint32_t& r2, uint32_t& r3){
    asm volatile("ldmatrix.sync.aligned.m8n8.x4.trans.shared.b16 {%0,%1,%2,%3},[%4];"
        :"=r"(r0),"=r"(r1),"=r"(r2),"=r"(r3):"r"(a));
}
__device__ __forceinline__ void mma16816(float* c, const uint32_t* a,
                                         uint32_t b0, uint32_t b1){
    asm volatile("mma.sync.aligned.m16n8k16.row.col.f32.f16.f16.f32 "
        "{%0,%1,%2,%3},{%4,%5,%6,%7},{%8,%9},{%0,%1,%2,%3};"
        :"+f"(c[0]),"+f"(c[1]),"+f"(c[2]),"+f"(c[3])
        :"r"(a[0]),"r"(a[1]),"r"(a[2]),"r"(a[3]),"r"(b0),"r"(b1));
}
__device__ __forceinline__ void mma16816h(uint32_t& d0, uint32_t& d1,
                                          const uint32_t* a,
                                          uint32_t b0, uint32_t b1){
    asm volatile("mma.sync.aligned.m16n8k16.row.col.f16.f16.f16.f16 "
        "{%0,%1},{%2,%3,%4,%5},{%6,%7},{%8,%9};"
        :"=r"(d0),"=r"(d1)
        :"r"(a[0]),"r"(a[1]),"r"(a[2]),"r"(a[3]),"r"(b0),"r"(b1),
         "r"(0u),"r"(0u));
}
__device__ __forceinline__ void mma16816hacc(uint32_t& d0, uint32_t& d1,
                                             const uint32_t* a,
                                             uint32_t b0, uint32_t b1){
    asm volatile("mma.sync.aligned.m16n8k16.row.col.f16.f16.f16.f16 "
        "{%0,%1},{%2,%3,%4,%5},{%6,%7},{%0,%1};"
        :"+r"(d0),"+r"(d1)
        :"r"(a[0]),"r"(a[1]),"r"(a[2]),"r"(a[3]),"r"(b0),"r"(b1));
}
__device__ __forceinline__ void cpa16(uint32_t dst, const void* src){
    asm volatile("cp.async.cg.shared.global [%0],[%1],16;"::"r"(dst),"l"(src));
}

// ---------------- single fused conversion kernel ----------------
__global__ void cvtall(const float* __restrict__ Wp, const float* __restrict__ qkvw,
                       const float* __restrict__ outw, const float* __restrict__ f1,
                       const float* __restrict__ f2, const float* __restrict__ x,
                       __half* __restrict__ hi, __half* __restrict__ x16)
{
    const int TOT = W16_TOT + NT*DD;
    for (int i = blockIdx.x*blockDim.x + threadIdx.x; i < TOT;
         i += gridDim.x*blockDim.x){
        if (i >= W16_TOT){
            int j = i - W16_TOT;
            x16[j] = __float2half_rn(x[j]);
            continue;
        }
        float w;
        if (i < OFF_QKV){
            w = Wp[i];
        } else if (i < OFF_OUT){
            int j = i - OFF_QKV;
            int L = j / (128*384); int r = j - L*(128*384);
            int k = r / 384, n = r - k*384;
            w = qkvw[(size_t)L*384*128 + (size_t)n*128 + k];
        } else if (i < OFF_F1){
            int j = i - OFF_OUT;
            int L = j / (128*128); int r = j - L*(128*128);
            int k = r >> 7, n = r & 127;
            w = outw[(size_t)L*128*128 + (size_t)n*128 + k];
        } else if (i < OFF_F2){
            w = f1[i - OFF_F1];
        } else {
            w = f2[i - OFF_F2];
        }
        hi[i] = __float2half_rn(w);
    }
}

// ---------------- fp16 tensor-core GEMM (f32 accum; R8 proven) ----------------
template<bool WF32, bool WF16, bool RELU, bool LN>
__global__ __launch_bounds__(256)
void hgemm(const __half* __restrict__ A, const __half* __restrict__ W,
           const float* __restrict__ bias,
           float* __restrict__ C32, __half* __restrict__ C16, int N, int K,
           const float* __restrict__ resid, const float* __restrict__ lng,
           const float* __restrict__ lnb)
{
    __shared__ __align__(16) __half As[2][128*32];
    __shared__ __align__(16) __half Ws[2][32*128];
    const int tid = threadIdx.x;
    const int lane = tid & 31, wid = tid >> 5;
    const int wm = wid & 3, wn = wid >> 2;
    const int bm = blockIdx.y * 128, bn = blockIdx.x * 128;

    float acc[2][8][4];
#pragma unroll
    for (int i=0;i<2;i++)
#pragma unroll
        for (int j=0;j<8;j++)
#pragma unroll
            for (int k=0;k<4;k++) acc[i][j][k]=0.f;

    const int KT = K/32;

    auto issue = [&](int kt){
        int buf = kt & 1;
        int k0  = kt * 32;
        uint32_t sA = su32(&As[buf][0]);
        uint32_t sW = su32(&Ws[buf][0]);
#pragma unroll
        for (int i=0;i<2;i++){
            int id = tid + i*256;
            int r = id >> 2, c = id & 3;
            cpa16(sA + r*64 + ((c ^ ((r>>1)&3)) << 4),
                  A + (size_t)(bm + r)*K + k0 + c*8);
            int k = id >> 4, cc = id & 15;
            cpa16(sW + k*256 + ((cc ^ (k&7)) << 4),
                  W + (size_t)(k0 + k)*N + bn + cc*8);
        }
        asm volatile("cp.async.commit_group;":::"memory");
    };

    issue(0);
    for (int kt = 0; kt < KT; kt++){
        int buf = kt & 1;
        if (kt + 1 < KT){
            issue(kt + 1);
            asm volatile("cp.async.wait_group 1;":::"memory");
        } else {
            asm volatile("cp.async.wait_group 0;":::"memory");
        }
        __syncthreads();
        uint32_t sA = su32(&As[buf][0]);
        uint32_t sW = su32(&Ws[buf][0]);
#pragma unroll
        for (int ks = 0; ks < 32; ks += 16){
            uint32_t afr[2][4];
#pragma unroll
            for (int mt=0; mt<2; mt++){
                int r = wm*32 + mt*16 + (lane & 15);
                int cg = (ks >> 3) + (lane >> 4);
                ldmx4(sA + r*64 + ((cg ^ ((r>>1)&3)) << 4),
                      afr[mt][0], afr[mt][1], afr[mt][2], afr[mt][3]);
            }
            uint32_t bfr[4][4];
#pragma unroll
            for (int ntp=0; ntp<4; ntp++){
                int k  = ks + (lane & 15);
                int cc = wn*8 + ntp*2 + (lane >> 4);
                ldmx4t(sW + k*256 + ((cc ^ (k&7)) << 4),
                       bfr[ntp][0], bfr[ntp][1], bfr[ntp][2], bfr[ntp][3]);
            }
#pragma unroll
            for (int mt=0; mt<2; mt++)
#pragma unroll
                for (int nt=0; nt<8; nt++)
                    mma16816(acc[mt][nt], afr[mt],
                             bfr[nt>>1][(nt&1)*2], bfr[nt>>1][(nt&1)*2+1]);
        }
        __syncthreads();
    }

    const int g = lane >> 2, q = lane & 3;

    if (LN) {
        __shared__ float sS[2][128], sQ[2][128];
        float vsum[2][2], vsq[2][2];
#pragma unroll
        for (int mt=0; mt<2; mt++){ vsum[mt][0]=vsum[mt][1]=0.f; vsq[mt][0]=vsq[mt][1]=0.f; }
#pragma unroll
        for (int mt=0; mt<2; mt++){
            int row0 = bm + wm*32 + mt*16 + g;
#pragma unroll
            for (int nt=0; nt<8; nt++){
                int col = bn + wn*64 + nt*8 + q*2;
                float2 bv  = *(const float2*)&bias[col];
                float2 rr0 = *(const float2*)&resid[(size_t)row0*128 + col];
                float2 rr1 = *(const float2*)&resid[(size_t)(row0+8)*128 + col];
                float v0 = acc[mt][nt][0] + bv.x + rr0.x;
                float v1 = acc[mt][nt][1] + bv.y + rr0.y;
                float v2 = acc[mt][nt][2] + bv.x + rr1.x;
                float v3 = acc[mt][nt][3] + bv.y + rr1.y;
                acc[mt][nt][0]=v0; acc[mt][nt][1]=v1;
                acc[mt][nt][2]=v2; acc[mt][nt][3]=v3;
                vsum[mt][0] += v0+v1; vsq[mt][0] = fmaf(v0,v0,fmaf(v1,v1,vsq[mt][0]));
                vsum[mt][1] += v2+v3; vsq[mt][1] = fmaf(v2,v2,fmaf(v3,v3,vsq[mt][1]));
            }
        }
#pragma unroll
        for (int mt=0; mt<2; mt++)
#pragma unroll
            for (int r2=0; r2<2; r2++){
                vsum[mt][r2] += __shfl_xor_sync(0xffffffffu, vsum[mt][r2], 1);
                vsum[mt][r2] += __shfl_xor_sync(0xffffffffu, vsum[mt][r2], 2);
                vsq[mt][r2]  += __shfl_xor_sync(0xffffffffu, vsq[mt][r2], 1);
                vsq[mt][r2]  += __shfl_xor_sync(0xffffffffu, vsq[mt][r2], 2);
            }
        if (q == 0){
#pragma unroll
            for (int mt=0; mt<2; mt++)
#pragma unroll
                for (int r2=0; r2<2; r2++){
                    int r = wm*32 + mt*16 + g + r2*8;
                    sS[wn][r] = vsum[mt][r2];
                    sQ[wn][r] = vsq[mt][r2];
                }
        }
        __syncthreads();
#pragma unroll
        for (int mt=0; mt<2; mt++){
            int r0 = wm*32 + mt*16 + g, r1 = r0 + 8;
            float mean0 = (sS[0][r0]+sS[1][r0]) * (1.f/128.f);
            float mean1 = (sS[0][r1]+sS[1][r1]) * (1.f/128.f);
            float var0  = (sQ[0][r0]+sQ[1][r0]) * (1.f/128.f) - mean0*mean0;
            float var1  = (sQ[0][r1]+sQ[1][r1]) * (1.f/128.f) - mean1*mean1;
            float rs0 = rsqrtf(var0 + 1e-5f);
            float rs1 = rsqrtf(var1 + 1e-5f);
            int row0 = bm + r0;
#pragma unroll
            for (int nt=0; nt<8; nt++){
                int col = bn + wn*64 + nt*8 + q*2;
                float2 gg = *(const float2*)&lng[col];
                float2 bb = *(const float2*)&lnb[col];
                float y0 = (acc[mt][nt][0]-mean0)*rs0*gg.x + bb.x;
                float y1 = (acc[mt][nt][1]-mean0)*rs0*gg.y + bb.y;
                float y2 = (acc[mt][nt][2]-mean1)*rs1*gg.x + bb.x;
                float y3 = (acc[mt][nt][3]-mean1)*rs1*gg.y + bb.y;
                *(float2*)&C32[(size_t)row0*128 + col]     = make_float2(y0,y1);
                *(float2*)&C32[(size_t)(row0+8)*128 + col] = make_float2(y2,y3);
                *(__half2*)&C16[(size_t)row0*128 + col]     = __floats2half2_rn(y0,y1);
                *(__half2*)&C16[(size_t)(row0+8)*128 + col] = __floats2half2_rn(y2,y3);
            }
        }
        return;
    }

#pragma unroll
    for (int mt=0; mt<2; mt++){
        int row = bm + wm*32 + mt*16 + g;
#pragma unroll
        for (int nt=0; nt<8; nt++){
            int col = bn + wn*64 + nt*8 + q*2;
            float2 bv = *(const float2*)&bias[col];
            float v0 = acc[mt][nt][0] + bv.x;
            float v1 = acc[mt][nt][1] + bv.y;
            float v2 = acc[mt][nt][2] + bv.x;
            float v3 = acc[mt][nt][3] + bv.y;
            if (RELU){
                v0=fmaxf(v0,0.f); v1=fmaxf(v1,0.f);
                v2=fmaxf(v2,0.f); v3=fmaxf(v3,0.f);
            }
            if (WF32){
                *(float2*)&C32[(size_t)row*N + col]     = make_float2(v0,v1);
                *(float2*)&C32[(size_t)(row+8)*N + col] = make_float2(v2,v3);
            }
            if (WF16){
                *(__half2*)&C16[(size_t)row*N + col]     = __floats2half2_rn(v0,v1);
                *(__half2*)&C16[(size_t)(row+8)*N + col] = __floats2half2_rn(v2,v3);
            }
        }
    }
}

// ---------------- f16-accumulator GEMM (qkv only) ----------------
__global__ __launch_bounds__(256)
void hgemm16(const __half* __restrict__ A, const __half* __restrict__ W,
             const float* __restrict__ bias, __half* __restrict__ C16,
             int N, int K)
{
    __shared__ __align__(16) __half As[2][128*32];
    __shared__ __align__(16) __half Ws[2][32*128];
    const int tid = threadIdx.x;
    const int lane = tid & 31, wid = tid >> 5;
    const int wm = wid & 3, wn = wid >> 2;
    const int bm = blockIdx.y * 128, bn = blockIdx.x * 128;

    uint32_t hacc[2][8][2];
#pragma unroll
    for (int i=0;i<2;i++)
#pragma unroll
        for (int j=0;j<8;j++){ hacc[i][j][0]=0u; hacc[i][j][1]=0u; }

    const int KT = K/32;

    auto issue = [&](int kt){
        int buf = kt & 1;
        int k0  = kt * 32;
        uint32_t sA = su32(&As[buf][0]);
        uint32_t sW = su32(&Ws[buf][0]);
#pragma unroll
        for (int i=0;i<2;i++){
            int id = tid + i*256;
            int r = id >> 2, c = id & 3;
            cpa16(sA + r*64 + ((c ^ ((r>>1)&3)) << 4),
                  A + (size_t)(bm + r)*K + k0 + c*8);
            int k = id >> 4, cc = id & 15;
            cpa16(sW + k*256 + ((cc ^ (k&7)) << 4),
                  W + (size_t)(k0 + k)*N + bn + cc*8);
        }
        asm volatile("cp.async.commit_group;":::"memory");
    };

    issue(0);
    for (int kt = 0; kt < KT; kt++){
        int buf = kt & 1;
        if (kt + 1 < KT){
            issue(kt + 1);
            asm volatile("cp.async.wait_group 1;":::"memory");
        } else {
            asm volatile("cp.async.wait_group 0;":::"memory");
        }
        __syncthreads();
        uint32_t sA = su32(&As[buf][0]);
        uint32_t sW = su32(&Ws[buf][0]);
#pragma unroll
        for (int ks = 0; ks < 32; ks += 16){
            uint32_t afr[2][4];
#pragma unroll
            for (int mt=0; mt<2; mt++){
                int r = wm*32 + mt*16 + (lane & 15);
                int cg = (ks >> 3) + (lane >> 4);
                ldmx4(sA + r*64 + ((cg ^ ((r>>1)&3)) << 4),
                      afr[mt][0], afr[mt][1], afr[mt][2], afr[mt][3]);
            }
            uint32_t bfr[4][4];
#pragma unroll
            for (int ntp=0; ntp<4; ntp++){
                int k  = ks + (lane & 15);
                int cc = wn*8 + ntp*2 + (lane >> 4);
                ldmx4t(sW + k*256 + ((cc ^ (k&7)) << 4),
                       bfr[ntp][0], bfr[ntp][1], bfr[ntp][2], bfr[ntp][3]);
            }
#pragma unroll
            for (int mt=0; mt<2; mt++)
#pragma unroll
                for (int nt=0; nt<8; nt++)
                    mma16816hacc(hacc[mt][nt][0], hacc[mt][nt][1], afr[mt],
                                 bfr[nt>>1][(nt&1)*2], bfr[nt>>1][(nt&1)*2+1]);
        }
        __syncthreads();
    }

    const int g = lane >> 2, q = lane & 3;
#pragma unroll
    for (int mt=0; mt<2; mt++){
        int row = bm + wm*32 + mt*16 + g;
#pragma unroll
        for (int nt=0; nt<8; nt++){
            int col = bn + wn*64 + nt*8 + q*2;
            float2 bv = *(const float2*)&bias[col];
            __half2 hb = __floats2half2_rn(bv.x, bv.y);
            __half2 v0 = __hadd2(*(__half2*)&hacc[mt][nt][0], hb);
            __half2 v1 = __hadd2(*(__half2*)&hacc[mt][nt][1], hb);
            *(__half2*)&C16[(size_t)row*N + col]     = v0;
            *(__half2*)&C16[(size_t)(row+8)*N + col] = v1;
        }
    }
}

// ---------------- fused FFN: h = LN(h + relu(h16@W1+b1)@W2 + b2) ----------------
__global__ __launch_bounds__(256)
void ffn_k(const __half* __restrict__ A16, const __half* __restrict__ W1,
           const float* __restrict__ b1, const __half* __restrict__ W2,
           const float* __restrict__ b2,
           float* __restrict__ h, __half* __restrict__ h16,
           const float* __restrict__ lng, const float* __restrict__ lnb)
{
    extern __shared__ __align__(16) char dsm[];
    __half* AF = (__half*)dsm;
    __half* FF = (__half*)(dsm + 32768);
    __half* WS = (__half*)(dsm + 32768 + 131072);
    float*  sS = (float*)(dsm + 32768 + 131072 + 16384);
    float*  sQ = sS + 256;

    const int tid = threadIdx.x, lane = tid & 31, wid = tid >> 5;
    const int wm = wid & 3, wn = wid >> 2;
    const int g = lane >> 2, q = lane & 3;
    const int bm = blockIdx.x * 128;

    const uint32_t sAF = su32(AF);
    const uint32_t sFF = su32(FF);
    const uint32_t sW  = su32(WS);

    {
#pragma unroll
        for (int i=0;i<8;i++){
            int id = tid + i*256;
            int r = id >> 4, c = id & 15;
            int kt = c >> 2, cc = c & 3;
            cpa16(sAF + kt*8192 + r*64 + ((cc ^ ((r>>1)&3)) << 4),
                  A16 + (size_t)(bm + r)*128 + c*8);
        }
        asm volatile("cp.async.commit_group;":::"memory");
    }

    auto issueW1 = [&](int j, int kt){
        int buf = kt & 1;
        int k0  = kt * 32;
#pragma unroll
        for (int i=0;i<2;i++){
            int id = tid + i*256;
            int k = id >> 4, cc = id & 15;
            cpa16(sW + buf*8192 + k*256 + ((cc ^ (k&7)) << 4),
                  W1 + (size_t)(k0 + k)*512 + j*128 + cc*8);
        }
        asm volatile("cp.async.commit_group;":::"memory");
    };
    auto issueW2 = [&](int kt){
        int buf = kt & 1;
        int k0  = kt * 32;
#pragma unroll
        for (int i=0;i<2;i++){
            int id = tid + i*256;
            int k = id >> 4, cc = id & 15;
            cpa16(sW + buf*8192 + k*256 + ((cc ^ (k&7)) << 4),
                  W2 + (size_t)(k0 + k)*128 + cc*8);
        }
        asm volatile("cp.async.commit_group;":::"memory");
    };

    // ---- phase 1: FF = relu(A @ W1 + b1) in smem ----
    for (int j=0;j<4;j++){
        float acc[2][8][4];
#pragma unroll
        for (int i=0;i<2;i++)
#pragma unroll
            for (int jj=0;jj<8;jj++)
#pragma unroll
                for (int k=0;k<4;k++) acc[i][jj][k]=0.f;

        issueW1(j, 0);
        for (int kt = 0; kt < 4; kt++){
            if (kt + 1 < 4){
                issueW1(j, kt + 1);
                asm volatile("cp.async.wait_group 1;":::"memory");
            } else {
                asm volatile("cp.async.wait_group 0;":::"memory");
            }
            __syncthreads();
            uint32_t sWb = sW + (kt&1)*8192;
#pragma unroll
            for (int ks = 0; ks < 32; ks += 16){
                uint32_t afr[2][4];
#pragma unroll
                for (int mt=0; mt<2; mt++){
                    int r = wm*32 + mt*16 + (lane & 15);
                    int cg = (ks >> 3) + (lane >> 4);
                    ldmx4(sAF + kt*8192 + r*64 + ((cg ^ ((r>>1)&3)) << 4),
                          afr[mt][0], afr[mt][1], afr[mt][2], afr[mt][3]);
                }
                uint32_t bfr[4][4];
#pragma unroll
                for (int ntp=0; ntp<4; ntp++){
                    int k  = ks + (lane & 15);
                    int cc = wn*8 + ntp*2 + (lane >> 4);
                    ldmx4t(sWb + k*256 + ((cc ^ (k&7)) << 4),
                           bfr[ntp][0], bfr[ntp][1], bfr[ntp][2], bfr[ntp][3]);
                }
#pragma unroll
                for (int mt=0; mt<2; mt++)
#pragma unroll
                    for (int nt=0; nt<8; nt++)
                        mma16816(acc[mt][nt], afr[mt],
                                 bfr[nt>>1][(nt&1)*2], bfr[nt>>1][(nt&1)*2+1]);
            }
            __syncthreads();
        }
#pragma unroll
        for (int mt=0; mt<2; mt++){
            int row0 = wm*32 + mt*16 + g;
            int row1 = row0 + 8;
#pragma unroll
            for (int nt=0; nt<8; nt++){
                int col = j*128 + wn*64 + nt*8 + q*2;
                float2 bv = *(const float2*)&b1[col];
                float v0 = fmaxf(acc[mt][nt][0] + bv.x, 0.f);
                float v1 = fmaxf(acc[mt][nt][1] + bv.y, 0.f);
                float v2 = fmaxf(acc[mt][nt][2] + bv.x, 0.f);
                float v3 = fmaxf(acc[mt][nt][3] + bv.y, 0.f);
                int ktile = col >> 5, c = col & 31, c8 = c >> 3;
                int base = ktile*8192 + (c&7)*2;
                int o0 = base + row0*64 + ((c8 ^ ((row0>>1)&3)) << 4);
                int o1 = base + row1*64 + ((c8 ^ ((row1>>1)&3)) << 4);
                *(__half2*)((char*)FF + o0) = __floats2half2_rn(v0, v1);
                *(__half2*)((char*)FF + o1) = __floats2half2_rn(v2, v3);
            }
        }
    }
    __syncthreads();

    // ---- phase 2: out = LN(resid + FF @ W2 + b2) ----
    float acc[2][8][4];
#pragma unroll
    for (int i=0;i<2;i++)
#pragma unroll
        for (int jj=0;jj<8;jj++)
#pragma unroll
            for (int k=0;k<4;k++) acc[i][jj][k]=0.f;

    issueW2(0);
    for (int kt = 0; kt < 16; kt++){
        if (kt + 1 < 16){
            issueW2(kt + 1);
            asm volatile("cp.async.wait_group 1;":::"memory");
        } else {
            asm volatile("cp.async.wait_group 0;":::"memory");
        }
        __syncthreads();
        uint32_t sWb = sW + (kt&1)*8192;
#pragma unroll
        for (int ks = 0; ks < 32; ks += 16){
            uint32_t afr[2][4];
#pragma unroll
            for (int mt=0; mt<2; mt++){
                int r = wm*32 + mt*16 + (lane & 15);
                int cg = (ks >> 3) + (lane >> 4);
                ldmx4(sFF + kt*8192 + r*64 + ((cg ^ ((r>>1)&3)) << 4),
                      afr[mt][0], afr[mt][1], afr[mt][2], afr[mt][3]);
            }
            uint32_t bfr[4][4];
#pragma unroll
            for (int ntp=0; ntp<4; ntp++){
                int k  = ks + (lane & 15);
                int cc = wn*8 + ntp*2 + (lane >> 4);
                ldmx4t(sWb + k*256 + ((cc ^ (k&7)) << 4),
                       bfr[ntp][0], bfr[ntp][1], bfr[ntp][2], bfr[ntp][3]);
            }
#pragma unroll
            for (int mt=0; mt<2; mt++)
#pragma unroll
                for (int nt=0; nt<8; nt++)
                    mma16816(acc[mt][nt], afr[mt],
                             bfr[nt>>1][(nt&1)*2], bfr[nt>>1][(nt&1)*2+1]);
        }
        __syncthreads();
    }

    {
        float vsum[2][2], vsq[2][2];
#pragma unroll
        for (int mt=0; mt<2; mt++){ vsum[mt][0]=vsum[mt][1]=0.f; vsq[mt][0]=vsq[mt][1]=0.f; }
#pragma unroll
        for (int mt=0; mt<2; mt++){
            int row0 = bm + wm*32 + mt*16 + g;
#pragma unroll
            for (int nt=0; nt<8; nt++){
                int col = wn*64 + nt*8 + q*2;
                float2 bv  = *(const float2*)&b2[col];
                float2 rr0 = *(const float2*)&h[(size_t)row0*128 + col];
                float2 rr1 = *(const float2*)&h[(size_t)(row0+8)*128 + col];
                float v0 = acc[mt][nt][0] + bv.x + rr0.x;
                float v1 = acc[mt][nt][1] + bv.y + rr0.y;
                float v2 = acc[mt][nt][2] + bv.x + rr1.x;
                float v3 = acc[mt][nt][3] + bv.y + rr1.y;
                acc[mt][nt][0]=v0; acc[mt][nt][1]=v1;
                acc[mt][nt][2]=v2; acc[mt][nt][3]=v3;
                vsum[mt][0] += v0+v1; vsq[mt][0] = fmaf(v0,v0,fmaf(v1,v1,vsq[mt][0]));
                vsum[mt][1] += v2+v3; vsq[mt][1] = fmaf(v2,v2,fmaf(v3,v3,vsq[mt][1]));
            }
        }
#pragma unroll
        for (int mt=0; mt<2; mt++)
#pragma unroll
            for (int r2=0; r2<2; r2++){
                vsum[mt][r2] += __shfl_xor_sync(0xffffffffu, vsum[mt][r2], 1);
                vsum[mt][r2] += __shfl_xor_sync(0xffffffffu, vsum[mt][r2], 2);
                vsq[mt][r2]  += __shfl_xor_sync(0xffffffffu, vsq[mt][r2], 1);
                vsq[mt][r2]  += __shfl_xor_sync(0xffffffffu, vsq[mt][r2], 2);
            }
        if (q == 0){
#pragma unroll
            for (int mt=0; mt<2; mt++)
#pragma unroll
                for (int r2=0; r2<2; r2++){
                    int r = wm*32 + mt*16 + g + r2*8;
                    sS[wn*128 + r] = vsum[mt][r2];
                    sQ[wn*128 + r] = vsq[mt][r2];
                }
        }
        __syncthreads();
#pragma unroll
        for (int mt=0; mt<2; mt++){
            int r0 = wm*32 + mt*16 + g, r1 = r0 + 8;
            float mean0 = (sS[r0]+sS[128+r0]) * (1.f/128.f);
            float mean1 = (sS[r1]+sS[128+r1]) * (1.f/128.f);
            float var0  = (sQ[r0]+sQ[128+r0]) * (1.f/128.f) - mean0*mean0;
            float var1  = (sQ[r1]+sQ[128+r1]) * (1.f/128.f) - mean1*mean1;
            float rs0 = rsqrtf(var0 + 1e-5f);
            float rs1 = rsqrtf(var1 + 1e-5f);
            int row0 = bm + r0;
#pragma unroll
            for (int nt=0; nt<8; nt++){
                int col = wn*64 + nt*8 + q*2;
                float2 gg = *(const float2*)&lng[col];
                float2 bb = *(const float2*)&lnb[col];
                float y0 = (acc[mt][nt][0]-mean0)*rs0*gg.x + bb.x;
                float y1 = (acc[mt][nt][1]-mean0)*rs0*gg.y + bb.y;
                float y2 = (acc[mt][nt][2]-mean1)*rs1*gg.x + bb.x;
                float y3 = (acc[mt][nt][3]-mean1)*rs1*gg.y + bb.y;
                *(float2*)&h[(size_t)row0*128 + col]     = make_float2(y0,y1);
                *(float2*)&h[(size_t)(row0+8)*128 + col] = make_float2(y2,y3);
                *(__half2*)&h16[(size_t)row0*128 + col]     = __floats2half2_rn(y0,y1);
                *(__half2*)&h16[(size_t)(row0+8)*128 + col] = __floats2half2_rn(y2,y3);
            }
        }
    }
}

// ---------------- fused flash MHA v7 (f16 accumulators for P·V and l) ----------------
__global__ __launch_bounds__(256)
void attn_k(const __half* __restrict__ qkv, __half* __restrict__ out)
{
    __shared__ __align__(16) __half Ks[3][128*24];
    __shared__ __align__(16) __half Vs[3][128*24];

    const int qb = blockIdx.x, h = blockIdx.y, b = blockIdx.z;
    const int tid = threadIdx.x, lane = tid & 31, w = tid >> 5;
    const int g = lane >> 2, q = lane & 3;
    const size_t base = (size_t)b * LL * 384;

    const __half2 C3 = __float2half2_rn(0.05550411f);
    const __half2 C2 = __float2half2_rn(0.24022651f);
    const __half2 C1 = __float2half2_rn(0.69314718f);
    const __half2 C0 = __float2half2_rn(1.0f);
    const uint32_t ONE2 = 0x3C003C00u;

    const int skey  = tid >> 2;
    const int spart = tid & 3;
    const __half* ssrc = qkv + base + 128 + (spart>>1)*128 + h*16 + (spart&1)*8;
    const int sd0 = skey*24 + (spart&1)*8;
    const int sd1 = (skey+64)*24 + (spart&1)*8;

    auto stage = [&](int c, int buf){
        __half* bb = (spart < 2) ? &Ks[buf][0] : &Vs[buf][0];
        cpa16(su32(bb + sd0), ssrc + (size_t)(c*128 + skey)*384);
        cpa16(su32(bb + sd1), ssrc + (size_t)(c*128 + skey + 64)*384);
        asm volatile("cp.async.commit_group;":::"memory");
    };

    const int koff = ((lane&7) + ((lane>>4)<<3))*48 + (((lane>>3)&1) << 4);
    const int voff = (lane&15)*48 + ((lane>>4) << 4);

    uint32_t qfr[4];
    {
        const int r0 = qb*128 + w*16 + g, r1 = r0 + 8;
        const __half* p0 = qkv + base + (size_t)r0*384 + h*16;
        const __half* p1 = qkv + base + (size_t)r1*384 + h*16;
        const __half2 cs = __float2half2_rn(0.25f * 1.44269504f);
        __half2 a0 = __hmul2(*(const __half2*)(p0 + 2*q), cs);
        __half2 a1 = __hmul2(*(const __half2*)(p1 + 2*q), cs);
        __half2 a2 = __hmul2(*(const __half2*)(p0 + 8 + 2*q), cs);
        __half2 a3 = __hmul2(*(const __half2*)(p1 + 8 + 2*q), cs);
        qfr[0] = *(uint32_t*)&a0; qfr[1] = *(uint32_t*)&a1;
        qfr[2] = *(uint32_t*)&a2; qfr[3] = *(uint32_t*)&a3;
    }

    auto exp2h2 = [&](uint32_t s)->uint32_t{
        __half2 y = *(__half2*)&s;
        __half2 p = __hfma2(C3, y, C2);
        p = __hfma2(p, y, C1);
        p = __hfma2(p, y, C0);
        return *(uint32_t*)&p;
    };

    // f16 accumulators: uo0/uo1 = output dims 0-7 / 8-15, uo2 = l (ones column)
    uint32_t uo0[2] = {0u,0u}, uo1[2] = {0u,0u}, uo2[2] = {0u,0u};

    stage(0, 0);
    stage(1, 1);
#pragma unroll
    for (int c = 0; c < 4; c++){
        if (c < 3) asm volatile("cp.async.wait_group 1;":::"memory");
        else       asm volatile("cp.async.wait_group 0;":::"memory");
        __syncthreads();
        if (c < 2) stage(c + 2, (c + 2) % 3);

        const int buf = c % 3;
        const uint32_t kb = su32(&Ks[buf][0]) + koff;
        const uint32_t vb = su32(&Vs[buf][0]) + voff;

        uint32_t pa[8][4];
#pragma unroll
        for (int jp=0; jp<8; jp++){
            uint32_t k0,k1,k2,k3, s0,s1,s2,s3;
            ldmx4(kb + jp*768, k0,k1,k2,k3);
            mma16816h(s0, s1, qfr, k0, k1);
            mma16816h(s2, s3, qfr, k2, k3);
            pa[jp][0] = exp2h2(s0); pa[jp][1] = exp2h2(s1);
            pa[jp][2] = exp2h2(s2); pa[jp][3] = exp2h2(s3);
        }
#pragma unroll
        for (int t=0; t<8; t++){
            uint32_t v0,v1,v2,v3;
            ldmx4t(vb + t*768, v0,v1,v2,v3);
            mma16816hacc(uo0[0], uo0[1], pa[t], v0, v1);
            mma16816hacc(uo1[0], uo1[1], pa[t], v2, v3);
            mma16816hacc(uo2[0], uo2[1], pa[t], ONE2, ONE2);
        }
    }

    // l per row: any column of the ones-mma result (low half of each D reg)
    const float l0 = __half2float(__low2half(*(__half2*)&uo2[0]));
    const float l1 = __half2float(__low2half(*(__half2*)&uo2[1]));
    const float i0 = 1.f / l0, i1 = 1.f / l1;

    __half2 o00 = *(__half2*)&uo0[0], o01 = *(__half2*)&uo0[1];
    __half2 o10 = *(__half2*)&uo1[0], o11 = *(__half2*)&uo1[1];

    const int row = b*LL + qb*128 + w*16 + g;
    {
        int col = h*16 + 2*q;
        *(__half2*)&out[(size_t)row*DD + col] =
            __floats2half2_rn(__half2float(__low2half(o00))*i0,
                              __half2float(__high2half(o00))*i0);
        *(__half2*)&out[(size_t)(row+8)*DD + col] =
            __floats2half2_rn(__half2float(__low2half(o01))*i1,
                              __half2float(__high2half(o01))*i1);
        *(__half2*)&out[(size_t)row*DD + col + 8] =
            __floats2half2_rn(__half2float(__low2half(o10))*i0,
                              __half2float(__high2half(o10))*i0);
        *(__half2*)&out[(size_t)(row+8)*DD + col + 8] =
            __floats2half2_rn(__half2float(__low2half(o11))*i1,
                              __half2float(__high2half(o11))*i1);
    }
}

// ---------------- pooling + classifier ----------------
__global__ __launch_bounds__(256)
void pool_k(const float* __restrict__ h, float* __restrict__ pooled4)
{
    const int b = blockIdx.x, c = blockIdx.y, t = threadIdx.x;
    const int col = t & 127, hs = t >> 7;
    __shared__ float red[256];
    const float* p = h + (size_t)b*LL*DD + (size_t)(c*128 + hs*64)*DD + col;
    float s = 0.f;
    for (int l=0; l<64; l++) s += p[(size_t)l*DD];
    red[t] = s;
    __syncthreads();
    if (t < 128) pooled4[(size_t)c*NB*DD + b*DD + t] = red[t] + red[t+128];
}

__global__ __launch_bounds__(64)
void cls_k(const float* __restrict__ pooled4,
           const float* __restrict__ W1, const float* __restrict__ b1,
           const float* __restrict__ W2, const float* __restrict__ b2,
           float* __restrict__ out)
{
    const int b = blockIdx.x, t = threadIdx.x;
    __shared__ float ps[128], hid[64];
#pragma unroll
    for (int i=0;i<2;i++){
        int col = t + i*64;
        float s = 0.f;
#pragma unroll
        for (int c=0;c<4;c++) s += pooled4[(size_t)c*NB*DD + b*DD + col];
        ps[col] = s * (1.f/(float)LL);
    }
    __syncthreads();
    float a = b1[t];
    for (int k=0;k<128;k++) a = fmaf(ps[k], W1[k*64 + t], a);
    hid[t] = fmaxf(a, 0.f);
    __syncthreads();
    if (t < OUTC){
        float o = b2[t];
#pragma unroll
        for (int k=0;k<64;k++) o = fmaf(hid[k], W2[k*OUTC + t], o);
        out[b*OUTC + t] = o;
    }
}

extern "C" void kernel_launch(void* const* d_in, const int* in_sizes, int n_in,
                              void* d_out, int out_size)
{
    const float* x      = (const float*)d_in[0];
    const float* Wp     = (const float*)d_in[n_in-18];
    const float* bp     = (const float*)d_in[n_in-17];
    const float* qkv_w  = (const float*)d_in[n_in-16];
    const float* qkv_b  = (const float*)d_in[n_in-15];
    const float* out_w  = (const float*)d_in[n_in-14];
    const float* out_b  = (const float*)d_in[n_in-13];
    const float* ln1_g  = (const float*)d_in[n_in-12];
    const float* ln1_b  = (const float*)d_in[n_in-11];
    const float* ffn_w1 = (const float*)d_in[n_in-10];
    const float* ffn_b1 = (const float*)d_in[n_in-9];
    const float* ffn_w2 = (const float*)d_in[n_in-8];
    const float* ffn_b2 = (const float*)d_in[n_in-7];
    const float* ln2_g  = (const float*)d_in[n_in-6];
    const float* ln2_b  = (const float*)d_in[n_in-5];
    const float* cls_w1 = (const float*)d_in[n_in-4];
    const float* cls_b1 = (const float*)d_in[n_in-3];
    const float* cls_w2 = (const float*)d_in[n_in-2];
    const float* cls_b2 = (const float*)d_in[n_in-1];
    float* out = (float*)d_out;

    float *h, *pooled4;
    __half *h16, *x16, *qkv16, *whi;
    cudaGetSymbolAddress((void**)&h,       g_h);
    cudaGetSymbolAddress((void**)&pooled4, g_pool4);
    cudaGetSymbolAddress((void**)&h16,     g_h16);
    cudaGetSymbolAddress((void**)&x16,     g_x16);
    cudaGetSymbolAddress((void**)&qkv16,   g_qkv16);
    cudaGetSymbolAddress((void**)&whi,     g_whi);
    __half* attn16 = x16;

    cudaFuncSetAttribute(ffn_k, cudaFuncAttributeMaxDynamicSharedMemorySize, FFN_SMEM);

    cvtall<<<2048,256>>>(Wp, qkv_w, out_w, ffn_w1, ffn_w2, x, whi, x16);

    const int MB = NT/128;

    hgemm<true,true,false,false><<<dim3(1,MB),256>>>(
        x16, whi+OFF_WP, bp, h, h16, DD, DD,
        (const float*)0, (const float*)0, (const float*)0);

    for (int i=0; i<NLAYERS; i++){
        hgemm16<<<dim3(3,MB),256>>>(
            h16, whi+OFF_QKV+(size_t)i*128*384,
            qkv_b+(size_t)i*384, qkv16, 384, 128);

        attn_k<<<dim3(4,HH,NB),256>>>(qkv16, attn16);

        hgemm<true,true,false,true><<<dim3(1,MB),256>>>(
            attn16, whi+OFF_OUT+(size_t)i*128*128,
            out_b+(size_t)i*128, h, h16, DD, DD,
            h, ln1_g+(size_t)i*DD, ln1_b+(size_t)i*DD);

        ffn_k<<<MB,256,FFN_SMEM>>>(
            h16, whi+OFF_F1+(size_t)i*128*512, ffn_b1+(size_t)i*512,
            whi+OFF_F2+(size_t)i*512*128, ffn_b2+(size_t)i*128,
            h, h16, ln2_g+(size_t)i*DD, ln2_b+(size_t)i*DD);
    }

    pool_k<<<dim3(NB,4),256>>>(h, pooled4);
    cls_k<<<NB,64>>>(pooled4, cls_w1, cls_b1, cls_w2, cls_b2, out);

    (void)in_sizes; (void)out_size;
}

// round 14
// speedup vs baseline: 1.6480x; 1.0714x over previous
#include <cuda_runtime.h>
#include <cuda_fp16.h>
#include <math.h>
#include <stdint.h>

#define NB 64
#define LL 512
#define NT (NB*LL)
#define DD 128
#define HH 8
#define FFD 512
#define NLAYERS 6
#define OUTC 10

#define SZ_WP   (128*128)
#define SZ_QKV  (NLAYERS*128*384)
#define SZ_OUT  (NLAYERS*128*128)
#define SZ_F1   (NLAYERS*128*512)
#define SZ_F2   (NLAYERS*512*128)
#define OFF_WP  0
#define OFF_QKV (SZ_WP)
#define OFF_OUT (OFF_QKV+SZ_QKV)
#define OFF_F1  (OFF_OUT+SZ_OUT)
#define OFF_F2  (OFF_F1+SZ_F1)
#define W16_TOT (OFF_F2+SZ_F2)

// fused layer dynamic smem: AF 32KB + FF 128KB + Ws 16KB + LN 2KB
#define LYR_SMEM (32768 + 131072 + 16384 + 2048)

typedef unsigned long long ull;

__device__ float  g_h   [NT*DD];
__device__ __align__(16) __half g_h16   [NT*DD];
__device__ __align__(16) __half g_x16   [NT*DD];   // also reused as attn16
__device__ __align__(16) __half g_qkv16 [NT*3*DD];
__device__ __align__(16) __half g_whi   [W16_TOT];
__device__ float g_pool4[4][NB*DD];

__device__ __forceinline__ uint32_t su32(const void* p){
    return (uint32_t)__cvta_generic_to_shared(p);
}
__device__ __forceinline__ void ldmx4(uint32_t a, uint32_t& r0, uint32_t& r1,
                                      uint32_t& r2, uint32_t& r3){
    asm volatile("ldmatrix.sync.aligned.m8n8.x4.shared.b16 {%0,%1,%2,%3},[%4];"
        :"=r"(r0),"=r"(r1),"=r"(r2),"=r"(r3):"r"(a));
}
__device__ __forceinline__ void ldmx4t(uint32_t a, uint32_t& r0, uint32_t& r1,
                                       uint32_t& r2, uint32_t& r3){
    asm volatile("ldmatrix.sync.aligned.m8n8.x4.trans.shared.b16 {%0,%1,%2,%3},[%4];"
        :"=r"(r0),"=r"(r1),"=r"(r2),"=r"(r3):"r"(a));
}
__device__ __forceinline__ void mma16816(float* c, const uint32_t* a,
                                         uint32_t b0, uint32_t b1){
    asm volatile("mma.sync.aligned.m16n8k16.row.col.f32.f16.f16.f32 "
        "{%0,%1,%2,%3},{%4,%5,%6,%7},{%8,%9},{%0,%1,%2,%3};"
        :"+f"(c[0]),"+f"(c[1]),"+f"(c[2]),"+f"(c[3])
        :"r"(a[0]),"r"(a[1]),"r"(a[2]),"r"(a[3]),"r"(b0),"r"(b1));
}
__device__ __forceinline__ void mma16816h(uint32_t& d0, uint32_t& d1,
                                          const uint32_t* a,
                                          uint32_t b0, uint32_t b1){
    asm volatile("mma.sync.aligned.m16n8k16.row.col.f16.f16.f16.f16 "
        "{%0,%1},{%2,%3,%4,%5},{%6,%7},{%8,%9};"
        :"=r"(d0),"=r"(d1)
        :"r"(a[0]),"r"(a[1]),"r"(a[2]),"r"(a[3]),"r"(b0),"r"(b1),
         "r"(0u),"r"(0u));
}
__device__ __forceinline__ void mma16816hacc(uint32_t& d0, uint32_t& d1,
                                             const uint32_t* a,
                                             uint32_t b0, uint32_t b1){
    asm volatile("mma.sync.aligned.m16n8k16.row.col.f16.f16.f16.f16 "
        "{%0,%1},{%2,%3,%4,%5},{%6,%7},{%0,%1};"
        :"+r"(d0),"+r"(d1)
        :"r"(a[0]),"r"(a[1]),"r"(a[2]),"r"(a[3]),"r"(b0),"r"(b1));
}
__device__ __forceinline__ void cpa16(uint32_t dst, const void* src){
    asm volatile("cp.async.cg.shared.global [%0],[%1],16;"::"r"(dst),"l"(src));
}

// ---------------- single fused conversion kernel ----------------
__global__ void cvtall(const float* __restrict__ Wp, const float* __restrict__ qkvw,
                       const float* __restrict__ outw, const float* __restrict__ f1,
                       const float* __restrict__ f2, const float* __restrict__ x,
                       __half* __restrict__ hi, __half* __restrict__ x16)
{
    const int TOT = W16_TOT + NT*DD;
    for (int i = blockIdx.x*blockDim.x + threadIdx.x; i < TOT;
         i += gridDim.x*blockDim.x){
        if (i >= W16_TOT){
            int j = i - W16_TOT;
            x16[j] = __float2half_rn(x[j]);
            continue;
        }
        float w;
        if (i < OFF_QKV){
            w = Wp[i];
        } else if (i < OFF_OUT){
            int j = i - OFF_QKV;
            int L = j / (128*384); int r = j - L*(128*384);
            int k = r / 384, n = r - k*384;
            w = qkvw[(size_t)L*384*128 + (size_t)n*128 + k];
        } else if (i < OFF_F1){
            int j = i - OFF_OUT;
            int L = j / (128*128); int r = j - L*(128*128);
            int k = r >> 7, n = r & 127;
            w = outw[(size_t)L*128*128 + (size_t)n*128 + k];
        } else if (i < OFF_F2){
            w = f1[i - OFF_F1];
        } else {
            w = f2[i - OFF_F2];
        }
        hi[i] = __float2half_rn(w);
    }
}

// ---------------- fp16 tensor-core GEMM (input projection only) ----------------
__global__ __launch_bounds__(256)
void hgemm(const __half* __restrict__ A, const __half* __restrict__ W,
           const float* __restrict__ bias,
           float* __restrict__ C32, __half* __restrict__ C16, int N, int K)
{
    __shared__ __align__(16) __half As[2][128*32];
    __shared__ __align__(16) __half Ws[2][32*128];
    const int tid = threadIdx.x;
    const int lane = tid & 31, wid = tid >> 5;
    const int wm = wid & 3, wn = wid >> 2;
    const int bm = blockIdx.y * 128, bn = blockIdx.x * 128;

    float acc[2][8][4];
#pragma unroll
    for (int i=0;i<2;i++)
#pragma unroll
        for (int j=0;j<8;j++)
#pragma unroll
            for (int k=0;k<4;k++) acc[i][j][k]=0.f;

    const int KT = K/32;

    auto issue = [&](int kt){
        int buf = kt & 1;
        int k0  = kt * 32;
        uint32_t sA = su32(&As[buf][0]);
        uint32_t sW = su32(&Ws[buf][0]);
#pragma unroll
        for (int i=0;i<2;i++){
            int id = tid + i*256;
            int r = id >> 2, c = id & 3;
            cpa16(sA + r*64 + ((c ^ ((r>>1)&3)) << 4),
                  A + (size_t)(bm + r)*K + k0 + c*8);
            int k = id >> 4, cc = id & 15;
            cpa16(sW + k*256 + ((cc ^ (k&7)) << 4),
                  W + (size_t)(k0 + k)*N + bn + cc*8);
        }
        asm volatile("cp.async.commit_group;":::"memory");
    };

    issue(0);
    for (int kt = 0; kt < KT; kt++){
        int buf = kt & 1;
        if (kt + 1 < KT){
            issue(kt + 1);
            asm volatile("cp.async.wait_group 1;":::"memory");
        } else {
            asm volatile("cp.async.wait_group 0;":::"memory");
        }
        __syncthreads();
        uint32_t sA = su32(&As[buf][0]);
        uint32_t sW = su32(&Ws[buf][0]);
#pragma unroll
        for (int ks = 0; ks < 32; ks += 16){
            uint32_t afr[2][4];
#pragma unroll
            for (int mt=0; mt<2; mt++){
                int r = wm*32 + mt*16 + (lane & 15);
                int cg = (ks >> 3) + (lane >> 4);
                ldmx4(sA + r*64 + ((cg ^ ((r>>1)&3)) << 4),
                      afr[mt][0], afr[mt][1], afr[mt][2], afr[mt][3]);
            }
            uint32_t bfr[4][4];
#pragma unroll
            for (int ntp=0; ntp<4; ntp++){
                int k  = ks + (lane & 15);
                int cc = wn*8 + ntp*2 + (lane >> 4);
                ldmx4t(sW + k*256 + ((cc ^ (k&7)) << 4),
                       bfr[ntp][0], bfr[ntp][1], bfr[ntp][2], bfr[ntp][3]);
            }
#pragma unroll
            for (int mt=0; mt<2; mt++)
#pragma unroll
                for (int nt=0; nt<8; nt++)
                    mma16816(acc[mt][nt], afr[mt],
                             bfr[nt>>1][(nt&1)*2], bfr[nt>>1][(nt&1)*2+1]);
        }
        __syncthreads();
    }

    const int g = lane >> 2, q = lane & 3;
#pragma unroll
    for (int mt=0; mt<2; mt++){
        int row = bm + wm*32 + mt*16 + g;
#pragma unroll
        for (int nt=0; nt<8; nt++){
            int col = bn + wn*64 + nt*8 + q*2;
            float2 bv = *(const float2*)&bias[col];
            float v0 = acc[mt][nt][0] + bv.x;
            float v1 = acc[mt][nt][1] + bv.y;
            float v2 = acc[mt][nt][2] + bv.x;
            float v3 = acc[mt][nt][3] + bv.y;
            *(float2*)&C32[(size_t)row*N + col]     = make_float2(v0,v1);
            *(float2*)&C32[(size_t)(row+8)*N + col] = make_float2(v2,v3);
            *(__half2*)&C16[(size_t)row*N + col]     = __floats2half2_rn(v0,v1);
            *(__half2*)&C16[(size_t)(row+8)*N + col] = __floats2half2_rn(v2,v3);
        }
    }
}

// ---------------- f16-accumulator GEMM (qkv only) ----------------
__global__ __launch_bounds__(256)
void hgemm16(const __half* __restrict__ A, const __half* __restrict__ W,
             const float* __restrict__ bias, __half* __restrict__ C16,
             int N, int K)
{
    __shared__ __align__(16) __half As[2][128*32];
    __shared__ __align__(16) __half Ws[2][32*128];
    const int tid = threadIdx.x;
    const int lane = tid & 31, wid = tid >> 5;
    const int wm = wid & 3, wn = wid >> 2;
    const int bm = blockIdx.y * 128, bn = blockIdx.x * 128;

    uint32_t hacc[2][8][2];
#pragma unroll
    for (int i=0;i<2;i++)
#pragma unroll
        for (int j=0;j<8;j++){ hacc[i][j][0]=0u; hacc[i][j][1]=0u; }

    const int KT = K/32;

    auto issue = [&](int kt){
        int buf = kt & 1;
        int k0  = kt * 32;
        uint32_t sA = su32(&As[buf][0]);
        uint32_t sW = su32(&Ws[buf][0]);
#pragma unroll
        for (int i=0;i<2;i++){
            int id = tid + i*256;
            int r = id >> 2, c = id & 3;
            cpa16(sA + r*64 + ((c ^ ((r>>1)&3)) << 4),
                  A + (size_t)(bm + r)*K + k0 + c*8);
            int k = id >> 4, cc = id & 15;
            cpa16(sW + k*256 + ((cc ^ (k&7)) << 4),
                  W + (size_t)(k0 + k)*N + bn + cc*8);
        }
        asm volatile("cp.async.commit_group;":::"memory");
    };

    issue(0);
    for (int kt = 0; kt < KT; kt++){
        int buf = kt & 1;
        if (kt + 1 < KT){
            issue(kt + 1);
            asm volatile("cp.async.wait_group 1;":::"memory");
        } else {
            asm volatile("cp.async.wait_group 0;":::"memory");
        }
        __syncthreads();
        uint32_t sA = su32(&As[buf][0]);
        uint32_t sW = su32(&Ws[buf][0]);
#pragma unroll
        for (int ks = 0; ks < 32; ks += 16){
            uint32_t afr[2][4];
#pragma unroll
            for (int mt=0; mt<2; mt++){
                int r = wm*32 + mt*16 + (lane & 15);
                int cg = (ks >> 3) + (lane >> 4);
                ldmx4(sA + r*64 + ((cg ^ ((r>>1)&3)) << 4),
                      afr[mt][0], afr[mt][1], afr[mt][2], afr[mt][3]);
            }
            uint32_t bfr[4][4];
#pragma unroll
            for (int ntp=0; ntp<4; ntp++){
                int k  = ks + (lane & 15);
                int cc = wn*8 + ntp*2 + (lane >> 4);
                ldmx4t(sW + k*256 + ((cc ^ (k&7)) << 4),
                       bfr[ntp][0], bfr[ntp][1], bfr[ntp][2], bfr[ntp][3]);
            }
#pragma unroll
            for (int mt=0; mt<2; mt++)
#pragma unroll
                for (int nt=0; nt<8; nt++)
                    mma16816hacc(hacc[mt][nt][0], hacc[mt][nt][1], afr[mt],
                                 bfr[nt>>1][(nt&1)*2], bfr[nt>>1][(nt&1)*2+1]);
        }
        __syncthreads();
    }

    const int g = lane >> 2, q = lane & 3;
#pragma unroll
    for (int mt=0; mt<2; mt++){
        int row = bm + wm*32 + mt*16 + g;
#pragma unroll
        for (int nt=0; nt<8; nt++){
            int col = bn + wn*64 + nt*8 + q*2;
            float2 bv = *(const float2*)&bias[col];
            __half2 hb = __floats2half2_rn(bv.x, bv.y);
            __half2 v0 = __hadd2(*(__half2*)&hacc[mt][nt][0], hb);
            __half2 v1 = __hadd2(*(__half2*)&hacc[mt][nt][1], hb);
            *(__half2*)&C16[(size_t)row*N + col]     = v0;
            *(__half2*)&C16[(size_t)(row+8)*N + col] = v1;
        }
    }
}

// ---------------- fused layer tail: out-proj + LN1 + FFN + LN2 ----------------
// phase0: u = LN1(h + attn16@Wout + bo)   (u fp32 kept in regs; fp16 -> AF smem)
// phase1: FF = relu(u16 @ W1 + b1)        (FF in smem)
// phase2: h = LN2(u + FF @ W2 + b2)
__global__ __launch_bounds__(256)
void layer_k(const __half* __restrict__ attn16,
             const __half* __restrict__ Wout, const float* __restrict__ bo,
             const float* __restrict__ ln1g, const float* __restrict__ ln1b,
             const __half* __restrict__ W1, const float* __restrict__ b1,
             const __half* __restrict__ W2, const float* __restrict__ b2,
             float* __restrict__ h, __half* __restrict__ h16,
             const float* __restrict__ ln2g, const float* __restrict__ ln2b)
{
    extern __shared__ __align__(16) char dsm[];
    __half* AF = (__half*)dsm;                       // 4 ktiles (32KB)
    __half* FF = (__half*)(dsm + 32768);             // 16 ktiles (128KB)
    __half* WS = (__half*)(dsm + 32768 + 131072);    // 2 bufs (16KB)
    float*  sS = (float*)(dsm + 32768 + 131072 + 16384);
    float*  sQ = sS + 256;

    const int tid = threadIdx.x, lane = tid & 31, wid = tid >> 5;
    const int wm = wid & 3, wn = wid >> 2;
    const int g = lane >> 2, q = lane & 3;
    const int bm = blockIdx.x * 128;

    const uint32_t sAF = su32(AF);
    const uint32_t sFF = su32(FF);
    const uint32_t sW  = su32(WS);

    // generic W staging: tile [32 x 128] from W[(k0+k)*N + j*128 + col]
    auto issueW = [&](const __half* W, int N, int j, int kt){
        int buf = kt & 1;
        int k0  = kt * 32;
#pragma unroll
        for (int i=0;i<2;i++){
            int id = tid + i*256;
            int k = id >> 4, cc = id & 15;
            cpa16(sW + buf*8192 + k*256 + ((cc ^ (k&7)) << 4),
                  W + (size_t)(k0 + k)*N + j*128 + cc*8);
        }
        asm volatile("cp.async.commit_group;":::"memory");
    };

    // LN-output registers (u) — live through phases 1 & 2
    float y[2][8][4];

    // ======== phase 0: out-proj + residual + LN1 ========
    {
        // stage attn16 block (128x128) into AF (4 ktiles)
#pragma unroll
        for (int i=0;i<8;i++){
            int id = tid + i*256;
            int r = id >> 4, c = id & 15;
            int kt = c >> 2, cc = c & 3;
            cpa16(sAF + kt*8192 + r*64 + ((cc ^ ((r>>1)&3)) << 4),
                  attn16 + (size_t)(bm + r)*128 + c*8);
        }
        asm volatile("cp.async.commit_group;":::"memory");

        float acc[2][8][4];
#pragma unroll
        for (int i=0;i<2;i++)
#pragma unroll
            for (int jj=0;jj<8;jj++)
#pragma unroll
                for (int k=0;k<4;k++) acc[i][jj][k]=0.f;

        issueW(Wout, 128, 0, 0);
        for (int kt = 0; kt < 4; kt++){
            if (kt + 1 < 4){
                issueW(Wout, 128, 0, kt + 1);
                asm volatile("cp.async.wait_group 1;":::"memory");
            } else {
                asm volatile("cp.async.wait_group 0;":::"memory");
            }
            __syncthreads();
            uint32_t sWb = sW + (kt&1)*8192;
#pragma unroll
            for (int ks = 0; ks < 32; ks += 16){
                uint32_t afr[2][4];
#pragma unroll
                for (int mt=0; mt<2; mt++){
                    int r = wm*32 + mt*16 + (lane & 15);
                    int cg = (ks >> 3) + (lane >> 4);
                    ldmx4(sAF + kt*8192 + r*64 + ((cg ^ ((r>>1)&3)) << 4),
                          afr[mt][0], afr[mt][1], afr[mt][2], afr[mt][3]);
                }
                uint32_t bfr[4][4];
#pragma unroll
                for (int ntp=0; ntp<4; ntp++){
                    int k  = ks + (lane & 15);
                    int cc = wn*8 + ntp*2 + (lane >> 4);
                    ldmx4t(sWb + k*256 + ((cc ^ (k&7)) << 4),
                           bfr[ntp][0], bfr[ntp][1], bfr[ntp][2], bfr[ntp][3]);
                }
#pragma unroll
                for (int mt=0; mt<2; mt++)
#pragma unroll
                    for (int nt=0; nt<8; nt++)
                        mma16816(acc[mt][nt], afr[mt],
                                 bfr[nt>>1][(nt&1)*2], bfr[nt>>1][(nt&1)*2+1]);
            }
            __syncthreads();
        }

        // residual + LN1 -> y regs + AF fp16
        float vsum[2][2], vsq[2][2];
#pragma unroll
        for (int mt=0; mt<2; mt++){ vsum[mt][0]=vsum[mt][1]=0.f; vsq[mt][0]=vsq[mt][1]=0.f; }
#pragma unroll
        for (int mt=0; mt<2; mt++){
            int row0 = bm + wm*32 + mt*16 + g;
#pragma unroll
            for (int nt=0; nt<8; nt++){
                int col = wn*64 + nt*8 + q*2;
                float2 bv  = *(const float2*)&bo[col];
                float2 rr0 = *(const float2*)&h[(size_t)row0*128 + col];
                float2 rr1 = *(const float2*)&h[(size_t)(row0+8)*128 + col];
                float v0 = acc[mt][nt][0] + bv.x + rr0.x;
                float v1 = acc[mt][nt][1] + bv.y + rr0.y;
                float v2 = acc[mt][nt][2] + bv.x + rr1.x;
                float v3 = acc[mt][nt][3] + bv.y + rr1.y;
                acc[mt][nt][0]=v0; acc[mt][nt][1]=v1;
                acc[mt][nt][2]=v2; acc[mt][nt][3]=v3;
                vsum[mt][0] += v0+v1; vsq[mt][0] = fmaf(v0,v0,fmaf(v1,v1,vsq[mt][0]));
                vsum[mt][1] += v2+v3; vsq[mt][1] = fmaf(v2,v2,fmaf(v3,v3,vsq[mt][1]));
            }
        }
#pragma unroll
        for (int mt=0; mt<2; mt++)
#pragma unroll
            for (int r2=0; r2<2; r2++){
                vsum[mt][r2] += __shfl_xor_sync(0xffffffffu, vsum[mt][r2], 1);
                vsum[mt][r2] += __shfl_xor_sync(0xffffffffu, vsum[mt][r2], 2);
                vsq[mt][r2]  += __shfl_xor_sync(0xffffffffu, vsq[mt][r2], 1);
                vsq[mt][r2]  += __shfl_xor_sync(0xffffffffu, vsq[mt][r2], 2);
            }
        if (q == 0){
#pragma unroll
            for (int mt=0; mt<2; mt++)
#pragma unroll
                for (int r2=0; r2<2; r2++){
                    int r = wm*32 + mt*16 + g + r2*8;
                    sS[wn*128 + r] = vsum[mt][r2];
                    sQ[wn*128 + r] = vsq[mt][r2];
                }
        }
        __syncthreads();
#pragma unroll
        for (int mt=0; mt<2; mt++){
            int r0 = wm*32 + mt*16 + g, r1 = r0 + 8;
            float mean0 = (sS[r0]+sS[128+r0]) * (1.f/128.f);
            float mean1 = (sS[r1]+sS[128+r1]) * (1.f/128.f);
            float var0  = (sQ[r0]+sQ[128+r0]) * (1.f/128.f) - mean0*mean0;
            float var1  = (sQ[r1]+sQ[128+r1]) * (1.f/128.f) - mean1*mean1;
            float rs0 = rsqrtf(var0 + 1e-5f);
            float rs1 = rsqrtf(var1 + 1e-5f);
#pragma unroll
            for (int nt=0; nt<8; nt++){
                int col = wn*64 + nt*8 + q*2;
                float2 gg = *(const float2*)&ln1g[col];
                float2 bb = *(const float2*)&ln1b[col];
                float y0 = (acc[mt][nt][0]-mean0)*rs0*gg.x + bb.x;
                float y1 = (acc[mt][nt][1]-mean0)*rs0*gg.y + bb.y;
                float y2 = (acc[mt][nt][2]-mean1)*rs1*gg.x + bb.x;
                float y3 = (acc[mt][nt][3]-mean1)*rs1*gg.y + bb.y;
                y[mt][nt][0]=y0; y[mt][nt][1]=y1;
                y[mt][nt][2]=y2; y[mt][nt][3]=y3;
                // fp16 copy into AF (phase-1 A operand); AF reads all done above
                int ktile = col >> 5, c = col & 31, c8 = c >> 3;
                int base = ktile*8192 + (c&7)*2;
                int row0l = wm*32 + mt*16 + g, row1l = row0l + 8;
                int o0 = base + row0l*64 + ((c8 ^ ((row0l>>1)&3)) << 4);
                int o1 = base + row1l*64 + ((c8 ^ ((row1l>>1)&3)) << 4);
                *(__half2*)((char*)AF + o0) = __floats2half2_rn(y0, y1);
                *(__half2*)((char*)AF + o1) = __floats2half2_rn(y2, y3);
            }
        }
        __syncthreads();   // AF(u16) visible to all warps
    }

    // ======== phase 1: FF = relu(u16 @ W1 + b1) in smem ========
    for (int j=0;j<4;j++){
        float acc[2][8][4];
#pragma unroll
        for (int i=0;i<2;i++)
#pragma unroll
            for (int jj=0;jj<8;jj++)
#pragma unroll
                for (int k=0;k<4;k++) acc[i][jj][k]=0.f;

        issueW(W1, 512, j, 0);
        for (int kt = 0; kt < 4; kt++){
            if (kt + 1 < 4){
                issueW(W1, 512, j, kt + 1);
                asm volatile("cp.async.wait_group 1;":::"memory");
            } else {
                asm volatile("cp.async.wait_group 0;":::"memory");
            }
            __syncthreads();
            uint32_t sWb = sW + (kt&1)*8192;
#pragma unroll
            for (int ks = 0; ks < 32; ks += 16){
                uint32_t afr[2][4];
#pragma unroll
                for (int mt=0; mt<2; mt++){
                    int r = wm*32 + mt*16 + (lane & 15);
                    int cg = (ks >> 3) + (lane >> 4);
                    ldmx4(sAF + kt*8192 + r*64 + ((cg ^ ((r>>1)&3)) << 4),
                          afr[mt][0], afr[mt][1], afr[mt][2], afr[mt][3]);
                }
                uint32_t bfr[4][4];
#pragma unroll
                for (int ntp=0; ntp<4; ntp++){
                    int k  = ks + (lane & 15);
                    int cc = wn*8 + ntp*2 + (lane >> 4);
                    ldmx4t(sWb + k*256 + ((cc ^ (k&7)) << 4),
                           bfr[ntp][0], bfr[ntp][1], bfr[ntp][2], bfr[ntp][3]);
                }
#pragma unroll
                for (int mt=0; mt<2; mt++)
#pragma unroll
                    for (int nt=0; nt<8; nt++)
                        mma16816(acc[mt][nt], afr[mt],
                                 bfr[nt>>1][(nt&1)*2], bfr[nt>>1][(nt&1)*2+1]);
            }
            __syncthreads();
        }
#pragma unroll
        for (int mt=0; mt<2; mt++){
            int row0 = wm*32 + mt*16 + g;
            int row1 = row0 + 8;
#pragma unroll
            for (int nt=0; nt<8; nt++){
                int col = j*128 + wn*64 + nt*8 + q*2;
                float2 bv = *(const float2*)&b1[col];
                float v0 = fmaxf(acc[mt][nt][0] + bv.x, 0.f);
                float v1 = fmaxf(acc[mt][nt][1] + bv.y, 0.f);
                float v2 = fmaxf(acc[mt][nt][2] + bv.x, 0.f);
                float v3 = fmaxf(acc[mt][nt][3] + bv.y, 0.f);
                int ktile = col >> 5, c = col & 31, c8 = c >> 3;
                int base = ktile*8192 + (c&7)*2;
                int o0 = base + row0*64 + ((c8 ^ ((row0>>1)&3)) << 4);
                int o1 = base + row1*64 + ((c8 ^ ((row1>>1)&3)) << 4);
                *(__half2*)((char*)FF + o0) = __floats2half2_rn(v0, v1);
                *(__half2*)((char*)FF + o1) = __floats2half2_rn(v2, v3);
            }
        }
    }
    __syncthreads();

    // ======== phase 2: h = LN2(u + FF @ W2 + b2) ========
    float acc[2][8][4];
#pragma unroll
    for (int i=0;i<2;i++)
#pragma unroll
        for (int jj=0;jj<8;jj++)
#pragma unroll
            for (int k=0;k<4;k++) acc[i][jj][k]=0.f;

    issueW(W2, 128, 0, 0);
    for (int kt = 0; kt < 16; kt++){
        if (kt + 1 < 16){
            issueW(W2, 128, 0, kt + 1);
            asm volatile("cp.async.wait_group 1;":::"memory");
        } else {
            asm volatile("cp.async.wait_group 0;":::"memory");
        }
        __syncthreads();
        uint32_t sWb = sW + (kt&1)*8192;
#pragma unroll
        for (int ks = 0; ks < 32; ks += 16){
            uint32_t afr[2][4];
#pragma unroll
            for (int mt=0; mt<2; mt++){
                int r = wm*32 + mt*16 + (lane & 15);
                int cg = (ks >> 3) + (lane >> 4);
                ldmx4(sFF + kt*8192 + r*64 + ((cg ^ ((r>>1)&3)) << 4),
                      afr[mt][0], afr[mt][1], afr[mt][2], afr[mt][3]);
            }
            uint32_t bfr[4][4];
#pragma unroll
            for (int ntp=0; ntp<4; ntp++){
                int k  = ks + (lane & 15);
                int cc = wn*8 + ntp*2 + (lane >> 4);
                ldmx4t(sWb + k*256 + ((cc ^ (k&7)) << 4),
                       bfr[ntp][0], bfr[ntp][1], bfr[ntp][2], bfr[ntp][3]);
            }
#pragma unroll
            for (int mt=0; mt<2; mt++)
#pragma unroll
                for (int nt=0; nt<8; nt++)
                    mma16816(acc[mt][nt], afr[mt],
                             bfr[nt>>1][(nt&1)*2], bfr[nt>>1][(nt&1)*2+1]);
        }
        __syncthreads();
    }

    {
        float vsum[2][2], vsq[2][2];
#pragma unroll
        for (int mt=0; mt<2; mt++){ vsum[mt][0]=vsum[mt][1]=0.f; vsq[mt][0]=vsq[mt][1]=0.f; }
#pragma unroll
        for (int mt=0; mt<2; mt++){
#pragma unroll
            for (int nt=0; nt<8; nt++){
                int col = wn*64 + nt*8 + q*2;
                float2 bv = *(const float2*)&b2[col];
                float v0 = acc[mt][nt][0] + bv.x + y[mt][nt][0];
                float v1 = acc[mt][nt][1] + bv.y + y[mt][nt][1];
                float v2 = acc[mt][nt][2] + bv.x + y[mt][nt][2];
                float v3 = acc[mt][nt][3] + bv.y + y[mt][nt][3];
                acc[mt][nt][0]=v0; acc[mt][nt][1]=v1;
                acc[mt][nt][2]=v2; acc[mt][nt][3]=v3;
                vsum[mt][0] += v0+v1; vsq[mt][0] = fmaf(v0,v0,fmaf(v1,v1,vsq[mt][0]));
                vsum[mt][1] += v2+v3; vsq[mt][1] = fmaf(v2,v2,fmaf(v3,v3,vsq[mt][1]));
            }
        }
#pragma unroll
        for (int mt=0; mt<2; mt++)
#pragma unroll
            for (int r2=0; r2<2; r2++){
                vsum[mt][r2] += __shfl_xor_sync(0xffffffffu, vsum[mt][r2], 1);
                vsum[mt][r2] += __shfl_xor_sync(0xffffffffu, vsum[mt][r2], 2);
                vsq[mt][r2]  += __shfl_xor_sync(0xffffffffu, vsq[mt][r2], 1);
                vsq[mt][r2]  += __shfl_xor_sync(0xffffffffu, vsq[mt][r2], 2);
            }
        if (q == 0){
#pragma unroll
            for (int mt=0; mt<2; mt++)
#pragma unroll
                for (int r2=0; r2<2; r2++){
                    int r = wm*32 + mt*16 + g + r2*8;
                    sS[wn*128 + r] = vsum[mt][r2];
                    sQ[wn*128 + r] = vsq[mt][r2];
                }
        }
        __syncthreads();
#pragma unroll
        for (int mt=0; mt<2; mt++){
            int r0 = wm*32 + mt*16 + g, r1 = r0 + 8;
            float mean0 = (sS[r0]+sS[128+r0]) * (1.f/128.f);
            float mean1 = (sS[r1]+sS[128+r1]) * (1.f/128.f);
            float var0  = (sQ[r0]+sQ[128+r0]) * (1.f/128.f) - mean0*mean0;
            float var1  = (sQ[r1]+sQ[128+r1]) * (1.f/128.f) - mean1*mean1;
            float rs0 = rsqrtf(var0 + 1e-5f);
            float rs1 = rsqrtf(var1 + 1e-5f);
            int row0 = bm + r0;
#pragma unroll
            for (int nt=0; nt<8; nt++){
                int col = wn*64 + nt*8 + q*2;
                float2 gg = *(const float2*)&ln2g[col];
                float2 bb = *(const float2*)&ln2b[col];
                float y0 = (acc[mt][nt][0]-mean0)*rs0*gg.x + bb.x;
                float y1 = (acc[mt][nt][1]-mean0)*rs0*gg.y + bb.y;
                float y2 = (acc[mt][nt][2]-mean1)*rs1*gg.x + bb.x;
                float y3 = (acc[mt][nt][3]-mean1)*rs1*gg.y + bb.y;
                *(float2*)&h[(size_t)row0*128 + col]     = make_float2(y0,y1);
                *(float2*)&h[(size_t)(row0+8)*128 + col] = make_float2(y2,y3);
                *(__half2*)&h16[(size_t)row0*128 + col]     = __floats2half2_rn(y0,y1);
                *(__half2*)&h16[(size_t)(row0+8)*128 + col] = __floats2half2_rn(y2,y3);
            }
        }
    }
}

// ---------------- fused flash MHA (R13 proven) ----------------
__global__ __launch_bounds__(256)
void attn_k(const __half* __restrict__ qkv, __half* __restrict__ out)
{
    __shared__ __align__(16) __half Ks[3][128*24];
    __shared__ __align__(16) __half Vs[3][128*24];

    const int qb = blockIdx.x, h = blockIdx.y, b = blockIdx.z;
    const int tid = threadIdx.x, lane = tid & 31, w = tid >> 5;
    const int g = lane >> 2, q = lane & 3;
    const size_t base = (size_t)b * LL * 384;

    const __half2 C3 = __float2half2_rn(0.05550411f);
    const __half2 C2 = __float2half2_rn(0.24022651f);
    const __half2 C1 = __float2half2_rn(0.69314718f);
    const __half2 C0 = __float2half2_rn(1.0f);
    const uint32_t ONE2 = 0x3C003C00u;

    const int skey  = tid >> 2;
    const int spart = tid & 3;
    const __half* ssrc = qkv + base + 128 + (spart>>1)*128 + h*16 + (spart&1)*8;
    const int sd0 = skey*24 + (spart&1)*8;
    const int sd1 = (skey+64)*24 + (spart&1)*8;

    auto stage = [&](int c, int buf){
        __half* bb = (spart < 2) ? &Ks[buf][0] : &Vs[buf][0];
        cpa16(su32(bb + sd0), ssrc + (size_t)(c*128 + skey)*384);
        cpa16(su32(bb + sd1), ssrc + (size_t)(c*128 + skey + 64)*384);
        asm volatile("cp.async.commit_group;":::"memory");
    };

    const int koff = ((lane&7) + ((lane>>4)<<3))*48 + (((lane>>3)&1) << 4);
    const int voff = (lane&15)*48 + ((lane>>4) << 4);

    uint32_t qfr[4];
    {
        const int r0 = qb*128 + w*16 + g, r1 = r0 + 8;
        const __half* p0 = qkv + base + (size_t)r0*384 + h*16;
        const __half* p1 = qkv + base + (size_t)r1*384 + h*16;
        const __half2 cs = __float2half2_rn(0.25f * 1.44269504f);
        __half2 a0 = __hmul2(*(const __half2*)(p0 + 2*q), cs);
        __half2 a1 = __hmul2(*(const __half2*)(p1 + 2*q), cs);
        __half2 a2 = __hmul2(*(const __half2*)(p0 + 8 + 2*q), cs);
        __half2 a3 = __hmul2(*(const __half2*)(p1 + 8 + 2*q), cs);
        qfr[0] = *(uint32_t*)&a0; qfr[1] = *(uint32_t*)&a1;
        qfr[2] = *(uint32_t*)&a2; qfr[3] = *(uint32_t*)&a3;
    }

    auto exp2h2 = [&](uint32_t s)->uint32_t{
        __half2 y = *(__half2*)&s;
        __half2 p = __hfma2(C3, y, C2);
        p = __hfma2(p, y, C1);
        p = __hfma2(p, y, C0);
        return *(uint32_t*)&p;
    };

    uint32_t uo0[2] = {0u,0u}, uo1[2] = {0u,0u}, uo2[2] = {0u,0u};

    stage(0, 0);
    stage(1, 1);
#pragma unroll
    for (int c = 0; c < 4; c++){
        if (c < 3) asm volatile("cp.async.wait_group 1;":::"memory");
        else       asm volatile("cp.async.wait_group 0;":::"memory");
        __syncthreads();
        if (c < 2) stage(c + 2, (c + 2) % 3);

        const int buf = c % 3;
        const uint32_t kb = su32(&Ks[buf][0]) + koff;
        const uint32_t vb = su32(&Vs[buf][0]) + voff;

        uint32_t pa[8][4];
#pragma unroll
        for (int jp=0; jp<8; jp++){
            uint32_t k0,k1,k2,k3, s0,s1,s2,s3;
            ldmx4(kb + jp*768, k0,k1,k2,k3);
            mma16816h(s0, s1, qfr, k0, k1);
            mma16816h(s2, s3, qfr, k2, k3);
            pa[jp][0] = exp2h2(s0); pa[jp][1] = exp2h2(s1);
            pa[jp][2] = exp2h2(s2); pa[jp][3] = exp2h2(s3);
        }
#pragma unroll
        for (int t=0; t<8; t++){
            uint32_t v0,v1,v2,v3;
            ldmx4t(vb + t*768, v0,v1,v2,v3);
            mma16816hacc(uo0[0], uo0[1], pa[t], v0, v1);
            mma16816hacc(uo1[0], uo1[1], pa[t], v2, v3);
            mma16816hacc(uo2[0], uo2[1], pa[t], ONE2, ONE2);
        }
    }

    const float l0 = __half2float(__low2half(*(__half2*)&uo2[0]));
    const float l1 = __half2float(__low2half(*(__half2*)&uo2[1]));
    const float i0 = 1.f / l0, i1 = 1.f / l1;

    __half2 o00 = *(__half2*)&uo0[0], o01 = *(__half2*)&uo0[1];
    __half2 o10 = *(__half2*)&uo1[0], o11 = *(__half2*)&uo1[1];

    const int row = b*LL + qb*128 + w*16 + g;
    {
        int col = h*16 + 2*q;
        *(__half2*)&out[(size_t)row*DD + col] =
            __floats2half2_rn(__half2float(__low2half(o00))*i0,
                              __half2float(__high2half(o00))*i0);
        *(__half2*)&out[(size_t)(row+8)*DD + col] =
            __floats2half2_rn(__half2float(__low2half(o01))*i1,
                              __half2float(__high2half(o01))*i1);
        *(__half2*)&out[(size_t)row*DD + col + 8] =
            __floats2half2_rn(__half2float(__low2half(o10))*i0,
                              __half2float(__high2half(o10))*i0);
        *(__half2*)&out[(size_t)(row+8)*DD + col + 8] =
            __floats2half2_rn(__half2float(__low2half(o11))*i1,
                              __half2float(__high2half(o11))*i1);
    }
}

// ---------------- pooling + classifier ----------------
__global__ __launch_bounds__(256)
void pool_k(const float* __restrict__ h, float* __restrict__ pooled4)
{
    const int b = blockIdx.x, c = blockIdx.y, t = threadIdx.x;
    const int col = t & 127, hs = t >> 7;
    __shared__ float red[256];
    const float* p = h + (size_t)b*LL*DD + (size_t)(c*128 + hs*64)*DD + col;
    float s = 0.f;
    for (int l=0; l<64; l++) s += p[(size_t)l*DD];
    red[t] = s;
    __syncthreads();
    if (t < 128) pooled4[(size_t)c*NB*DD + b*DD + t] = red[t] + red[t+128];
}

__global__ __launch_bounds__(64)
void cls_k(const float* __restrict__ pooled4,
           const float* __restrict__ W1, const float* __restrict__ b1,
           const float* __restrict__ W2, const float* __restrict__ b2,
           float* __restrict__ out)
{
    const int b = blockIdx.x, t = threadIdx.x;
    __shared__ float ps[128], hid[64];
#pragma unroll
    for (int i=0;i<2;i++){
        int col = t + i*64;
        float s = 0.f;
#pragma unroll
        for (int c=0;c<4;c++) s += pooled4[(size_t)c*NB*DD + b*DD + col];
        ps[col] = s * (1.f/(float)LL);
    }
    __syncthreads();
    float a = b1[t];
    for (int k=0;k<128;k++) a = fmaf(ps[k], W1[k*64 + t], a);
    hid[t] = fmaxf(a, 0.f);
    __syncthreads();
    if (t < OUTC){
        float o = b2[t];
#pragma unroll
        for (int k=0;k<64;k++) o = fmaf(hid[k], W2[k*OUTC + t], o);
        out[b*OUTC + t] = o;
    }
}

extern "C" void kernel_launch(void* const* d_in, const int* in_sizes, int n_in,
                              void* d_out, int out_size)
{
    const float* x      = (const float*)d_in[0];
    const float* Wp     = (const float*)d_in[n_in-18];
    const float* bp     = (const float*)d_in[n_in-17];
    const float* qkv_w  = (const float*)d_in[n_in-16];
    const float* qkv_b  = (const float*)d_in[n_in-15];
    const float* out_w  = (const float*)d_in[n_in-14];
    const float* out_b  = (const float*)d_in[n_in-13];
    const float* ln1_g  = (const float*)d_in[n_in-12];
    const float* ln1_b  = (const float*)d_in[n_in-11];
    const float* ffn_w1 = (const float*)d_in[n_in-10];
    const float* ffn_b1 = (const float*)d_in[n_in-9];
    const float* ffn_w2 = (const float*)d_in[n_in-8];
    const float* ffn_b2 = (const float*)d_in[n_in-7];
    const float* ln2_g  = (const float*)d_in[n_in-6];
    const float* ln2_b  = (const float*)d_in[n_in-5];
    const float* cls_w1 = (const float*)d_in[n_in-4];
    const float* cls_b1 = (const float*)d_in[n_in-3];
    const float* cls_w2 = (const float*)d_in[n_in-2];
    const float* cls_b2 = (const float*)d_in[n_in-1];
    float* out = (float*)d_out;

    float *h, *pooled4;
    __half *h16, *x16, *qkv16, *whi;
    cudaGetSymbolAddress((void**)&h,       g_h);
    cudaGetSymbolAddress((void**)&pooled4, g_pool4);
    cudaGetSymbolAddress((void**)&h16,     g_h16);
    cudaGetSymbolAddress((void**)&x16,     g_x16);
    cudaGetSymbolAddress((void**)&qkv16,   g_qkv16);
    cudaGetSymbolAddress((void**)&whi,     g_whi);
    __half* attn16 = x16;

    cudaFuncSetAttribute(layer_k, cudaFuncAttributeMaxDynamicSharedMemorySize, LYR_SMEM);

    cvtall<<<2048,256>>>(Wp, qkv_w, out_w, ffn_w1, ffn_w2, x, whi, x16);

    const int MB = NT/128;

    hgemm<<<dim3(1,MB),256>>>(x16, whi+OFF_WP, bp, h, h16, DD, DD);

    for (int i=0; i<NLAYERS; i++){
        hgemm16<<<dim3(3,MB),256>>>(
            h16, whi+OFF_QKV+(size_t)i*128*384,
            qkv_b+(size_t)i*384, qkv16, 384, 128);

        attn_k<<<dim3(4,HH,NB),256>>>(qkv16, attn16);

        layer_k<<<MB,256,LYR_SMEM>>>(
            attn16,
            whi+OFF_OUT+(size_t)i*128*128, out_b+(size_t)i*128,
            ln1_g+(size_t)i*DD, ln1_b+(size_t)i*DD,
            whi+OFF_F1+(size_t)i*128*512, ffn_b1+(size_t)i*512,
            whi+OFF_F2+(size_t)i*512*128, ffn_b2+(size_t)i*128,
            h, h16, ln2_g+(size_t)i*DD, ln2_b+(size_t)i*DD);
    }

    pool_k<<<dim3(NB,4),256>>>(h, pooled4);
    cls_k<<<NB,64>>>(pooled4, cls_w1, cls_b1, cls_w2, cls_b2, out);

    (void)in_sizes; (void)out_size;
}

// round 15
// speedup vs baseline: 1.7885x; 1.0853x over previous
#include <cuda_runtime.h>
#include <cuda_fp16.h>
#include <math.h>
#include <stdint.h>

#define NB 64
#define LL 512
#define NT (NB*LL)
#define DD 128
#define HH 8
#define FFD 512
#define NLAYERS 6
#define OUTC 10

#define SZ_WP   (128*128)
#define SZ_QKV  (NLAYERS*128*384)
#define SZ_OUT  (NLAYERS*128*128)
#define SZ_F1   (NLAYERS*128*512)
#define SZ_F2   (NLAYERS*512*128)
#define OFF_WP  0
#define OFF_QKV (SZ_WP)
#define OFF_OUT (OFF_QKV+SZ_QKV)
#define OFF_F1  (OFF_OUT+SZ_OUT)
#define OFF_F2  (OFF_F1+SZ_F1)
#define W16_TOT (OFF_F2+SZ_F2)

// fused layer dynamic smem: AF 32KB + FF 128KB + Ws 4x8KB + LN 2KB
#define LYR_SMEM (32768 + 131072 + 32768 + 2048)

typedef unsigned long long ull;

__device__ float  g_h   [NT*DD];
__device__ __align__(16) __half g_h16   [NT*DD];
__device__ __align__(16) __half g_x16   [NT*DD];   // also reused as attn16
__device__ __align__(16) __half g_qkv16 [NT*3*DD];
__device__ __align__(16) __half g_whi   [W16_TOT];
__device__ float g_pool4[4][NB*DD];

__device__ __forceinline__ uint32_t su32(const void* p){
    return (uint32_t)__cvta_generic_to_shared(p);
}
__device__ __forceinline__ void ldmx4(uint32_t a, uint32_t& r0, uint32_t& r1,
                                      uint32_t& r2, uint32_t& r3){
    asm volatile("ldmatrix.sync.aligned.m8n8.x4.shared.b16 {%0,%1,%2,%3},[%4];"
        :"=r"(r0),"=r"(r1),"=r"(r2),"=r"(r3):"r"(a));
}
__device__ __forceinline__ void ldmx4t(uint32_t a, uint32_t& r0, uint32_t& r1,
                                       uint32_t& r2, uint32_t& r3){
    asm volatile("ldmatrix.sync.aligned.m8n8.x4.trans.shared.b16 {%0,%1,%2,%3},[%4];"
        :"=r"(r0),"=r"(r1),"=r"(r2),"=r"(r3):"r"(a));
}
__device__ __forceinline__ void mma16816(float* c, const uint32_t* a,
                                         uint32_t b0, uint32_t b1){
    asm volatile("mma.sync.aligned.m16n8k16.row.col.f32.f16.f16.f32 "
        "{%0,%1,%2,%3},{%4,%5,%6,%7},{%8,%9},{%0,%1,%2,%3};"
        :"+f"(c[0]),"+f"(c[1]),"+f"(c[2]),"+f"(c[3])
        :"r"(a[0]),"r"(a[1]),"r"(a[2]),"r"(a[3]),"r"(b0),"r"(b1));
}
__device__ __forceinline__ void mma16816h(uint32_t& d0, uint32_t& d1,
                                          const uint32_t* a,
                                          uint32_t b0, uint32_t b1){
    asm volatile("mma.sync.aligned.m16n8k16.row.col.f16.f16.f16.f16 "
        "{%0,%1},{%2,%3,%4,%5},{%6,%7},{%8,%9};"
        :"=r"(d0),"=r"(d1)
        :"r"(a[0]),"r"(a[1]),"r"(a[2]),"r"(a[3]),"r"(b0),"r"(b1),
         "r"(0u),"r"(0u));
}
__device__ __forceinline__ void mma16816hacc(uint32_t& d0, uint32_t& d1,
                                             const uint32_t* a,
                                             uint32_t b0, uint32_t b1){
    asm volatile("mma.sync.aligned.m16n8k16.row.col.f16.f16.f16.f16 "
        "{%0,%1},{%2,%3,%4,%5},{%6,%7},{%0,%1};"
        :"+r"(d0),"+r"(d1)
        :"r"(a[0]),"r"(a[1]),"r"(a[2]),"r"(a[3]),"r"(b0),"r"(b1));
}
__device__ __forceinline__ void cpa16(uint32_t dst, const void* src){
    asm volatile("cp.async.cg.shared.global [%0],[%1],16;"::"r"(dst),"l"(src));
}
#define WAITG(n) asm volatile("cp.async.wait_group " #n ";":::"memory")
// wait so that iteration kt's group is complete; rem = NITER-1-kt
__device__ __forceinline__ void waitg_rem(int rem){
    if (rem >= 2) WAITG(2);
    else if (rem == 1) WAITG(1);
    else WAITG(0);
}

// ---------------- single fused conversion kernel ----------------
__global__ void cvtall(const float* __restrict__ Wp, const float* __restrict__ qkvw,
                       const float* __restrict__ outw, const float* __restrict__ f1,
                       const float* __restrict__ f2, const float* __restrict__ x,
                       __half* __restrict__ hi, __half* __restrict__ x16)
{
    const int TOT = W16_TOT + NT*DD;
    for (int i = blockIdx.x*blockDim.x + threadIdx.x; i < TOT;
         i += gridDim.x*blockDim.x){
        if (i >= W16_TOT){
            int j = i - W16_TOT;
            x16[j] = __float2half_rn(x[j]);
            continue;
        }
        float w;
        if (i < OFF_QKV){
            w = Wp[i];
        } else if (i < OFF_OUT){
            int j = i - OFF_QKV;
            int L = j / (128*384); int r = j - L*(128*384);
            int k = r / 384, n = r - k*384;
            w = qkvw[(size_t)L*384*128 + (size_t)n*128 + k];
        } else if (i < OFF_F1){
            int j = i - OFF_OUT;
            int L = j / (128*128); int r = j - L*(128*128);
            int k = r >> 7, n = r & 127;
            w = outw[(size_t)L*128*128 + (size_t)n*128 + k];
        } else if (i < OFF_F2){
            w = f1[i - OFF_F1];
        } else {
            w = f2[i - OFF_F2];
        }
        hi[i] = __float2half_rn(w);
    }
}

// ---------------- fp16 tensor-core GEMM (input projection only) ----------------
__global__ __launch_bounds__(256)
void hgemm(const __half* __restrict__ A, const __half* __restrict__ W,
           const float* __restrict__ bias,
           float* __restrict__ C32, __half* __restrict__ C16, int N, int K)
{
    __shared__ __align__(16) __half As[2][128*32];
    __shared__ __align__(16) __half Ws[2][32*128];
    const int tid = threadIdx.x;
    const int lane = tid & 31, wid = tid >> 5;
    const int wm = wid & 3, wn = wid >> 2;
    const int bm = blockIdx.y * 128, bn = blockIdx.x * 128;

    float acc[2][8][4];
#pragma unroll
    for (int i=0;i<2;i++)
#pragma unroll
        for (int j=0;j<8;j++)
#pragma unroll
            for (int k=0;k<4;k++) acc[i][j][k]=0.f;

    const int KT = K/32;

    auto issue = [&](int kt){
        int buf = kt & 1;
        int k0  = kt * 32;
        uint32_t sA = su32(&As[buf][0]);
        uint32_t sW = su32(&Ws[buf][0]);
#pragma unroll
        for (int i=0;i<2;i++){
            int id = tid + i*256;
            int r = id >> 2, c = id & 3;
            cpa16(sA + r*64 + ((c ^ ((r>>1)&3)) << 4),
                  A + (size_t)(bm + r)*K + k0 + c*8);
            int k = id >> 4, cc = id & 15;
            cpa16(sW + k*256 + ((cc ^ (k&7)) << 4),
                  W + (size_t)(k0 + k)*N + bn + cc*8);
        }
        asm volatile("cp.async.commit_group;":::"memory");
    };

    issue(0);
    for (int kt = 0; kt < KT; kt++){
        int buf = kt & 1;
        if (kt + 1 < KT){
            issue(kt + 1);
            asm volatile("cp.async.wait_group 1;":::"memory");
        } else {
            asm volatile("cp.async.wait_group 0;":::"memory");
        }
        __syncthreads();
        uint32_t sA = su32(&As[buf][0]);
        uint32_t sW = su32(&Ws[buf][0]);
#pragma unroll
        for (int ks = 0; ks < 32; ks += 16){
            uint32_t afr[2][4];
#pragma unroll
            for (int mt=0; mt<2; mt++){
                int r = wm*32 + mt*16 + (lane & 15);
                int cg = (ks >> 3) + (lane >> 4);
                ldmx4(sA + r*64 + ((cg ^ ((r>>1)&3)) << 4),
                      afr[mt][0], afr[mt][1], afr[mt][2], afr[mt][3]);
            }
            uint32_t bfr[4][4];
#pragma unroll
            for (int ntp=0; ntp<4; ntp++){
                int k  = ks + (lane & 15);
                int cc = wn*8 + ntp*2 + (lane >> 4);
                ldmx4t(sW + k*256 + ((cc ^ (k&7)) << 4),
                       bfr[ntp][0], bfr[ntp][1], bfr[ntp][2], bfr[ntp][3]);
            }
#pragma unroll
            for (int mt=0; mt<2; mt++)
#pragma unroll
                for (int nt=0; nt<8; nt++)
                    mma16816(acc[mt][nt], afr[mt],
                             bfr[nt>>1][(nt&1)*2], bfr[nt>>1][(nt&1)*2+1]);
        }
        __syncthreads();
    }

    const int g = lane >> 2, q = lane & 3;
#pragma unroll
    for (int mt=0; mt<2; mt++){
        int row = bm + wm*32 + mt*16 + g;
#pragma unroll
        for (int nt=0; nt<8; nt++){
            int col = bn + wn*64 + nt*8 + q*2;
            float2 bv = *(const float2*)&bias[col];
            float v0 = acc[mt][nt][0] + bv.x;
            float v1 = acc[mt][nt][1] + bv.y;
            float v2 = acc[mt][nt][2] + bv.x;
            float v3 = acc[mt][nt][3] + bv.y;
            *(float2*)&C32[(size_t)row*N + col]     = make_float2(v0,v1);
            *(float2*)&C32[(size_t)(row+8)*N + col] = make_float2(v2,v3);
            *(__half2*)&C16[(size_t)row*N + col]     = __floats2half2_rn(v0,v1);
            *(__half2*)&C16[(size_t)(row+8)*N + col] = __floats2half2_rn(v2,v3);
        }
    }
}

// ---------------- f16-accumulator GEMM (qkv only) ----------------
__global__ __launch_bounds__(256)
void hgemm16(const __half* __restrict__ A, const __half* __restrict__ W,
             const float* __restrict__ bias, __half* __restrict__ C16,
             int N, int K)
{
    __shared__ __align__(16) __half As[2][128*32];
    __shared__ __align__(16) __half Ws[2][32*128];
    const int tid = threadIdx.x;
    const int lane = tid & 31, wid = tid >> 5;
    const int wm = wid & 3, wn = wid >> 2;
    const int bm = blockIdx.y * 128, bn = blockIdx.x * 128;

    uint32_t hacc[2][8][2];
#pragma unroll
    for (int i=0;i<2;i++)
#pragma unroll
        for (int j=0;j<8;j++){ hacc[i][j][0]=0u; hacc[i][j][1]=0u; }

    const int KT = K/32;

    auto issue = [&](int kt){
        int buf = kt & 1;
        int k0  = kt * 32;
        uint32_t sA = su32(&As[buf][0]);
        uint32_t sW = su32(&Ws[buf][0]);
#pragma unroll
        for (int i=0;i<2;i++){
            int id = tid + i*256;
            int r = id >> 2, c = id & 3;
            cpa16(sA + r*64 + ((c ^ ((r>>1)&3)) << 4),
                  A + (size_t)(bm + r)*K + k0 + c*8);
            int k = id >> 4, cc = id & 15;
            cpa16(sW + k*256 + ((cc ^ (k&7)) << 4),
                  W + (size_t)(k0 + k)*N + bn + cc*8);
        }
        asm volatile("cp.async.commit_group;":::"memory");
    };

    issue(0);
    for (int kt = 0; kt < KT; kt++){
        int buf = kt & 1;
        if (kt + 1 < KT){
            issue(kt + 1);
            asm volatile("cp.async.wait_group 1;":::"memory");
        } else {
            asm volatile("cp.async.wait_group 0;":::"memory");
        }
        __syncthreads();
        uint32_t sA = su32(&As[buf][0]);
        uint32_t sW = su32(&Ws[buf][0]);
#pragma unroll
        for (int ks = 0; ks < 32; ks += 16){
            uint32_t afr[2][4];
#pragma unroll
            for (int mt=0; mt<2; mt++){
                int r = wm*32 + mt*16 + (lane & 15);
                int cg = (ks >> 3) + (lane >> 4);
                ldmx4(sA + r*64 + ((cg ^ ((r>>1)&3)) << 4),
                      afr[mt][0], afr[mt][1], afr[mt][2], afr[mt][3]);
            }
            uint32_t bfr[4][4];
#pragma unroll
            for (int ntp=0; ntp<4; ntp++){
                int k  = ks + (lane & 15);
                int cc = wn*8 + ntp*2 + (lane >> 4);
                ldmx4t(sW + k*256 + ((cc ^ (k&7)) << 4),
                       bfr[ntp][0], bfr[ntp][1], bfr[ntp][2], bfr[ntp][3]);
            }
#pragma unroll
            for (int mt=0; mt<2; mt++)
#pragma unroll
                for (int nt=0; nt<8; nt++)
                    mma16816hacc(hacc[mt][nt][0], hacc[mt][nt][1], afr[mt],
                                 bfr[nt>>1][(nt&1)*2], bfr[nt>>1][(nt&1)*2+1]);
        }
        __syncthreads();
    }

    const int g = lane >> 2, q = lane & 3;
#pragma unroll
    for (int mt=0; mt<2; mt++){
        int row = bm + wm*32 + mt*16 + g;
#pragma unroll
        for (int nt=0; nt<8; nt++){
            int col = bn + wn*64 + nt*8 + q*2;
            float2 bv = *(const float2*)&bias[col];
            __half2 hb = __floats2half2_rn(bv.x, bv.y);
            __half2 v0 = __hadd2(*(__half2*)&hacc[mt][nt][0], hb);
            __half2 v1 = __hadd2(*(__half2*)&hacc[mt][nt][1], hb);
            *(__half2*)&C16[(size_t)row*N + col]     = v0;
            *(__half2*)&C16[(size_t)(row+8)*N + col] = v1;
        }
    }
}

// ---------------- fused layer tail: out-proj + LN1 + FFN + LN2 ----------------
// 4-buffer / 3-deep W pipeline, single sync per k-tile iteration.
__global__ __launch_bounds__(256)
void layer_k(const __half* __restrict__ attn16,
             const __half* __restrict__ Wout, const float* __restrict__ bo,
             const float* __restrict__ ln1g, const float* __restrict__ ln1b,
             const __half* __restrict__ W1, const float* __restrict__ b1,
             const __half* __restrict__ W2, const float* __restrict__ b2,
             float* __restrict__ h, __half* __restrict__ h16,
             const float* __restrict__ ln2g, const float* __restrict__ ln2b)
{
    extern __shared__ __align__(16) char dsm[];
    __half* AF = (__half*)dsm;                       // 4 ktiles (32KB)
    __half* FF = (__half*)(dsm + 32768);             // 16 ktiles (128KB)
    __half* WS = (__half*)(dsm + 32768 + 131072);    // 4 bufs (32KB)
    float*  sS = (float*)(dsm + 32768 + 131072 + 32768);
    float*  sQ = sS + 256;

    const int tid = threadIdx.x, lane = tid & 31, wid = tid >> 5;
    const int wm = wid & 3, wn = wid >> 2;
    const int g = lane >> 2, q = lane & 3;
    const int bm = blockIdx.x * 128;

    const uint32_t sAF = su32(AF);
    const uint32_t sFF = su32(FF);
    const uint32_t sW  = su32(WS);

    // W staging: tile [32 x 128] into buf (kt&3)
    auto issueW = [&](const __half* W, int N, int j, int kt){
        int buf = kt & 3;
        int k0  = kt * 32;
#pragma unroll
        for (int i=0;i<2;i++){
            int id = tid + i*256;
            int k = id >> 4, cc = id & 15;
            cpa16(sW + buf*8192 + k*256 + ((cc ^ (k&7)) << 4),
                  W + (size_t)(k0 + k)*N + j*128 + cc*8);
        }
        asm volatile("cp.async.commit_group;":::"memory");
    };

    float y[2][8][4];   // LN1 output, lives through phases 1 & 2

    // ======== phase 0: out-proj + residual + LN1 ========
    {
        // stage attn16 block (128x128) into AF (1 group)
#pragma unroll
        for (int i=0;i<8;i++){
            int id = tid + i*256;
            int r = id >> 4, c = id & 15;
            int kt = c >> 2, cc = c & 3;
            cpa16(sAF + kt*8192 + r*64 + ((cc ^ ((r>>1)&3)) << 4),
                  attn16 + (size_t)(bm + r)*128 + c*8);
        }
        asm volatile("cp.async.commit_group;":::"memory");

        float acc[2][8][4];
#pragma unroll
        for (int i=0;i<2;i++)
#pragma unroll
            for (int jj=0;jj<8;jj++)
#pragma unroll
                for (int k=0;k<4;k++) acc[i][jj][k]=0.f;

        issueW(Wout, 128, 0, 0);
        issueW(Wout, 128, 0, 1);
        issueW(Wout, 128, 0, 2);
#pragma unroll
        for (int kt = 0; kt < 4; kt++){
            waitg_rem(3 - kt);
            __syncthreads();
            if (kt == 0) issueW(Wout, 128, 0, 3);
            uint32_t sWb = sW + (kt&3)*8192;
#pragma unroll
            for (int ks = 0; ks < 32; ks += 16){
                uint32_t afr[2][4];
#pragma unroll
                for (int mt=0; mt<2; mt++){
                    int r = wm*32 + mt*16 + (lane & 15);
                    int cg = (ks >> 3) + (lane >> 4);
                    ldmx4(sAF + kt*8192 + r*64 + ((cg ^ ((r>>1)&3)) << 4),
                          afr[mt][0], afr[mt][1], afr[mt][2], afr[mt][3]);
                }
                uint32_t bfr[4][4];
#pragma unroll
                for (int ntp=0; ntp<4; ntp++){
                    int k  = ks + (lane & 15);
                    int cc = wn*8 + ntp*2 + (lane >> 4);
                    ldmx4t(sWb + k*256 + ((cc ^ (k&7)) << 4),
                           bfr[ntp][0], bfr[ntp][1], bfr[ntp][2], bfr[ntp][3]);
                }
#pragma unroll
                for (int mt=0; mt<2; mt++)
#pragma unroll
                    for (int nt=0; nt<8; nt++)
                        mma16816(acc[mt][nt], afr[mt],
                                 bfr[nt>>1][(nt&1)*2], bfr[nt>>1][(nt&1)*2+1]);
            }
        }
        __syncthreads();   // all warps done with AF reads before epilogue rewrites AF

        // residual + LN1 -> y regs + AF fp16
        float vsum[2][2], vsq[2][2];
#pragma unroll
        for (int mt=0; mt<2; mt++){ vsum[mt][0]=vsum[mt][1]=0.f; vsq[mt][0]=vsq[mt][1]=0.f; }
#pragma unroll
        for (int mt=0; mt<2; mt++){
            int row0 = bm + wm*32 + mt*16 + g;
#pragma unroll
            for (int nt=0; nt<8; nt++){
                int col = wn*64 + nt*8 + q*2;
                float2 bv  = *(const float2*)&bo[col];
                float2 rr0 = *(const float2*)&h[(size_t)row0*128 + col];
                float2 rr1 = *(const float2*)&h[(size_t)(row0+8)*128 + col];
                float v0 = acc[mt][nt][0] + bv.x + rr0.x;
                float v1 = acc[mt][nt][1] + bv.y + rr0.y;
                float v2 = acc[mt][nt][2] + bv.x + rr1.x;
                float v3 = acc[mt][nt][3] + bv.y + rr1.y;
                acc[mt][nt][0]=v0; acc[mt][nt][1]=v1;
                acc[mt][nt][2]=v2; acc[mt][nt][3]=v3;
                vsum[mt][0] += v0+v1; vsq[mt][0] = fmaf(v0,v0,fmaf(v1,v1,vsq[mt][0]));
                vsum[mt][1] += v2+v3; vsq[mt][1] = fmaf(v2,v2,fmaf(v3,v3,vsq[mt][1]));
            }
        }
#pragma unroll
        for (int mt=0; mt<2; mt++)
#pragma unroll
            for (int r2=0; r2<2; r2++){
                vsum[mt][r2] += __shfl_xor_sync(0xffffffffu, vsum[mt][r2], 1);
                vsum[mt][r2] += __shfl_xor_sync(0xffffffffu, vsum[mt][r2], 2);
                vsq[mt][r2]  += __shfl_xor_sync(0xffffffffu, vsq[mt][r2], 1);
                vsq[mt][r2]  += __shfl_xor_sync(0xffffffffu, vsq[mt][r2], 2);
            }
        if (q == 0){
#pragma unroll
            for (int mt=0; mt<2; mt++)
#pragma unroll
                for (int r2=0; r2<2; r2++){
                    int r = wm*32 + mt*16 + g + r2*8;
                    sS[wn*128 + r] = vsum[mt][r2];
                    sQ[wn*128 + r] = vsq[mt][r2];
                }
        }
        __syncthreads();
#pragma unroll
        for (int mt=0; mt<2; mt++){
            int r0 = wm*32 + mt*16 + g, r1 = r0 + 8;
            float mean0 = (sS[r0]+sS[128+r0]) * (1.f/128.f);
            float mean1 = (sS[r1]+sS[128+r1]) * (1.f/128.f);
            float var0  = (sQ[r0]+sQ[128+r0]) * (1.f/128.f) - mean0*mean0;
            float var1  = (sQ[r1]+sQ[128+r1]) * (1.f/128.f) - mean1*mean1;
            float rs0 = rsqrtf(var0 + 1e-5f);
            float rs1 = rsqrtf(var1 + 1e-5f);
#pragma unroll
            for (int nt=0; nt<8; nt++){
                int col = wn*64 + nt*8 + q*2;
                float2 gg = *(const float2*)&ln1g[col];
                float2 bb = *(const float2*)&ln1b[col];
                float y0 = (acc[mt][nt][0]-mean0)*rs0*gg.x + bb.x;
                float y1 = (acc[mt][nt][1]-mean0)*rs0*gg.y + bb.y;
                float y2 = (acc[mt][nt][2]-mean1)*rs1*gg.x + bb.x;
                float y3 = (acc[mt][nt][3]-mean1)*rs1*gg.y + bb.y;
                y[mt][nt][0]=y0; y[mt][nt][1]=y1;
                y[mt][nt][2]=y2; y[mt][nt][3]=y3;
                int ktile = col >> 5, c = col & 31, c8 = c >> 3;
                int base = ktile*8192 + (c&7)*2;
                int row0l = wm*32 + mt*16 + g, row1l = row0l + 8;
                int o0 = base + row0l*64 + ((c8 ^ ((row0l>>1)&3)) << 4);
                int o1 = base + row1l*64 + ((c8 ^ ((row1l>>1)&3)) << 4);
                *(__half2*)((char*)AF + o0) = __floats2half2_rn(y0, y1);
                *(__half2*)((char*)AF + o1) = __floats2half2_rn(y2, y3);
            }
        }
        __syncthreads();   // AF(u16) visible to all warps
    }

    // ======== phase 1: FF = relu(u16 @ W1 + b1) in smem ========
    for (int j=0;j<4;j++){
        float acc[2][8][4];
#pragma unroll
        for (int i=0;i<2;i++)
#pragma unroll
            for (int jj=0;jj<8;jj++)
#pragma unroll
                for (int k=0;k<4;k++) acc[i][jj][k]=0.f;

        issueW(W1, 512, j, 0);
        issueW(W1, 512, j, 1);
        issueW(W1, 512, j, 2);
#pragma unroll
        for (int kt = 0; kt < 4; kt++){
            waitg_rem(3 - kt);
            __syncthreads();
            if (kt == 0) issueW(W1, 512, j, 3);
            uint32_t sWb = sW + (kt&3)*8192;
#pragma unroll
            for (int ks = 0; ks < 32; ks += 16){
                uint32_t afr[2][4];
#pragma unroll
                for (int mt=0; mt<2; mt++){
                    int r = wm*32 + mt*16 + (lane & 15);
                    int cg = (ks >> 3) + (lane >> 4);
                    ldmx4(sAF + kt*8192 + r*64 + ((cg ^ ((r>>1)&3)) << 4),
                          afr[mt][0], afr[mt][1], afr[mt][2], afr[mt][3]);
                }
                uint32_t bfr[4][4];
#pragma unroll
                for (int ntp=0; ntp<4; ntp++){
                    int k  = ks + (lane & 15);
                    int cc = wn*8 + ntp*2 + (lane >> 4);
                    ldmx4t(sWb + k*256 + ((cc ^ (k&7)) << 4),
                           bfr[ntp][0], bfr[ntp][1], bfr[ntp][2], bfr[ntp][3]);
                }
#pragma unroll
                for (int mt=0; mt<2; mt++)
#pragma unroll
                    for (int nt=0; nt<8; nt++)
                        mma16816(acc[mt][nt], afr[mt],
                                 bfr[nt>>1][(nt&1)*2], bfr[nt>>1][(nt&1)*2+1]);
            }
        }
#pragma unroll
        for (int mt=0; mt<2; mt++){
            int row0 = wm*32 + mt*16 + g;
            int row1 = row0 + 8;
#pragma unroll
            for (int nt=0; nt<8; nt++){
                int col = j*128 + wn*64 + nt*8 + q*2;
                float2 bv = *(const float2*)&b1[col];
                float v0 = fmaxf(acc[mt][nt][0] + bv.x, 0.f);
                float v1 = fmaxf(acc[mt][nt][1] + bv.y, 0.f);
                float v2 = fmaxf(acc[mt][nt][2] + bv.x, 0.f);
                float v3 = fmaxf(acc[mt][nt][3] + bv.y, 0.f);
                int ktile = col >> 5, c = col & 31, c8 = c >> 3;
                int base = ktile*8192 + (c&7)*2;
                int o0 = base + row0*64 + ((c8 ^ ((row0>>1)&3)) << 4);
                int o1 = base + row1*64 + ((c8 ^ ((row1>>1)&3)) << 4);
                *(__half2*)((char*)FF + o0) = __floats2half2_rn(v0, v1);
                *(__half2*)((char*)FF + o1) = __floats2half2_rn(v2, v3);
            }
        }
    }
    __syncthreads();   // FF complete

    // ======== phase 2: h = LN2(u + FF @ W2 + b2) ========
    float acc[2][8][4];
#pragma unroll
    for (int i=0;i<2;i++)
#pragma unroll
        for (int jj=0;jj<8;jj++)
#pragma unroll
            for (int k=0;k<4;k++) acc[i][jj][k]=0.f;

    issueW(W2, 128, 0, 0);
    issueW(W2, 128, 0, 1);
    issueW(W2, 128, 0, 2);
#pragma unroll
    for (int kt = 0; kt < 16; kt++){
        waitg_rem(15 - kt);
        __syncthreads();
        if (kt + 3 < 16) issueW(W2, 128, 0, kt + 3);
        uint32_t sWb = sW + (kt&3)*8192;
#pragma unroll
        for (int ks = 0; ks < 32; ks += 16){
            uint32_t afr[2][4];
#pragma unroll
            for (int mt=0; mt<2; mt++){
                int r = wm*32 + mt*16 + (lane & 15);
                int cg = (ks >> 3) + (lane >> 4);
                ldmx4(sFF + kt*8192 + r*64 + ((cg ^ ((r>>1)&3)) << 4),
                      afr[mt][0], afr[mt][1], afr[mt][2], afr[mt][3]);
            }
            uint32_t bfr[4][4];
#pragma unroll
            for (int ntp=0; ntp<4; ntp++){
                int k  = ks + (lane & 15);
                int cc = wn*8 + ntp*2 + (lane >> 4);
                ldmx4t(sWb + k*256 + ((cc ^ (k&7)) << 4),
                       bfr[ntp][0], bfr[ntp][1], bfr[ntp][2], bfr[ntp][3]);
            }
#pragma unroll
            for (int mt=0; mt<2; mt++)
#pragma unroll
                for (int nt=0; nt<8; nt++)
                    mma16816(acc[mt][nt], afr[mt],
                             bfr[nt>>1][(nt&1)*2], bfr[nt>>1][(nt&1)*2+1]);
        }
    }

    {
        float vsum[2][2], vsq[2][2];
#pragma unroll
        for (int mt=0; mt<2; mt++){ vsum[mt][0]=vsum[mt][1]=0.f; vsq[mt][0]=vsq[mt][1]=0.f; }
#pragma unroll
        for (int mt=0; mt<2; mt++){
#pragma unroll
            for (int nt=0; nt<8; nt++){
                int col = wn*64 + nt*8 + q*2;
                float2 bv = *(const float2*)&b2[col];
                float v0 = acc[mt][nt][0] + bv.x + y[mt][nt][0];
                float v1 = acc[mt][nt][1] + bv.y + y[mt][nt][1];
                float v2 = acc[mt][nt][2] + bv.x + y[mt][nt][2];
                float v3 = acc[mt][nt][3] + bv.y + y[mt][nt][3];
                acc[mt][nt][0]=v0; acc[mt][nt][1]=v1;
                acc[mt][nt][2]=v2; acc[mt][nt][3]=v3;
                vsum[mt][0] += v0+v1; vsq[mt][0] = fmaf(v0,v0,fmaf(v1,v1,vsq[mt][0]));
                vsum[mt][1] += v2+v3; vsq[mt][1] = fmaf(v2,v2,fmaf(v3,v3,vsq[mt][1]));
            }
        }
#pragma unroll
        for (int mt=0; mt<2; mt++)
#pragma unroll
            for (int r2=0; r2<2; r2++){
                vsum[mt][r2] += __shfl_xor_sync(0xffffffffu, vsum[mt][r2], 1);
                vsum[mt][r2] += __shfl_xor_sync(0xffffffffu, vsum[mt][r2], 2);
                vsq[mt][r2]  += __shfl_xor_sync(0xffffffffu, vsq[mt][r2], 1);
                vsq[mt][r2]  += __shfl_xor_sync(0xffffffffu, vsq[mt][r2], 2);
            }
        if (q == 0){
#pragma unroll
            for (int mt=0; mt<2; mt++)
#pragma unroll
                for (int r2=0; r2<2; r2++){
                    int r = wm*32 + mt*16 + g + r2*8;
                    sS[wn*128 + r] = vsum[mt][r2];
                    sQ[wn*128 + r] = vsq[mt][r2];
                }
        }
        __syncthreads();
#pragma unroll
        for (int mt=0; mt<2; mt++){
            int r0 = wm*32 + mt*16 + g, r1 = r0 + 8;
            float mean0 = (sS[r0]+sS[128+r0]) * (1.f/128.f);
            float mean1 = (sS[r1]+sS[128+r1]) * (1.f/128.f);
            float var0  = (sQ[r0]+sQ[128+r0]) * (1.f/128.f) - mean0*mean0;
            float var1  = (sQ[r1]+sQ[128+r1]) * (1.f/128.f) - mean1*mean1;
            float rs0 = rsqrtf(var0 + 1e-5f);
            float rs1 = rsqrtf(var1 + 1e-5f);
            int row0 = bm + r0;
#pragma unroll
            for (int nt=0; nt<8; nt++){
                int col = wn*64 + nt*8 + q*2;
                float2 gg = *(const float2*)&ln2g[col];
                float2 bb = *(const float2*)&ln2b[col];
                float y0 = (acc[mt][nt][0]-mean0)*rs0*gg.x + bb.x;
                float y1 = (acc[mt][nt][1]-mean0)*rs0*gg.y + bb.y;
                float y2 = (acc[mt][nt][2]-mean1)*rs1*gg.x + bb.x;
                float y3 = (acc[mt][nt][3]-mean1)*rs1*gg.y + bb.y;
                *(float2*)&h[(size_t)row0*128 + col]     = make_float2(y0,y1);
                *(float2*)&h[(size_t)(row0+8)*128 + col] = make_float2(y2,y3);
                *(__half2*)&h16[(size_t)row0*128 + col]     = __floats2half2_rn(y0,y1);
                *(__half2*)&h16[(size_t)(row0+8)*128 + col] = __floats2half2_rn(y2,y3);
            }
        }
    }
}

// ---------------- fused flash MHA (R13 proven) ----------------
__global__ __launch_bounds__(256)
void attn_k(const __half* __restrict__ qkv, __half* __restrict__ out)
{
    __shared__ __align__(16) __half Ks[3][128*24];
    __shared__ __align__(16) __half Vs[3][128*24];

    const int qb = blockIdx.x, h = blockIdx.y, b = blockIdx.z;
    const int tid = threadIdx.x, lane = tid & 31, w = tid >> 5;
    const int g = lane >> 2, q = lane & 3;
    const size_t base = (size_t)b * LL * 384;

    const __half2 C3 = __float2half2_rn(0.05550411f);
    const __half2 C2 = __float2half2_rn(0.24022651f);
    const __half2 C1 = __float2half2_rn(0.69314718f);
    const __half2 C0 = __float2half2_rn(1.0f);
    const uint32_t ONE2 = 0x3C003C00u;

    const int skey  = tid >> 2;
    const int spart = tid & 3;
    const __half* ssrc = qkv + base + 128 + (spart>>1)*128 + h*16 + (spart&1)*8;
    const int sd0 = skey*24 + (spart&1)*8;
    const int sd1 = (skey+64)*24 + (spart&1)*8;

    auto stage = [&](int c, int buf){
        __half* bb = (spart < 2) ? &Ks[buf][0] : &Vs[buf][0];
        cpa16(su32(bb + sd0), ssrc + (size_t)(c*128 + skey)*384);
        cpa16(su32(bb + sd1), ssrc + (size_t)(c*128 + skey + 64)*384);
        asm volatile("cp.async.commit_group;":::"memory");
    };

    const int koff = ((lane&7) + ((lane>>4)<<3))*48 + (((lane>>3)&1) << 4);
    const int voff = (lane&15)*48 + ((lane>>4) << 4);

    uint32_t qfr[4];
    {
        const int r0 = qb*128 + w*16 + g, r1 = r0 + 8;
        const __half* p0 = qkv + base + (size_t)r0*384 + h*16;
        const __half* p1 = qkv + base + (size_t)r1*384 + h*16;
        const __half2 cs = __float2half2_rn(0.25f * 1.44269504f);
        __half2 a0 = __hmul2(*(const __half2*)(p0 + 2*q), cs);
        __half2 a1 = __hmul2(*(const __half2*)(p1 + 2*q), cs);
        __half2 a2 = __hmul2(*(const __half2*)(p0 + 8 + 2*q), cs);
        __half2 a3 = __hmul2(*(const __half2*)(p1 + 8 + 2*q), cs);
        qfr[0] = *(uint32_t*)&a0; qfr[1] = *(uint32_t*)&a1;
        qfr[2] = *(uint32_t*)&a2; qfr[3] = *(uint32_t*)&a3;
    }

    auto exp2h2 = [&](uint32_t s)->uint32_t{
        __half2 y = *(__half2*)&s;
        __half2 p = __hfma2(C3, y, C2);
        p = __hfma2(p, y, C1);
        p = __hfma2(p, y, C0);
        return *(uint32_t*)&p;
    };

    uint32_t uo0[2] = {0u,0u}, uo1[2] = {0u,0u}, uo2[2] = {0u,0u};

    stage(0, 0);
    stage(1, 1);
#pragma unroll
    for (int c = 0; c < 4; c++){
        if (c < 3) asm volatile("cp.async.wait_group 1;":::"memory");
        else       asm volatile("cp.async.wait_group 0;":::"memory");
        __syncthreads();
        if (c < 2) stage(c + 2, (c + 2) % 3);

        const int buf = c % 3;
        const uint32_t kb = su32(&Ks[buf][0]) + koff;
        const uint32_t vb = su32(&Vs[buf][0]) + voff;

        uint32_t pa[8][4];
#pragma unroll
        for (int jp=0; jp<8; jp++){
            uint32_t k0,k1,k2,k3, s0,s1,s2,s3;
            ldmx4(kb + jp*768, k0,k1,k2,k3);
            mma16816h(s0, s1, qfr, k0, k1);
            mma16816h(s2, s3, qfr, k2, k3);
            pa[jp][0] = exp2h2(s0); pa[jp][1] = exp2h2(s1);
            pa[jp][2] = exp2h2(s2); pa[jp][3] = exp2h2(s3);
        }
#pragma unroll
        for (int t=0; t<8; t++){
            uint32_t v0,v1,v2,v3;
            ldmx4t(vb + t*768, v0,v1,v2,v3);
            mma16816hacc(uo0[0], uo0[1], pa[t], v0, v1);
            mma16816hacc(uo1[0], uo1[1], pa[t], v2, v3);
            mma16816hacc(uo2[0], uo2[1], pa[t], ONE2, ONE2);
        }
    }

    const float l0 = __half2float(__low2half(*(__half2*)&uo2[0]));
    const float l1 = __half2float(__low2half(*(__half2*)&uo2[1]));
    const float i0 = 1.f / l0, i1 = 1.f / l1;

    __half2 o00 = *(__half2*)&uo0[0], o01 = *(__half2*)&uo0[1];
    __half2 o10 = *(__half2*)&uo1[0], o11 = *(__half2*)&uo1[1];

    const int row = b*LL + qb*128 + w*16 + g;
    {
        int col = h*16 + 2*q;
        *(__half2*)&out[(size_t)row*DD + col] =
            __floats2half2_rn(__half2float(__low2half(o00))*i0,
                              __half2float(__high2half(o00))*i0);
        *(__half2*)&out[(size_t)(row+8)*DD + col] =
            __floats2half2_rn(__half2float(__low2half(o01))*i1,
                              __half2float(__high2half(o01))*i1);
        *(__half2*)&out[(size_t)row*DD + col + 8] =
            __floats2half2_rn(__half2float(__low2half(o10))*i0,
                              __half2float(__high2half(o10))*i0);
        *(__half2*)&out[(size_t)(row+8)*DD + col + 8] =
            __floats2half2_rn(__half2float(__low2half(o11))*i1,
                              __half2float(__high2half(o11))*i1);
    }
}

// ---------------- pooling + classifier ----------------
__global__ __launch_bounds__(256)
void pool_k(const float* __restrict__ h, float* __restrict__ pooled4)
{
    const int b = blockIdx.x, c = blockIdx.y, t = threadIdx.x;
    const int col = t & 127, hs = t >> 7;
    __shared__ float red[256];
    const float* p = h + (size_t)b*LL*DD + (size_t)(c*128 + hs*64)*DD + col;
    float s = 0.f;
    for (int l=0; l<64; l++) s += p[(size_t)l*DD];
    red[t] = s;
    __syncthreads();
    if (t < 128) pooled4[(size_t)c*NB*DD + b*DD + t] = red[t] + red[t+128];
}

__global__ __launch_bounds__(64)
void cls_k(const float* __restrict__ pooled4,
           const float* __restrict__ W1, const float* __restrict__ b1,
           const float* __restrict__ W2, const float* __restrict__ b2,
           float* __restrict__ out)
{
    const int b = blockIdx.x, t = threadIdx.x;
    __shared__ float ps[128], hid[64];
#pragma unroll
    for (int i=0;i<2;i++){
        int col = t + i*64;
        float s = 0.f;
#pragma unroll
        for (int c=0;c<4;c++) s += pooled4[(size_t)c*NB*DD + b*DD + col];
        ps[col] = s * (1.f/(float)LL);
    }
    __syncthreads();
    float a = b1[t];
    for (int k=0;k<128;k++) a = fmaf(ps[k], W1[k*64 + t], a);
    hid[t] = fmaxf(a, 0.f);
    __syncthreads();
    if (t < OUTC){
        float o = b2[t];
#pragma unroll
        for (int k=0;k<64;k++) o = fmaf(hid[k], W2[k*OUTC + t], o);
        out[b*OUTC + t] = o;
    }
}

extern "C" void kernel_launch(void* const* d_in, const int* in_sizes, int n_in,
                              void* d_out, int out_size)
{
    const float* x      = (const float*)d_in[0];
    const float* Wp     = (const float*)d_in[n_in-18];
    const float* bp     = (const float*)d_in[n_in-17];
    const float* qkv_w  = (const float*)d_in[n_in-16];
    const float* qkv_b  = (const float*)d_in[n_in-15];
    const float* out_w  = (const float*)d_in[n_in-14];
    const float* out_b  = (const float*)d_in[n_in-13];
    const float* ln1_g  = (const float*)d_in[n_in-12];
    const float* ln1_b  = (const float*)d_in[n_in-11];
    const float* ffn_w1 = (const float*)d_in[n_in-10];
    const float* ffn_b1 = (const float*)d_in[n_in-9];
    const float* ffn_w2 = (const float*)d_in[n_in-8];
    const float* ffn_b2 = (const float*)d_in[n_in-7];
    const float* ln2_g  = (const float*)d_in[n_in-6];
    const float* ln2_b  = (const float*)d_in[n_in-5];
    const float* cls_w1 = (const float*)d_in[n_in-4];
    const float* cls_b1 = (const float*)d_in[n_in-3];
    const float* cls_w2 = (const float*)d_in[n_in-2];
    const float* cls_b2 = (const float*)d_in[n_in-1];
    float* out = (float*)d_out;

    float *h, *pooled4;
    __half *h16, *x16, *qkv16, *whi;
    cudaGetSymbolAddress((void**)&h,       g_h);
    cudaGetSymbolAddress((void**)&pooled4, g_pool4);
    cudaGetSymbolAddress((void**)&h16,     g_h16);
    cudaGetSymbolAddress((void**)&x16,     g_x16);
    cudaGetSymbolAddress((void**)&qkv16,   g_qkv16);
    cudaGetSymbolAddress((void**)&whi,     g_whi);
    __half* attn16 = x16;

    cudaFuncSetAttribute(layer_k, cudaFuncAttributeMaxDynamicSharedMemorySize, LYR_SMEM);

    cvtall<<<2048,256>>>(Wp, qkv_w, out_w, ffn_w1, ffn_w2, x, whi, x16);

    const int MB = NT/128;

    hgemm<<<dim3(1,MB),256>>>(x16, whi+OFF_WP, bp, h, h16, DD, DD);

    for (int i=0; i<NLAYERS; i++){
        hgemm16<<<dim3(3,MB),256>>>(
            h16, whi+OFF_QKV+(size_t)i*128*384,
            qkv_b+(size_t)i*384, qkv16, 384, 128);

        attn_k<<<dim3(4,HH,NB),256>>>(qkv16, attn16);

        layer_k<<<MB,256,LYR_SMEM>>>(
            attn16,
            whi+OFF_OUT+(size_t)i*128*128, out_b+(size_t)i*128,
            ln1_g+(size_t)i*DD, ln1_b+(size_t)i*DD,
            whi+OFF_F1+(size_t)i*128*512, ffn_b1+(size_t)i*512,
            whi+OFF_F2+(size_t)i*512*128, ffn_b2+(size_t)i*128,
            h, h16, ln2_g+(size_t)i*DD, ln2_b+(size_t)i*DD);
    }

    pool_k<<<dim3(NB,4),256>>>(h, pooled4);
    cls_k<<<NB,64>>>(pooled4, cls_w1, cls_b1, cls_w2, cls_b2, out);

    (void)in_sizes; (void)out_size;
}